// round 1
// baseline (speedup 1.0000x reference)
#include <cuda_runtime.h>
#include <math.h>

#define H 256
#define FH 1024
#define LNUM 2
#define KHOPS 4
#define NNODES 20000
#define NEDGES 160000
#define NLGE 640000

#define FLAG_ACC 1
#define FLAG_GELU 2

// ---------------- scratch (device globals; no allocations) ----------------
__device__ float g_x0[(size_t)NNODES * H];
__device__ float g_x1[(size_t)NNODES * H];
__device__ float g_lg0[(size_t)NEDGES * H];
__device__ float g_lg1[(size_t)NEDGES * H];
__device__ float g_fn[(size_t)NNODES * H];
__device__ float g_fe[(size_t)NEDGES * H];
__device__ float g_z0[(size_t)NEDGES * H];
__device__ float g_z1[(size_t)NEDGES * H];
__device__ float g_acc[(size_t)NEDGES * H];
__device__ float g_ln1[(size_t)NEDGES * H];
__device__ float g_ffh[(size_t)NEDGES * FH];

// ---------------- device helpers ----------------
__device__ __forceinline__ float gelu_f(float v) {
    return 0.5f * v * (1.0f + erff(v * 0.70710678118654752f));
}

// ---------------- GEMM: C = [C +] A @ B + bias, optional gelu ----------------
// A: [M,K] row-major, B: [K,N] row-major, C: [M,N]. N % 128 == 0, K % 8 == 0.
__global__ __launch_bounds__(256, 2)
void sgemm_kernel(const float* __restrict__ A, const float* __restrict__ B,
                  const float* __restrict__ bias, float* __restrict__ C,
                  int M, int N, int K, int flags)
{
    __shared__ float As[8][128];
    __shared__ float Bs[8][128];
    const int tid = threadIdx.x;
    const int row0 = blockIdx.y * 128;
    const int col0 = blockIdx.x * 128;
    const int tr = (tid / 16) * 8;
    const int tc = (tid % 16) * 8;
    const int aRow = tid >> 1;
    const int aCol = (tid & 1) * 4;
    const int bRow = tid >> 5;
    const int bCol = (tid & 31) * 4;

    float acc[8][8];
#pragma unroll
    for (int i = 0; i < 8; i++)
#pragma unroll
        for (int j = 0; j < 8; j++) acc[i][j] = 0.f;

    for (int k0 = 0; k0 < K; k0 += 8) {
        float4 av = make_float4(0.f, 0.f, 0.f, 0.f);
        if (row0 + aRow < M)
            av = *(const float4*)(A + (size_t)(row0 + aRow) * K + k0 + aCol);
        As[aCol + 0][aRow] = av.x;
        As[aCol + 1][aRow] = av.y;
        As[aCol + 2][aRow] = av.z;
        As[aCol + 3][aRow] = av.w;
        float4 bv = *(const float4*)(B + (size_t)(k0 + bRow) * N + col0 + bCol);
        *(float4*)&Bs[bRow][bCol] = bv;
        __syncthreads();
#pragma unroll
        for (int k = 0; k < 8; k++) {
            float ar[8], br[8];
#pragma unroll
            for (int i = 0; i < 8; i++) ar[i] = As[k][tr + i];
#pragma unroll
            for (int j = 0; j < 8; j++) br[j] = Bs[k][tc + j];
#pragma unroll
            for (int i = 0; i < 8; i++)
#pragma unroll
                for (int j = 0; j < 8; j++)
                    acc[i][j] = fmaf(ar[i], br[j], acc[i][j]);
        }
        __syncthreads();
    }

#pragma unroll
    for (int i = 0; i < 8; i++) {
        int r = row0 + tr + i;
        if (r >= M) continue;
#pragma unroll
        for (int j = 0; j < 8; j += 4) {
            int c = col0 + tc + j;
            float* cp = C + (size_t)r * N + c;
            float4 res;
            res.x = acc[i][j + 0] + bias[c + 0];
            res.y = acc[i][j + 1] + bias[c + 1];
            res.z = acc[i][j + 2] + bias[c + 2];
            res.w = acc[i][j + 3] + bias[c + 3];
            if (flags & FLAG_ACC) {
                float4 old = *(const float4*)cp;
                res.x += old.x; res.y += old.y; res.z += old.z; res.w += old.w;
            }
            if (flags & FLAG_GELU) {
                res.x = gelu_f(res.x); res.y = gelu_f(res.y);
                res.z = gelu_f(res.z); res.w = gelu_f(res.w);
            }
            *(float4*)cp = res;
        }
    }
}

// ---------------- scatter add: out[sidx[e]] += in[gidx?gidx[e]:e] ----------------
__global__ void scatter_add_kernel(float* __restrict__ out, const float* __restrict__ in,
                                   const int* __restrict__ gidx, const int* __restrict__ sidx,
                                   int m)
{
    long t = (long)blockIdx.x * blockDim.x + threadIdx.x;
    if (t >= (long)m * 64) return;
    int e = (int)(t >> 6);
    int c = (int)(t & 63) << 2;
    int rin = gidx ? gidx[e] : e;
    int rout = sidx[e];
    float4 v = *(const float4*)(in + (size_t)rin * H + c);
    float* o = out + (size_t)rout * H + c;
    atomicAdd(o + 0, v.x);
    atomicAdd(o + 1, v.y);
    atomicAdd(o + 2, v.z);
    atomicAdd(o + 3, v.w);
}

// ---------------- gather sum: out[e] = x[src[e]] + x[dst[e]] ----------------
__global__ void gather_sum_kernel(float* __restrict__ out, const float* __restrict__ x,
                                  const int* __restrict__ src, const int* __restrict__ dst,
                                  int m)
{
    long t = (long)blockIdx.x * blockDim.x + threadIdx.x;
    if (t >= (long)m * 64) return;
    int e = (int)(t >> 6);
    int c = (int)(t & 63) << 2;
    float4 a = *(const float4*)(x + (size_t)src[e] * H + c);
    float4 b = *(const float4*)(x + (size_t)dst[e] * H + c);
    float4 r = make_float4(a.x + b.x, a.y + b.y, a.z + b.z, a.w + b.w);
    *(float4*)(out + (size_t)e * H + c) = r;
}

// ---------------- embedding gather: out[e] = rel[feat[e]] ----------------
__global__ void gather_embed_kernel(float* __restrict__ out, const float* __restrict__ rel,
                                    const int* __restrict__ feat, int m)
{
    long t = (long)blockIdx.x * blockDim.x + threadIdx.x;
    if (t >= (long)m * 64) return;
    int e = (int)(t >> 6);
    int c = (int)(t & 63) << 2;
    float4 v = *(const float4*)(rel + (size_t)feat[e] * H + c);
    *(float4*)(out + (size_t)e * H + c) = v;
}

// ---------------- residual + (gelu) + layernorm, one warp per row ----------------
__global__ void residual_ln_kernel(const float* __restrict__ resid,
                                   const float* __restrict__ y,
                                   const float* __restrict__ gamma,
                                   const float* __restrict__ beta,
                                   float* __restrict__ out,
                                   int n, int do_gelu)
{
    int gw = (int)(((long)blockIdx.x * blockDim.x + threadIdx.x) >> 5);
    int lane = threadIdx.x & 31;
    if (gw >= n) return;
    const float* rp = resid + (size_t)gw * H;
    const float* yp = y + (size_t)gw * H;
    float v[8];
    float sum = 0.f, sq = 0.f;
#pragma unroll
    for (int h = 0; h < 2; h++) {
        int c = h * 128 + lane * 4;
        float4 a = *(const float4*)(rp + c);
        float4 b = *(const float4*)(yp + c);
        float tb[4] = {b.x, b.y, b.z, b.w};
        float ta[4] = {a.x, a.y, a.z, a.w};
#pragma unroll
        for (int j = 0; j < 4; j++) {
            float u = do_gelu ? gelu_f(tb[j]) : tb[j];
            u += ta[j];
            v[h * 4 + j] = u;
            sum += u;
            sq += u * u;
        }
    }
#pragma unroll
    for (int o = 16; o > 0; o >>= 1) {
        sum += __shfl_xor_sync(0xFFFFFFFFu, sum, o);
        sq  += __shfl_xor_sync(0xFFFFFFFFu, sq, o);
    }
    float mean = sum * (1.0f / H);
    float var = sq * (1.0f / H) - mean * mean;
    float rstd = rsqrtf(var + 1e-5f);
    float* op = out + (size_t)gw * H;
#pragma unroll
    for (int h = 0; h < 2; h++) {
        int c = h * 128 + lane * 4;
        float4 gv = *(const float4*)(gamma + c);
        float4 bv = *(const float4*)(beta + c);
        float4 o4;
        o4.x = (v[h * 4 + 0] - mean) * rstd * gv.x + bv.x;
        o4.y = (v[h * 4 + 1] - mean) * rstd * gv.y + bv.y;
        o4.z = (v[h * 4 + 2] - mean) * rstd * gv.z + bv.z;
        o4.w = (v[h * 4 + 3] - mean) * rstd * gv.w + bv.w;
        *(float4*)(op + c) = o4;
    }
}

// ---------------- host-side helpers ----------------
static inline void launch_gemm(const float* A, const float* B, const float* bias, float* C,
                               int M, int N, int K, int flags)
{
    dim3 grid(N / 128, (M + 127) / 128);
    sgemm_kernel<<<grid, 256>>>(A, B, bias, C, M, N, K, flags);
}

static inline int blocks_for(long threads) { return (int)((threads + 255) / 256); }

struct Scratch {
    float *x0, *x1, *lg0, *lg1, *fn, *fe, *z0, *z1, *acc, *ln1, *ffh;
};

static void run_core(const Scratch& S,
                     const float* xin, const float* fused, float* xout,
                     int n, const int* src, const int* dst, int m,
                     const float* ws, const float* bs,
                     const float* wk, const float* bk,
                     const float* wf, const float* bf,
                     const float* w1, const float* b1,
                     const float* w2, const float* b2,
                     const float* g1, const float* c1,
                     const float* g2, const float* c2)
{
    // acc = xin @ ws + bs
    launch_gemm(xin, ws, bs, S.acc, n, H, H, 0);

    // k-hop aggregation
    const float* z = xin;
    float* zbuf[2] = {S.z0, S.z1};
    for (int i = 0; i < KHOPS; i++) {
        float* znext = zbuf[i & 1];
        cudaMemsetAsync(znext, 0, (size_t)n * H * sizeof(float));
        scatter_add_kernel<<<blocks_for((long)m * 64), 256>>>(znext, z, src, dst, m);
        launch_gemm(znext, wk + (size_t)i * H * H, bk + (size_t)i * H, S.acc, n, H, H, FLAG_ACC);
        z = znext;
    }

    // acc += fused @ wf + bf
    launch_gemm(fused, wf, bf, S.acc, n, H, H, FLAG_ACC);

    // ln1 = LN(xin + gelu(acc))
    residual_ln_kernel<<<(n + 7) / 8, 256>>>(xin, S.acc, g1, c1, S.ln1, n, 1);

    // ffh = gelu(ln1 @ w1 + b1)
    launch_gemm(S.ln1, w1, b1, S.ffh, n, FH, H, FLAG_GELU);
    // acc = ffh @ w2 + b2
    launch_gemm(S.ffh, w2, b2, S.acc, n, H, FH, 0);

    // xout = LN(ln1 + acc)
    residual_ln_kernel<<<(n + 7) / 8, 256>>>(S.ln1, S.acc, g2, c2, xout, n, 0);
}

extern "C" void kernel_launch(void* const* d_in, const int* in_sizes, int n_in,
                              void* d_out, int out_size)
{
    const float* x_in      = (const float*)d_in[0];
    const int*   edge_feat = (const int*)d_in[1];
    const int*   eig       = (const int*)d_in[2];
    const int*   eil       = (const int*)d_in[3];
    const float* rel       = (const float*)d_in[4];
    const float* w_self    = (const float*)d_in[5];
    const float* b_self    = (const float*)d_in[6];
    const float* w_khop    = (const float*)d_in[7];
    const float* b_khop    = (const float*)d_in[8];
    const float* w_fuse    = (const float*)d_in[9];
    const float* b_fuse    = (const float*)d_in[10];
    const float* w_ff1     = (const float*)d_in[11];
    const float* b_ff1     = (const float*)d_in[12];
    const float* w_ff2     = (const float*)d_in[13];
    const float* b_ff2     = (const float*)d_in[14];
    const float* ln1_g     = (const float*)d_in[15];
    const float* ln1_b     = (const float*)d_in[16];
    const float* ln2_g     = (const float*)d_in[17];
    const float* ln2_b     = (const float*)d_in[18];

    const int* src_g = eig;
    const int* dst_g = eig + NEDGES;
    const int* src_l = eil;
    const int* dst_l = eil + NLGE;

    Scratch S;
    void* p;
    cudaGetSymbolAddress(&p, g_x0);  S.x0  = (float*)p;
    cudaGetSymbolAddress(&p, g_x1);  S.x1  = (float*)p;
    cudaGetSymbolAddress(&p, g_lg0); S.lg0 = (float*)p;
    cudaGetSymbolAddress(&p, g_lg1); S.lg1 = (float*)p;
    cudaGetSymbolAddress(&p, g_fn);  S.fn  = (float*)p;
    cudaGetSymbolAddress(&p, g_fe);  S.fe  = (float*)p;
    cudaGetSymbolAddress(&p, g_z0);  S.z0  = (float*)p;
    cudaGetSymbolAddress(&p, g_z1);  S.z1  = (float*)p;
    cudaGetSymbolAddress(&p, g_acc); S.acc = (float*)p;
    cudaGetSymbolAddress(&p, g_ln1); S.ln1 = (float*)p;
    cudaGetSymbolAddress(&p, g_ffh); S.ffh = (float*)p;

    float* xb[2]  = {S.x0, S.x1};
    float* lgb[2] = {S.lg0, S.lg1};

    // init: x copy, lg_x = rel_embed[edge_feat]
    cudaMemcpyAsync(S.x0, x_in, (size_t)NNODES * H * sizeof(float), cudaMemcpyDeviceToDevice);
    gather_embed_kernel<<<blocks_for((long)NEDGES * 64), 256>>>(S.lg0, rel, edge_feat, NEDGES);

    int cur = 0;
    for (int l = 0; l < LNUM; l++) {
        const float* x  = xb[cur];
        const float* lg = lgb[cur];
        float* xn  = xb[1 - cur];
        float* lgn = lgb[1 - cur];

        // fused_nodes = segsum(lg, src_g) + segsum(lg, dst_g)
        cudaMemsetAsync(S.fn, 0, (size_t)NNODES * H * sizeof(float));
        scatter_add_kernel<<<blocks_for((long)NEDGES * 64), 256>>>(S.fn, lg, nullptr, src_g, NEDGES);
        scatter_add_kernel<<<blocks_for((long)NEDGES * 64), 256>>>(S.fn, lg, nullptr, dst_g, NEDGES);
        // fused_edges = x[src_g] + x[dst_g]
        gather_sum_kernel<<<blocks_for((long)NEDGES * 64), 256>>>(S.fe, x, src_g, dst_g, NEDGES);

        // parameter offsets for (l, core)
        for (int c = 0; c < 2; c++) {
            size_t lc = (size_t)l * 2 + c;
            const float* ws = w_self + lc * H * H;
            const float* bs = b_self + lc * H;
            const float* wk = w_khop + lc * KHOPS * H * H;
            const float* bk = b_khop + lc * KHOPS * H;
            const float* wf = w_fuse + lc * H * H;
            const float* bf = b_fuse + lc * H;
            const float* w1 = w_ff1 + lc * H * FH;
            const float* b1 = b_ff1 + lc * FH;
            const float* w2 = w_ff2 + lc * FH * H;
            const float* b2 = b_ff2 + lc * H;
            const float* g1 = ln1_g + lc * H;
            const float* c1 = ln1_b + lc * H;
            const float* g2 = ln2_g + lc * H;
            const float* c2 = ln2_b + lc * H;
            if (c == 0) {
                run_core(S, x, S.fn, xn, NNODES, src_g, dst_g, NEDGES,
                         ws, bs, wk, bk, wf, bf, w1, b1, w2, b2, g1, c1, g2, c2);
            } else {
                run_core(S, lg, S.fe, lgn, NEDGES, src_l, dst_l, NLGE,
                         ws, bs, wk, bk, wf, bf, w1, b1, w2, b2, g1, c1, g2, c2);
            }
        }
        cur = 1 - cur;
    }

    // output: x then lg_x
    cudaMemcpyAsync(d_out, xb[cur], (size_t)NNODES * H * sizeof(float),
                    cudaMemcpyDeviceToDevice);
    cudaMemcpyAsync((float*)d_out + (size_t)NNODES * H, lgb[cur],
                    (size_t)NEDGES * H * sizeof(float), cudaMemcpyDeviceToDevice);
}

// round 3
// speedup vs baseline: 2.2177x; 2.2177x over previous
#include <cuda_runtime.h>
#include <math.h>
#include <stdint.h>

#define H 256
#define FH 1024
#define LNUM 2
#define KHOPS 4
#define NNODES 20000
#define NEDGES 160000
#define NLGE 640000
#define ZW 1536          // concat width: x | fused | z1..z4

#define FLAG_GELU 2

// ---------------- scratch (device globals; no allocations) ----------------
__device__ float g_x0[(size_t)NNODES * H];
__device__ float g_x1[(size_t)NNODES * H];
__device__ float g_lg0[(size_t)NEDGES * H];
__device__ float g_lg1[(size_t)NEDGES * H];
__device__ float g_fn[(size_t)NNODES * H];
__device__ float g_fe[(size_t)NEDGES * H];
__device__ float g_zbig[(size_t)NEDGES * ZW];
__device__ float g_acc[(size_t)NEDGES * H];
__device__ float g_ln1[(size_t)NEDGES * H];
__device__ float g_ffh[(size_t)NEDGES * FH];
// pre-transposed weights, [lc][N][K] K-major
__device__ float g_wtcat[(size_t)4 * H * ZW];
__device__ float g_wt1[(size_t)4 * FH * H];
__device__ float g_wt2[(size_t)4 * H * FH];
__device__ float g_bcat[(size_t)4 * H];

// ---------------- device helpers ----------------
__device__ __forceinline__ float to_tf32(float x) {
    float y;
    asm("cvt.rna.tf32.f32 %0, %1;" : "=f"(y) : "f"(x));
    return y;
}
__device__ __forceinline__ float gelu_f(float v) {
    return 0.5f * v * (1.0f + erff(v * 0.70710678118654752f));
}

// ---------------- tf32 mma.sync GEMM ----------------
// C[M,N] = A[M,K(lda)] @ Bt[N,K]^T + bias, optional gelu.
// Block tile 128x128, BK=32, 8 warps (64x32 warp tiles), double-buffered smem.
#define BK 32
#define LDA_S 36                       // 32 + 4 pad (floats)
#define ABUF (128 * LDA_S)             // floats per buffer
#define GEMM_SMEM (4 * ABUF * 4)       // 2 A bufs + 2 B bufs, bytes

__device__ __forceinline__ void mma_tf32(float* c, const uint32_t* a, const uint32_t* b) {
    asm volatile(
        "mma.sync.aligned.m16n8k8.row.col.f32.tf32.tf32.f32 "
        "{%0,%1,%2,%3}, {%4,%5,%6,%7}, {%8,%9}, {%0,%1,%2,%3};"
        : "+f"(c[0]), "+f"(c[1]), "+f"(c[2]), "+f"(c[3])
        : "r"(a[0]), "r"(a[1]), "r"(a[2]), "r"(a[3]), "r"(b[0]), "r"(b[1]));
}

__global__ __launch_bounds__(256)
void mma_gemm(const float* __restrict__ A, int lda,
              const float* __restrict__ Bt,
              const float* __restrict__ bias, float* __restrict__ C,
              int M, int N, int K, int flags)
{
    extern __shared__ float smem[];
    float* AsBase = smem;                 // [2][128][LDA_S]
    float* BsBase = smem + 2 * ABUF;      // [2][128][LDA_S]

    const int tid = threadIdx.x;
    const int wid = tid >> 5, lane = tid & 31;
    const int gid = lane >> 2, tig = lane & 3;
    const int warp_m = (wid & 1) * 64;
    const int warp_n = (wid >> 1) * 32;
    const int row0 = blockIdx.y * 128;
    const int col0 = blockIdx.x * 128;

    float acc[4][4][4];
#pragma unroll
    for (int mt = 0; mt < 4; mt++)
#pragma unroll
        for (int nt = 0; nt < 4; nt++)
#pragma unroll
            for (int j = 0; j < 4; j++) acc[mt][nt][j] = 0.f;

    const int nc = K / BK;
    float4 ra[4], rb[4];

    // per-thread load coords: 1024 float4 per 128x32 tile / 256 threads = 4 each
    const int lr = tid >> 3;          // wrong granularity helper below; computed per f

#pragma unroll
    for (int f = 0; f < 4; f++) {
        int i = f * 256 + tid, r = i >> 3, c4 = i & 7;
        int gr = row0 + r; if (gr >= M) gr = M - 1;
        ra[f] = *(const float4*)(A + (size_t)gr * lda + c4 * 4);
        rb[f] = *(const float4*)(Bt + (size_t)(col0 + r) * K + c4 * 4);
    }
    {
        float* As = AsBase; float* Bs = BsBase;
#pragma unroll
        for (int f = 0; f < 4; f++) {
            int i = f * 256 + tid, r = i >> 3, c4 = i & 7;
            float4 va = ra[f], vb = rb[f];
            va.x = to_tf32(va.x); va.y = to_tf32(va.y); va.z = to_tf32(va.z); va.w = to_tf32(va.w);
            vb.x = to_tf32(vb.x); vb.y = to_tf32(vb.y); vb.z = to_tf32(vb.z); vb.w = to_tf32(vb.w);
            *(float4*)(As + r * LDA_S + c4 * 4) = va;
            *(float4*)(Bs + r * LDA_S + c4 * 4) = vb;
        }
    }
    __syncthreads();

    for (int c = 0; c < nc; c++) {
        const int nxt = c + 1;
        if (nxt < nc) {
            const int k0 = nxt * BK;
#pragma unroll
            for (int f = 0; f < 4; f++) {
                int i = f * 256 + tid, r = i >> 3, c4 = i & 7;
                int gr = row0 + r; if (gr >= M) gr = M - 1;
                ra[f] = *(const float4*)(A + (size_t)gr * lda + k0 + c4 * 4);
                rb[f] = *(const float4*)(Bt + (size_t)(col0 + r) * K + k0 + c4 * 4);
            }
        }

        const uint32_t* Asu = (const uint32_t*)(AsBase + (c & 1) * ABUF);
        const uint32_t* Bsu = (const uint32_t*)(BsBase + (c & 1) * ABUF);
#pragma unroll
        for (int ks = 0; ks < 4; ks++) {
            const int k0c = ks * 8;
            uint32_t afr[4][4], bfr[4][2];
#pragma unroll
            for (int mt = 0; mt < 4; mt++) {
                int r = warp_m + mt * 16 + gid;
                afr[mt][0] = Asu[r * LDA_S + k0c + tig];
                afr[mt][1] = Asu[(r + 8) * LDA_S + k0c + tig];
                afr[mt][2] = Asu[r * LDA_S + k0c + tig + 4];
                afr[mt][3] = Asu[(r + 8) * LDA_S + k0c + tig + 4];
            }
#pragma unroll
            for (int nt = 0; nt < 4; nt++) {
                int cc = warp_n + nt * 8 + gid;
                bfr[nt][0] = Bsu[cc * LDA_S + k0c + tig];
                bfr[nt][1] = Bsu[cc * LDA_S + k0c + tig + 4];
            }
#pragma unroll
            for (int mt = 0; mt < 4; mt++)
#pragma unroll
                for (int nt = 0; nt < 4; nt++)
                    mma_tf32(acc[mt][nt], afr[mt], bfr[nt]);
        }

        if (nxt < nc) {
            float* As = AsBase + (nxt & 1) * ABUF;
            float* Bs = BsBase + (nxt & 1) * ABUF;
#pragma unroll
            for (int f = 0; f < 4; f++) {
                int i = f * 256 + tid, r = i >> 3, c4 = i & 7;
                float4 va = ra[f], vb = rb[f];
                va.x = to_tf32(va.x); va.y = to_tf32(va.y); va.z = to_tf32(va.z); va.w = to_tf32(va.w);
                vb.x = to_tf32(vb.x); vb.y = to_tf32(vb.y); vb.z = to_tf32(vb.z); vb.w = to_tf32(vb.w);
                *(float4*)(As + r * LDA_S + c4 * 4) = va;
                *(float4*)(Bs + r * LDA_S + c4 * 4) = vb;
            }
        }
        __syncthreads();
    }

    // epilogue
#pragma unroll
    for (int mt = 0; mt < 4; mt++) {
#pragma unroll
        for (int nt = 0; nt < 4; nt++) {
            int cc = col0 + warp_n + nt * 8 + 2 * tig;
            float bx = bias[cc], by = bias[cc + 1];
#pragma unroll
            for (int h = 0; h < 2; h++) {
                int r = row0 + warp_m + mt * 16 + gid + h * 8;
                if (r >= M) continue;
                float ox = acc[mt][nt][h * 2 + 0] + bx;
                float oy = acc[mt][nt][h * 2 + 1] + by;
                if (flags & FLAG_GELU) { ox = gelu_f(ox); oy = gelu_f(oy); }
                float2 o2 = make_float2(ox, oy);
                *(float2*)(C + (size_t)r * N + cc) = o2;
            }
        }
    }
}

// ---------------- weight prep (transpose to [N,K] K-major) ----------------
__global__ void build_wtcat_kernel(const float* __restrict__ ws, const float* __restrict__ wf,
                                   const float* __restrict__ wk, float* __restrict__ out)
{
    long t = (long)blockIdx.x * blockDim.x + threadIdx.x;
    if (t >= (long)4 * H * ZW) return;
    int lc = (int)(t / (H * ZW));
    int rem = (int)(t % (H * ZW));
    int n = rem / ZW, k = rem % ZW;
    float v;
    if (k < 256) v = ws[(size_t)lc * 65536 + k * 256 + n];
    else if (k < 512) v = wf[(size_t)lc * 65536 + (k - 256) * 256 + n];
    else {
        int hop = (k - 512) >> 8, kk = (k - 512) & 255;
        v = wk[((size_t)(lc * 4 + hop) * 256 + kk) * 256 + n];
    }
    out[t] = v;
}

__global__ void build_wt1_kernel(const float* __restrict__ w1, float* __restrict__ out)
{
    long t = (long)blockIdx.x * blockDim.x + threadIdx.x;
    if (t >= (long)4 * FH * H) return;
    int lc = (int)(t / (FH * H));
    int rem = (int)(t % (FH * H));
    int n = rem / H, k = rem % H;
    out[t] = w1[(size_t)lc * (H * FH) + (size_t)k * FH + n];
}

__global__ void build_wt2_kernel(const float* __restrict__ w2, float* __restrict__ out)
{
    long t = (long)blockIdx.x * blockDim.x + threadIdx.x;
    if (t >= (long)4 * H * FH) return;
    int lc = (int)(t / (H * FH));
    int rem = (int)(t % (H * FH));
    int n = rem / FH, k = rem % FH;
    out[t] = w2[(size_t)lc * (FH * H) + (size_t)k * H + n];
}

__global__ void build_bcat_kernel(const float* __restrict__ bs, const float* __restrict__ bf,
                                  const float* __restrict__ bk, float* __restrict__ out)
{
    int t = blockIdx.x * blockDim.x + threadIdx.x;
    if (t >= 4 * H) return;
    int lc = t / H, n = t % H;
    float v = bs[lc * H + n] + bf[lc * H + n];
    for (int i = 0; i < KHOPS; i++) v += bk[(lc * KHOPS + i) * H + n];
    out[t] = v;
}

// ---------------- Zbig init: [x | fused | 0 x 1024] ----------------
__global__ void init_zbig_kernel(float* __restrict__ zb, const float* __restrict__ x,
                                 const float* __restrict__ fused, int n)
{
    long t = (long)blockIdx.x * blockDim.x + threadIdx.x;
    if (t >= (long)n * (ZW / 4)) return;
    int r = (int)(t / (ZW / 4));
    int c = (int)(t % (ZW / 4)) * 4;
    float4 v;
    if (c < 256) v = *(const float4*)(x + (size_t)r * H + c);
    else if (c < 512) v = *(const float4*)(fused + (size_t)r * H + (c - 256));
    else v = make_float4(0.f, 0.f, 0.f, 0.f);
    *(float4*)(zb + (size_t)r * ZW + c) = v;
}

// ---------------- scatter add with strides ----------------
__global__ void scatter_add_kernel(float* __restrict__ out, long ostride,
                                   const float* __restrict__ in, long istride,
                                   const int* __restrict__ gidx, const int* __restrict__ sidx,
                                   int m)
{
    long t = (long)blockIdx.x * blockDim.x + threadIdx.x;
    if (t >= (long)m * 64) return;
    int e = (int)(t >> 6);
    int c = (int)(t & 63) << 2;
    int rin = gidx ? gidx[e] : e;
    int rout = sidx[e];
    float4 v = *(const float4*)(in + (size_t)rin * istride + c);
    float* o = out + (size_t)rout * ostride + c;
    atomicAdd(o + 0, v.x);
    atomicAdd(o + 1, v.y);
    atomicAdd(o + 2, v.z);
    atomicAdd(o + 3, v.w);
}

__global__ void gather_sum_kernel(float* __restrict__ out, const float* __restrict__ x,
                                  const int* __restrict__ src, const int* __restrict__ dst,
                                  int m)
{
    long t = (long)blockIdx.x * blockDim.x + threadIdx.x;
    if (t >= (long)m * 64) return;
    int e = (int)(t >> 6);
    int c = (int)(t & 63) << 2;
    float4 a = *(const float4*)(x + (size_t)src[e] * H + c);
    float4 b = *(const float4*)(x + (size_t)dst[e] * H + c);
    *(float4*)(out + (size_t)e * H + c) = make_float4(a.x + b.x, a.y + b.y, a.z + b.z, a.w + b.w);
}

__global__ void gather_embed_kernel(float* __restrict__ out, const float* __restrict__ rel,
                                    const int* __restrict__ feat, int m)
{
    long t = (long)blockIdx.x * blockDim.x + threadIdx.x;
    if (t >= (long)m * 64) return;
    int e = (int)(t >> 6);
    int c = (int)(t & 63) << 2;
    *(float4*)(out + (size_t)e * H + c) = *(const float4*)(rel + (size_t)feat[e] * H + c);
}

// ---------------- residual + (gelu) + layernorm, one warp per row ----------------
__global__ void residual_ln_kernel(const float* __restrict__ resid,
                                   const float* __restrict__ y,
                                   const float* __restrict__ gamma,
                                   const float* __restrict__ beta,
                                   float* __restrict__ out,
                                   int n, int do_gelu)
{
    int gw = (int)(((long)blockIdx.x * blockDim.x + threadIdx.x) >> 5);
    int lane = threadIdx.x & 31;
    if (gw >= n) return;
    const float* rp = resid + (size_t)gw * H;
    const float* yp = y + (size_t)gw * H;
    float v[8];
    float sum = 0.f, sq = 0.f;
#pragma unroll
    for (int h = 0; h < 2; h++) {
        int c = h * 128 + lane * 4;
        float4 a = *(const float4*)(rp + c);
        float4 b = *(const float4*)(yp + c);
        float tb[4] = {b.x, b.y, b.z, b.w};
        float ta[4] = {a.x, a.y, a.z, a.w};
#pragma unroll
        for (int j = 0; j < 4; j++) {
            float u = do_gelu ? gelu_f(tb[j]) : tb[j];
            u += ta[j];
            v[h * 4 + j] = u;
            sum += u;
            sq += u * u;
        }
    }
#pragma unroll
    for (int o = 16; o > 0; o >>= 1) {
        sum += __shfl_xor_sync(0xFFFFFFFFu, sum, o);
        sq  += __shfl_xor_sync(0xFFFFFFFFu, sq, o);
    }
    float mean = sum * (1.0f / H);
    float var = sq * (1.0f / H) - mean * mean;
    float rstd = rsqrtf(var + 1e-5f);
    float* op = out + (size_t)gw * H;
#pragma unroll
    for (int h = 0; h < 2; h++) {
        int c = h * 128 + lane * 4;
        float4 gv = *(const float4*)(gamma + c);
        float4 bv = *(const float4*)(beta + c);
        float4 o4;
        o4.x = (v[h * 4 + 0] - mean) * rstd * gv.x + bv.x;
        o4.y = (v[h * 4 + 1] - mean) * rstd * gv.y + bv.y;
        o4.z = (v[h * 4 + 2] - mean) * rstd * gv.z + bv.z;
        o4.w = (v[h * 4 + 3] - mean) * rstd * gv.w + bv.w;
        *(float4*)(op + c) = o4;
    }
}

// ---------------- host side ----------------
static inline int blocks_for(long threads) { return (int)((threads + 255) / 256); }

static inline void launch_gemm(const float* A, int lda, const float* Bt, const float* bias,
                               float* C, int M, int N, int K, int flags)
{
    dim3 grid(N / 128, (M + 127) / 128);
    mma_gemm<<<grid, 256, GEMM_SMEM>>>(A, lda, Bt, bias, C, M, N, K, flags);
}

struct Scratch {
    float *x0, *x1, *lg0, *lg1, *fn, *fe, *zbig, *acc, *ln1, *ffh;
    float *wtcat, *wt1, *wt2, *bcat;
};

static void run_core(const Scratch& S,
                     const float* xin, const float* fused, float* xout,
                     int n, const int* src, const int* dst, int m,
                     int lc,
                     const float* b_ff1, const float* b_ff2,
                     const float* g1, const float* c1,
                     const float* g2, const float* c2)
{
    // Zbig = [xin | fused | 0...]
    init_zbig_kernel<<<blocks_for((long)n * (ZW / 4)), 256>>>(S.zbig, xin, fused, n);

    // k-hop chain into Zbig slices 2..5
    for (int i = 1; i <= KHOPS; i++) {
        const float* in = (i == 1) ? xin : (S.zbig + (size_t)i * H);
        long istride = (i == 1) ? H : ZW;
        float* out = S.zbig + (size_t)(i + 1) * H;
        scatter_add_kernel<<<blocks_for((long)m * 64), 256>>>(out, ZW, in, istride, src, dst, m);
    }

    // acc = Zbig @ Wcat + bcat
    launch_gemm(S.zbig, ZW, S.wtcat + (size_t)lc * H * ZW, S.bcat + (size_t)lc * H,
                S.acc, n, H, ZW, 0);

    // ln1 = LN(xin + gelu(acc))
    residual_ln_kernel<<<(n + 7) / 8, 256>>>(xin, S.acc, g1, c1, S.ln1, n, 1);

    // ffh = gelu(ln1 @ w1 + b1)
    launch_gemm(S.ln1, H, S.wt1 + (size_t)lc * FH * H, b_ff1, S.ffh, n, FH, H, FLAG_GELU);
    // acc = ffh @ w2 + b2
    launch_gemm(S.ffh, FH, S.wt2 + (size_t)lc * H * FH, b_ff2, S.acc, n, H, FH, 0);

    // xout = LN(ln1 + acc)
    residual_ln_kernel<<<(n + 7) / 8, 256>>>(S.ln1, S.acc, g2, c2, xout, n, 0);
}

extern "C" void kernel_launch(void* const* d_in, const int* in_sizes, int n_in,
                              void* d_out, int out_size)
{
    const float* x_in      = (const float*)d_in[0];
    const int*   edge_feat = (const int*)d_in[1];
    const int*   eig       = (const int*)d_in[2];
    const int*   eil       = (const int*)d_in[3];
    const float* rel       = (const float*)d_in[4];
    const float* w_self    = (const float*)d_in[5];
    const float* b_self    = (const float*)d_in[6];
    const float* w_khop    = (const float*)d_in[7];
    const float* b_khop    = (const float*)d_in[8];
    const float* w_fuse    = (const float*)d_in[9];
    const float* b_fuse    = (const float*)d_in[10];
    const float* w_ff1     = (const float*)d_in[11];
    const float* b_ff1     = (const float*)d_in[12];
    const float* w_ff2     = (const float*)d_in[13];
    const float* b_ff2     = (const float*)d_in[14];
    const float* ln1_g     = (const float*)d_in[15];
    const float* ln1_b     = (const float*)d_in[16];
    const float* ln2_g     = (const float*)d_in[17];
    const float* ln2_b     = (const float*)d_in[18];

    const int* src_g = eig;
    const int* dst_g = eig + NEDGES;
    const int* src_l = eil;
    const int* dst_l = eil + NLGE;

    cudaFuncSetAttribute(mma_gemm, cudaFuncAttributeMaxDynamicSharedMemorySize, GEMM_SMEM);

    Scratch S;
    void* p;
    cudaGetSymbolAddress(&p, g_x0);    S.x0    = (float*)p;
    cudaGetSymbolAddress(&p, g_x1);    S.x1    = (float*)p;
    cudaGetSymbolAddress(&p, g_lg0);   S.lg0   = (float*)p;
    cudaGetSymbolAddress(&p, g_lg1);   S.lg1   = (float*)p;
    cudaGetSymbolAddress(&p, g_fn);    S.fn    = (float*)p;
    cudaGetSymbolAddress(&p, g_fe);    S.fe    = (float*)p;
    cudaGetSymbolAddress(&p, g_zbig);  S.zbig  = (float*)p;
    cudaGetSymbolAddress(&p, g_acc);   S.acc   = (float*)p;
    cudaGetSymbolAddress(&p, g_ln1);   S.ln1   = (float*)p;
    cudaGetSymbolAddress(&p, g_ffh);   S.ffh   = (float*)p;
    cudaGetSymbolAddress(&p, g_wtcat); S.wtcat = (float*)p;
    cudaGetSymbolAddress(&p, g_wt1);   S.wt1   = (float*)p;
    cudaGetSymbolAddress(&p, g_wt2);   S.wt2   = (float*)p;
    cudaGetSymbolAddress(&p, g_bcat);  S.bcat  = (float*)p;

    // weight prep
    build_wtcat_kernel<<<blocks_for((long)4 * H * ZW), 256>>>(w_self, w_fuse, w_khop, S.wtcat);
    build_wt1_kernel<<<blocks_for((long)4 * FH * H), 256>>>(w_ff1, S.wt1);
    build_wt2_kernel<<<blocks_for((long)4 * H * FH), 256>>>(w_ff2, S.wt2);
    build_bcat_kernel<<<blocks_for(4 * H), 256>>>(b_self, b_fuse, b_khop, S.bcat);

    float* xb[2]  = {S.x0, S.x1};
    float* lgb[2] = {S.lg0, S.lg1};

    cudaMemcpyAsync(S.x0, x_in, (size_t)NNODES * H * sizeof(float), cudaMemcpyDeviceToDevice);
    gather_embed_kernel<<<blocks_for((long)NEDGES * 64), 256>>>(S.lg0, rel, edge_feat, NEDGES);

    int cur = 0;
    for (int l = 0; l < LNUM; l++) {
        const float* x  = xb[cur];
        const float* lg = lgb[cur];
        float* xn  = xb[1 - cur];
        float* lgn = lgb[1 - cur];

        cudaMemsetAsync(S.fn, 0, (size_t)NNODES * H * sizeof(float));
        scatter_add_kernel<<<blocks_for((long)NEDGES * 64), 256>>>(S.fn, H, lg, H, nullptr, src_g, NEDGES);
        scatter_add_kernel<<<blocks_for((long)NEDGES * 64), 256>>>(S.fn, H, lg, H, nullptr, dst_g, NEDGES);
        gather_sum_kernel<<<blocks_for((long)NEDGES * 64), 256>>>(S.fe, x, src_g, dst_g, NEDGES);

        {
            int lc = l * 2 + 0;
            run_core(S, x, S.fn, xn, NNODES, src_g, dst_g, NEDGES, lc,
                     b_ff1 + (size_t)lc * FH, b_ff2 + (size_t)lc * H,
                     ln1_g + (size_t)lc * H, ln1_b + (size_t)lc * H,
                     ln2_g + (size_t)lc * H, ln2_b + (size_t)lc * H);
        }
        {
            int lc = l * 2 + 1;
            run_core(S, lg, S.fe, lgn, NEDGES, src_l, dst_l, NLGE, lc,
                     b_ff1 + (size_t)lc * FH, b_ff2 + (size_t)lc * H,
                     ln1_g + (size_t)lc * H, ln1_b + (size_t)lc * H,
                     ln2_g + (size_t)lc * H, ln2_b + (size_t)lc * H);
        }
        cur = 1 - cur;
    }

    cudaMemcpyAsync(d_out, xb[cur], (size_t)NNODES * H * sizeof(float),
                    cudaMemcpyDeviceToDevice);
    cudaMemcpyAsync((float*)d_out + (size_t)NNODES * H, lgb[cur],
                    (size_t)NEDGES * H * sizeof(float), cudaMemcpyDeviceToDevice);
}

// round 5
// speedup vs baseline: 2.6807x; 1.2088x over previous
#include <cuda_runtime.h>
#include <math.h>
#include <stdint.h>

#define H 256
#define FH 1024
#define LNUM 2
#define KHOPS 4
#define NNODES 20000
#define NEDGES 160000
#define NLGE 640000
#define ZW 1536          // concat width: x | fused | z1..z4

#define FLAG_GELU 2

// ---------------- scratch (device globals; no allocations) ----------------
__device__ __align__(256) float g_x0[(size_t)NNODES * H];
__device__ __align__(256) float g_x1[(size_t)NNODES * H];
__device__ __align__(256) float g_lg0[(size_t)NEDGES * H];
__device__ __align__(256) float g_lg1[(size_t)NEDGES * H];
__device__ __align__(256) float g_fn[(size_t)NNODES * H];
__device__ __align__(256) float g_fe[(size_t)NEDGES * H];
__device__ __align__(256) float g_zbig[(size_t)NEDGES * ZW];
__device__ __align__(256) float g_acc[(size_t)NEDGES * H];
__device__ __align__(256) float g_ln1[(size_t)NEDGES * H];
__device__ __align__(256) float g_ffh[(size_t)NEDGES * FH];
// pre-transposed (and tf32-rounded) weights, [lc][N][K] K-major
__device__ __align__(256) float g_wtcat[(size_t)4 * H * ZW];
__device__ __align__(256) float g_wt1[(size_t)4 * FH * H];
__device__ __align__(256) float g_wt2[(size_t)4 * H * FH];
__device__ __align__(256) float g_bcat[(size_t)4 * H];

// ---------------- device helpers ----------------
__device__ __forceinline__ float to_tf32(float x) {
    float y;
    asm("cvt.rna.tf32.f32 %0, %1;" : "=f"(y) : "f"(x));
    return y;
}
__device__ __forceinline__ float gelu_f(float v) {
    return 0.5f * v * (1.0f + erff(v * 0.70710678118654752f));
}
__device__ __forceinline__ void red_add_v4(float* addr, float4 v) {
    asm volatile("red.global.add.v4.f32 [%0], {%1, %2, %3, %4};"
                 :: "l"(addr), "f"(v.x), "f"(v.y), "f"(v.z), "f"(v.w) : "memory");
}
__device__ __forceinline__ void cp_async16(uint32_t saddr, const void* gptr) {
    asm volatile("cp.async.cg.shared.global [%0], [%1], 16;" :: "r"(saddr), "l"(gptr));
}
#define CP_COMMIT() asm volatile("cp.async.commit_group;")
#define CP_WAIT0()  asm volatile("cp.async.wait_group 0;")

// ---------------- tf32 mma.sync GEMM ----------------
// C[M,N] = A[M,K(lda)] @ Bt[N,K]^T + bias, optional gelu.
// Block tile 128x256, BK=32, 8 warps in 2x4 (64x64 warp tiles), double-buffered.
// Bt must be pre-rounded to tf32; A is rounded on the smem-store path.
#define BK 32
#define ASTR 36                         // 32 + 4 pad floats
#define ABUF_A (128 * ASTR)
#define ABUF_B (256 * ASTR)
#define GEMM_SMEM ((2 * ABUF_A + 2 * ABUF_B) * 4)

__device__ __forceinline__ void mma_tf32(float* c, const uint32_t* a, const uint32_t* b) {
    asm volatile(
        "mma.sync.aligned.m16n8k8.row.col.f32.tf32.tf32.f32 "
        "{%0,%1,%2,%3}, {%4,%5,%6,%7}, {%8,%9}, {%0,%1,%2,%3};"
        : "+f"(c[0]), "+f"(c[1]), "+f"(c[2]), "+f"(c[3])
        : "r"(a[0]), "r"(a[1]), "r"(a[2]), "r"(a[3]), "r"(b[0]), "r"(b[1]));
}

__global__ __launch_bounds__(256)
void mma_gemm(const float* __restrict__ A, int lda,
              const float* __restrict__ Bt,
              const float* __restrict__ bias, float* __restrict__ C,
              int M, int N, int K, int flags)
{
    extern __shared__ float smem[];
    float* AsBase = smem;                     // [2][128][ASTR]
    float* BsBase = smem + 2 * ABUF_A;        // [2][256][ASTR]

    const int tid = threadIdx.x;
    const int wid = tid >> 5, lane = tid & 31;
    const int gid = lane >> 2, tig = lane & 3;
    const int warp_m = (wid & 1) * 64;
    const int warp_n = (wid >> 1) * 64;
    const int row0 = blockIdx.y * 128;
    const int col0 = blockIdx.x * 256;

    float acc[4][8][4];
#pragma unroll
    for (int mt = 0; mt < 4; mt++)
#pragma unroll
        for (int nt = 0; nt < 8; nt++)
#pragma unroll
            for (int j = 0; j < 4; j++) acc[mt][nt][j] = 0.f;

    const int nc = K / BK;
    float4 ra[4];

    // ---- prologue: chunk 0 ----
#pragma unroll
    for (int f = 0; f < 8; f++) {
        int i = f * 256 + tid, r = i >> 3, c4 = i & 7;
        uint32_t dst = (uint32_t)__cvta_generic_to_shared(BsBase + r * ASTR + c4 * 4);
        cp_async16(dst, Bt + (size_t)(col0 + r) * K + c4 * 4);
    }
    CP_COMMIT();
#pragma unroll
    for (int f = 0; f < 4; f++) {
        int i = f * 256 + tid, r = i >> 3, c4 = i & 7;
        int gr = row0 + r; if (gr >= M) gr = M - 1;
        ra[f] = *(const float4*)(A + (size_t)gr * lda + c4 * 4);
    }
#pragma unroll
    for (int f = 0; f < 4; f++) {
        int i = f * 256 + tid, r = i >> 3, c4 = i & 7;
        float4 v = ra[f];
        v.x = to_tf32(v.x); v.y = to_tf32(v.y); v.z = to_tf32(v.z); v.w = to_tf32(v.w);
        *(float4*)(AsBase + r * ASTR + c4 * 4) = v;
    }
    CP_WAIT0();
    __syncthreads();

    for (int c = 0; c < nc; c++) {
        const int nxt = c + 1;
        if (nxt < nc) {
            const int k0 = nxt * BK;
            float* Bs = BsBase + (nxt & 1) * ABUF_B;
#pragma unroll
            for (int f = 0; f < 8; f++) {
                int i = f * 256 + tid, r = i >> 3, c4 = i & 7;
                uint32_t dst = (uint32_t)__cvta_generic_to_shared(Bs + r * ASTR + c4 * 4);
                cp_async16(dst, Bt + (size_t)(col0 + r) * K + k0 + c4 * 4);
            }
            CP_COMMIT();
#pragma unroll
            for (int f = 0; f < 4; f++) {
                int i = f * 256 + tid, r = i >> 3, c4 = i & 7;
                int gr = row0 + r; if (gr >= M) gr = M - 1;
                ra[f] = *(const float4*)(A + (size_t)gr * lda + k0 + c4 * 4);
            }
        }

        const uint32_t* Asu = (const uint32_t*)(AsBase + (c & 1) * ABUF_A);
        const uint32_t* Bsu = (const uint32_t*)(BsBase + (c & 1) * ABUF_B);
#pragma unroll
        for (int ks = 0; ks < 4; ks++) {
            const int k0c = ks * 8;
            uint32_t afr[4][4], bfr[8][2];
#pragma unroll
            for (int mt = 0; mt < 4; mt++) {
                int r = warp_m + mt * 16 + gid;
                afr[mt][0] = Asu[r * ASTR + k0c + tig];
                afr[mt][1] = Asu[(r + 8) * ASTR + k0c + tig];
                afr[mt][2] = Asu[r * ASTR + k0c + tig + 4];
                afr[mt][3] = Asu[(r + 8) * ASTR + k0c + tig + 4];
            }
#pragma unroll
            for (int nt = 0; nt < 8; nt++) {
                int cc = warp_n + nt * 8 + gid;
                bfr[nt][0] = Bsu[cc * ASTR + k0c + tig];
                bfr[nt][1] = Bsu[cc * ASTR + k0c + tig + 4];
            }
#pragma unroll
            for (int mt = 0; mt < 4; mt++)
#pragma unroll
                for (int nt = 0; nt < 8; nt++)
                    mma_tf32(acc[mt][nt], afr[mt], bfr[nt]);
        }

        if (nxt < nc) {
            float* As = AsBase + (nxt & 1) * ABUF_A;
#pragma unroll
            for (int f = 0; f < 4; f++) {
                int i = f * 256 + tid, r = i >> 3, c4 = i & 7;
                float4 v = ra[f];
                v.x = to_tf32(v.x); v.y = to_tf32(v.y); v.z = to_tf32(v.z); v.w = to_tf32(v.w);
                *(float4*)(As + r * ASTR + c4 * 4) = v;
            }
            CP_WAIT0();
        }
        __syncthreads();
    }

    // ---- epilogue ----
#pragma unroll
    for (int mt = 0; mt < 4; mt++) {
#pragma unroll
        for (int nt = 0; nt < 8; nt++) {
            int cc = col0 + warp_n + nt * 8 + 2 * tig;
            float bx = bias[cc], by = bias[cc + 1];
#pragma unroll
            for (int h = 0; h < 2; h++) {
                int r = row0 + warp_m + mt * 16 + gid + h * 8;
                if (r >= M) continue;
                float ox = acc[mt][nt][h * 2 + 0] + bx;
                float oy = acc[mt][nt][h * 2 + 1] + by;
                if (flags & FLAG_GELU) { ox = gelu_f(ox); oy = gelu_f(oy); }
                *(float2*)(C + (size_t)r * N + cc) = make_float2(ox, oy);
            }
        }
    }
}

// ---------------- weight prep (transpose to [N,K] K-major, tf32-rounded) ----------------
__global__ void build_wtcat_kernel(const float* __restrict__ ws, const float* __restrict__ wf,
                                   const float* __restrict__ wk, float* __restrict__ out)
{
    long t = (long)blockIdx.x * blockDim.x + threadIdx.x;
    if (t >= (long)4 * H * ZW) return;
    int lc = (int)(t / (H * ZW));
    int rem = (int)(t % (H * ZW));
    int n = rem / ZW, k = rem % ZW;
    float v;
    if (k < 256) v = ws[(size_t)lc * 65536 + k * 256 + n];
    else if (k < 512) v = wf[(size_t)lc * 65536 + (k - 256) * 256 + n];
    else {
        int hop = (k - 512) >> 8, kk = (k - 512) & 255;
        v = wk[((size_t)(lc * 4 + hop) * 256 + kk) * 256 + n];
    }
    out[t] = to_tf32(v);
}

__global__ void build_wt1_kernel(const float* __restrict__ w1, float* __restrict__ out)
{
    long t = (long)blockIdx.x * blockDim.x + threadIdx.x;
    if (t >= (long)4 * FH * H) return;
    int lc = (int)(t / (FH * H));
    int rem = (int)(t % (FH * H));
    int n = rem / H, k = rem % H;
    out[t] = to_tf32(w1[(size_t)lc * (H * FH) + (size_t)k * FH + n]);
}

__global__ void build_wt2_kernel(const float* __restrict__ w2, float* __restrict__ out)
{
    long t = (long)blockIdx.x * blockDim.x + threadIdx.x;
    if (t >= (long)4 * H * FH) return;
    int lc = (int)(t / (H * FH));
    int rem = (int)(t % (H * FH));
    int n = rem / FH, k = rem % FH;
    out[t] = to_tf32(w2[(size_t)lc * (FH * H) + (size_t)k * H + n]);
}

__global__ void build_bcat_kernel(const float* __restrict__ bs, const float* __restrict__ bf,
                                  const float* __restrict__ bk, float* __restrict__ out)
{
    int t = blockIdx.x * blockDim.x + threadIdx.x;
    if (t >= 4 * H) return;
    int lc = t / H, n = t % H;
    float v = bs[lc * H + n] + bf[lc * H + n];
    for (int i = 0; i < KHOPS; i++) v += bk[(lc * KHOPS + i) * H + n];
    out[t] = v;
}

// ---------------- Zbig init: [x | fused | 0 x 1024] ----------------
__global__ void init_zbig_kernel(float* __restrict__ zb, const float* __restrict__ x,
                                 const float* __restrict__ fused, int n)
{
    long t = (long)blockIdx.x * blockDim.x + threadIdx.x;
    if (t >= (long)n * (ZW / 4)) return;
    int r = (int)(t / (ZW / 4));
    int c = (int)(t % (ZW / 4)) * 4;
    float4 v;
    if (c < 256) v = *(const float4*)(x + (size_t)r * H + c);
    else if (c < 512) v = *(const float4*)(fused + (size_t)r * H + (c - 256));
    else v = make_float4(0.f, 0.f, 0.f, 0.f);
    *(float4*)(zb + (size_t)r * ZW + c) = v;
}

// ---------------- scatter add (vector red) ----------------
__global__ void scatter_add_kernel(float* __restrict__ out, long ostride,
                                   const float* __restrict__ in, long istride,
                                   const int* __restrict__ gidx, const int* __restrict__ sidx,
                                   int m)
{
    long t = (long)blockIdx.x * blockDim.x + threadIdx.x;
    if (t >= (long)m * 64) return;
    int e = (int)(t >> 6);
    int c = (int)(t & 63) << 2;
    int rin = gidx ? gidx[e] : e;
    int rout = sidx[e];
    float4 v = *(const float4*)(in + (size_t)rin * istride + c);
    red_add_v4(out + (size_t)rout * ostride + c, v);
}

// fused_nodes: read lg row once, reduce to both endpoints
__global__ void scatter_both_kernel(float* __restrict__ out, const float* __restrict__ in,
                                    const int* __restrict__ src, const int* __restrict__ dst,
                                    int m)
{
    long t = (long)blockIdx.x * blockDim.x + threadIdx.x;
    if (t >= (long)m * 64) return;
    int e = (int)(t >> 6);
    int c = (int)(t & 63) << 2;
    float4 v = *(const float4*)(in + (size_t)e * H + c);
    red_add_v4(out + (size_t)src[e] * H + c, v);
    red_add_v4(out + (size_t)dst[e] * H + c, v);
}

__global__ void gather_sum_kernel(float* __restrict__ out, const float* __restrict__ x,
                                  const int* __restrict__ src, const int* __restrict__ dst,
                                  int m)
{
    long t = (long)blockIdx.x * blockDim.x + threadIdx.x;
    if (t >= (long)m * 64) return;
    int e = (int)(t >> 6);
    int c = (int)(t & 63) << 2;
    float4 a = *(const float4*)(x + (size_t)src[e] * H + c);
    float4 b = *(const float4*)(x + (size_t)dst[e] * H + c);
    *(float4*)(out + (size_t)e * H + c) = make_float4(a.x + b.x, a.y + b.y, a.z + b.z, a.w + b.w);
}

__global__ void gather_embed_kernel(float* __restrict__ out, const float* __restrict__ rel,
                                    const int* __restrict__ feat, int m)
{
    long t = (long)blockIdx.x * blockDim.x + threadIdx.x;
    if (t >= (long)m * 64) return;
    int e = (int)(t >> 6);
    int c = (int)(t & 63) << 2;
    *(float4*)(out + (size_t)e * H + c) = *(const float4*)(rel + (size_t)feat[e] * H + c);
}

// ---------------- residual + (gelu) + layernorm, one warp per row ----------------
__global__ void residual_ln_kernel(const float* __restrict__ resid,
                                   const float* __restrict__ y,
                                   const float* __restrict__ gamma,
                                   const float* __restrict__ beta,
                                   float* __restrict__ out,
                                   int n, int do_gelu)
{
    int gw = (int)(((long)blockIdx.x * blockDim.x + threadIdx.x) >> 5);
    int lane = threadIdx.x & 31;
    if (gw >= n) return;
    const float* rp = resid + (size_t)gw * H;
    const float* yp = y + (size_t)gw * H;
    float v[8];
    float sum = 0.f, sq = 0.f;
#pragma unroll
    for (int h = 0; h < 2; h++) {
        int c = h * 128 + lane * 4;
        float4 a = *(const float4*)(rp + c);
        float4 b = *(const float4*)(yp + c);
        float tb[4] = {b.x, b.y, b.z, b.w};
        float ta[4] = {a.x, a.y, a.z, a.w};
#pragma unroll
        for (int j = 0; j < 4; j++) {
            float u = do_gelu ? gelu_f(tb[j]) : tb[j];
            u += ta[j];
            v[h * 4 + j] = u;
            sum += u;
            sq += u * u;
        }
    }
#pragma unroll
    for (int o = 16; o > 0; o >>= 1) {
        sum += __shfl_xor_sync(0xFFFFFFFFu, sum, o);
        sq  += __shfl_xor_sync(0xFFFFFFFFu, sq, o);
    }
    float mean = sum * (1.0f / H);
    float var = sq * (1.0f / H) - mean * mean;
    float rstd = rsqrtf(var + 1e-5f);
    float* op = out + (size_t)gw * H;
#pragma unroll
    for (int h = 0; h < 2; h++) {
        int c = h * 128 + lane * 4;
        float4 gv = *(const float4*)(gamma + c);
        float4 bv = *(const float4*)(beta + c);
        float4 o4;
        o4.x = (v[h * 4 + 0] - mean) * rstd * gv.x + bv.x;
        o4.y = (v[h * 4 + 1] - mean) * rstd * gv.y + bv.y;
        o4.z = (v[h * 4 + 2] - mean) * rstd * gv.z + bv.z;
        o4.w = (v[h * 4 + 3] - mean) * rstd * gv.w + bv.w;
        *(float4*)(op + c) = o4;
    }
}

// ---------------- host side ----------------
static inline int blocks_for(long threads) { return (int)((threads + 255) / 256); }

static inline void launch_gemm(const float* A, int lda, const float* Bt, const float* bias,
                               float* C, int M, int N, int K, int flags)
{
    dim3 grid(N / 256, (M + 127) / 128);
    mma_gemm<<<grid, 256, GEMM_SMEM>>>(A, lda, Bt, bias, C, M, N, K, flags);
}

struct Scratch {
    float *x0, *x1, *lg0, *lg1, *fn, *fe, *zbig, *acc, *ln1, *ffh;
    float *wtcat, *wt1, *wt2, *bcat;
};

static void run_core(const Scratch& S,
                     const float* xin, const float* fused, float* xout,
                     int n, const int* src, const int* dst, int m,
                     int lc,
                     const float* b_ff1, const float* b_ff2,
                     const float* g1, const float* c1,
                     const float* g2, const float* c2)
{
    // Zbig = [xin | fused | 0...]
    init_zbig_kernel<<<blocks_for((long)n * (ZW / 4)), 256>>>(S.zbig, xin, fused, n);

    // k-hop chain into Zbig slices 2..5
    for (int i = 1; i <= KHOPS; i++) {
        const float* in = (i == 1) ? xin : (S.zbig + (size_t)i * H);
        long istride = (i == 1) ? H : ZW;
        float* out = S.zbig + (size_t)(i + 1) * H;
        scatter_add_kernel<<<blocks_for((long)m * 64), 256>>>(out, ZW, in, istride, src, dst, m);
    }

    // acc = Zbig @ Wcat + bcat
    launch_gemm(S.zbig, ZW, S.wtcat + (size_t)lc * H * ZW, S.bcat + (size_t)lc * H,
                S.acc, n, H, ZW, 0);

    // ln1 = LN(xin + gelu(acc))
    residual_ln_kernel<<<(n + 7) / 8, 256>>>(xin, S.acc, g1, c1, S.ln1, n, 1);

    // ffh = gelu(ln1 @ w1 + b1)
    launch_gemm(S.ln1, H, S.wt1 + (size_t)lc * FH * H, b_ff1, S.ffh, n, FH, H, FLAG_GELU);
    // acc = ffh @ w2 + b2
    launch_gemm(S.ffh, FH, S.wt2 + (size_t)lc * H * FH, b_ff2, S.acc, n, H, FH, 0);

    // xout = LN(ln1 + acc)
    residual_ln_kernel<<<(n + 7) / 8, 256>>>(S.ln1, S.acc, g2, c2, xout, n, 0);
}

extern "C" void kernel_launch(void* const* d_in, const int* in_sizes, int n_in,
                              void* d_out, int out_size)
{
    const float* x_in      = (const float*)d_in[0];
    const int*   edge_feat = (const int*)d_in[1];
    const int*   eig       = (const int*)d_in[2];
    const int*   eil       = (const int*)d_in[3];
    const float* rel       = (const float*)d_in[4];
    const float* w_self    = (const float*)d_in[5];
    const float* b_self    = (const float*)d_in[6];
    const float* w_khop    = (const float*)d_in[7];
    const float* b_khop    = (const float*)d_in[8];
    const float* w_fuse    = (const float*)d_in[9];
    const float* b_fuse    = (const float*)d_in[10];
    const float* w_ff1     = (const float*)d_in[11];
    const float* b_ff1     = (const float*)d_in[12];
    const float* w_ff2     = (const float*)d_in[13];
    const float* b_ff2     = (const float*)d_in[14];
    const float* ln1_g     = (const float*)d_in[15];
    const float* ln1_b     = (const float*)d_in[16];
    const float* ln2_g     = (const float*)d_in[17];
    const float* ln2_b     = (const float*)d_in[18];

    const int* src_g = eig;
    const int* dst_g = eig + NEDGES;
    const int* src_l = eil;
    const int* dst_l = eil + NLGE;

    cudaFuncSetAttribute(mma_gemm, cudaFuncAttributeMaxDynamicSharedMemorySize, GEMM_SMEM);

    Scratch S;
    void* p;
    cudaGetSymbolAddress(&p, g_x0);    S.x0    = (float*)p;
    cudaGetSymbolAddress(&p, g_x1);    S.x1    = (float*)p;
    cudaGetSymbolAddress(&p, g_lg0);   S.lg0   = (float*)p;
    cudaGetSymbolAddress(&p, g_lg1);   S.lg1   = (float*)p;
    cudaGetSymbolAddress(&p, g_fn);    S.fn    = (float*)p;
    cudaGetSymbolAddress(&p, g_fe);    S.fe    = (float*)p;
    cudaGetSymbolAddress(&p, g_zbig);  S.zbig  = (float*)p;
    cudaGetSymbolAddress(&p, g_acc);   S.acc   = (float*)p;
    cudaGetSymbolAddress(&p, g_ln1);   S.ln1   = (float*)p;
    cudaGetSymbolAddress(&p, g_ffh);   S.ffh   = (float*)p;
    cudaGetSymbolAddress(&p, g_wtcat); S.wtcat = (float*)p;
    cudaGetSymbolAddress(&p, g_wt1);   S.wt1   = (float*)p;
    cudaGetSymbolAddress(&p, g_wt2);   S.wt2   = (float*)p;
    cudaGetSymbolAddress(&p, g_bcat);  S.bcat  = (float*)p;

    // weight prep (tf32-rounded)
    build_wtcat_kernel<<<blocks_for((long)4 * H * ZW), 256>>>(w_self, w_fuse, w_khop, S.wtcat);
    build_wt1_kernel<<<blocks_for((long)4 * FH * H), 256>>>(w_ff1, S.wt1);
    build_wt2_kernel<<<blocks_for((long)4 * H * FH), 256>>>(w_ff2, S.wt2);
    build_bcat_kernel<<<blocks_for(4 * H), 256>>>(b_self, b_fuse, b_khop, S.bcat);

    float* xb[2]  = {S.x0, S.x1};
    float* lgb[2] = {S.lg0, S.lg1};

    cudaMemcpyAsync(S.x0, x_in, (size_t)NNODES * H * sizeof(float), cudaMemcpyDeviceToDevice);
    gather_embed_kernel<<<blocks_for((long)NEDGES * 64), 256>>>(S.lg0, rel, edge_feat, NEDGES);

    int cur = 0;
    for (int l = 0; l < LNUM; l++) {
        const float* x  = xb[cur];
        const float* lg = lgb[cur];
        float* xn  = xb[1 - cur];
        float* lgn = lgb[1 - cur];

        cudaMemsetAsync(S.fn, 0, (size_t)NNODES * H * sizeof(float));
        scatter_both_kernel<<<blocks_for((long)NEDGES * 64), 256>>>(S.fn, lg, src_g, dst_g, NEDGES);
        gather_sum_kernel<<<blocks_for((long)NEDGES * 64), 256>>>(S.fe, x, src_g, dst_g, NEDGES);

        {
            int lc = l * 2 + 0;
            run_core(S, x, S.fn, xn, NNODES, src_g, dst_g, NEDGES, lc,
                     b_ff1 + (size_t)lc * FH, b_ff2 + (size_t)lc * H,
                     ln1_g + (size_t)lc * H, ln1_b + (size_t)lc * H,
                     ln2_g + (size_t)lc * H, ln2_b + (size_t)lc * H);
        }
        {
            int lc = l * 2 + 1;
            run_core(S, lg, S.fe, lgn, NEDGES, src_l, dst_l, NLGE, lc,
                     b_ff1 + (size_t)lc * FH, b_ff2 + (size_t)lc * H,
                     ln1_g + (size_t)lc * H, ln1_b + (size_t)lc * H,
                     ln2_g + (size_t)lc * H, ln2_b + (size_t)lc * H);
        }
        cur = 1 - cur;
    }

    cudaMemcpyAsync(d_out, xb[cur], (size_t)NNODES * H * sizeof(float),
                    cudaMemcpyDeviceToDevice);
    cudaMemcpyAsync((float*)d_out + (size_t)NNODES * H, lgb[cur],
                    (size_t)NEDGES * H * sizeof(float), cudaMemcpyDeviceToDevice);
}

// round 7
// speedup vs baseline: 2.6991x; 1.0069x over previous
#include <cuda_runtime.h>
#include <math.h>
#include <stdint.h>

#define H 256
#define FH 1024
#define LNUM 2
#define KHOPS 4
#define NNODES 20000
#define NEDGES 160000
#define NLGE 640000

// ---------------- scratch (device globals; no allocations) ----------------
__device__ __align__(256) float g_x0[(size_t)NNODES * H];
__device__ __align__(256) float g_x1[(size_t)NNODES * H];
__device__ __align__(256) float g_lg0[(size_t)NEDGES * H];
__device__ __align__(256) float g_lg1[(size_t)NEDGES * H];
__device__ __align__(256) float g_fn[(size_t)NNODES * H];
__device__ __align__(256) float g_fe[(size_t)NEDGES * H];
__device__ __align__(256) float g_z[(size_t)4 * NEDGES * H];   // z1..z4 hop buffers
__device__ __align__(256) float g_ln1[(size_t)NEDGES * H];
__device__ __align__(256) float g_ffh[(size_t)NEDGES * FH];
// pre-transposed (and tf32-rounded) weights, [lc][N][K] K-major
__device__ __align__(256) float g_wtcat[(size_t)4 * H * (6 * H)];
__device__ __align__(256) float g_wt1[(size_t)4 * FH * H];
__device__ __align__(256) float g_wt2[(size_t)4 * H * FH];
__device__ __align__(256) float g_bcat[(size_t)4 * H];

// ---------------- device helpers ----------------
__device__ __forceinline__ float to_tf32(float x) {
    float y;
    asm("cvt.rna.tf32.f32 %0, %1;" : "=f"(y) : "f"(x));
    return y;
}
__device__ __forceinline__ float gelu_f(float v) {
    return 0.5f * v * (1.0f + erff(v * 0.70710678118654752f));
}
__device__ __forceinline__ void red_add_v4(float* addr, float4 v) {
    asm volatile("red.global.add.v4.f32 [%0], {%1, %2, %3, %4};"
                 :: "l"(addr), "f"(v.x), "f"(v.y), "f"(v.z), "f"(v.w) : "memory");
}
__device__ __forceinline__ void cp_async16(uint32_t saddr, const void* gptr) {
    asm volatile("cp.async.cg.shared.global [%0], [%1], 16;" :: "r"(saddr), "l"(gptr));
}
#define CP_COMMIT() asm volatile("cp.async.commit_group;")
#define CP_WAIT0()  asm volatile("cp.async.wait_group 0;")

// ---------------- tf32 mma.sync GEMM with segmented A + fused epilogues ----------------
// C[M,N] = concat_A[M,K] @ Bt[N,K]^T + bias, then per-mode epilogue.
// A comes from up to 6 slices of 256 columns each (ptr, row-stride).
// Block tile 128x256, BK=32, 8 warps (64x64 warp tiles), double-buffered.
// mode 0: gelu(out) -> C                      (FFN1, N may be >256)
// mode 1: LN( resid + gelu(out) ) -> C        (post-concat GEMM; requires N==256, grid.x==1)
// mode 2: LN( resid + out ) -> C              (post-FFN2;        requires N==256, grid.x==1)
#define BK 32
#define ASTR 36
#define ABUF_A (128 * ASTR)
#define ABUF_B (256 * ASTR)
#define GEMM_SMEM ((2 * ABUF_A + 2 * ABUF_B) * 4)

struct SliceArgs {
    const float* p[6];
    int ld[6];
};

__device__ __forceinline__ void mma_tf32(float* c, const uint32_t* a, const uint32_t* b) {
    asm volatile(
        "mma.sync.aligned.m16n8k8.row.col.f32.tf32.tf32.f32 "
        "{%0,%1,%2,%3}, {%4,%5,%6,%7}, {%8,%9}, {%0,%1,%2,%3};"
        : "+f"(c[0]), "+f"(c[1]), "+f"(c[2]), "+f"(c[3])
        : "r"(a[0]), "r"(a[1]), "r"(a[2]), "r"(a[3]), "r"(b[0]), "r"(b[1]));
}

__global__ __launch_bounds__(256)
void mma_gemm2(SliceArgs sa,
               const float* __restrict__ Bt,
               const float* __restrict__ bias,
               const float* __restrict__ resid,
               const float* __restrict__ gamma,
               const float* __restrict__ beta,
               float* __restrict__ C,
               int M, int N, int K, int mode)
{
    extern __shared__ float smem[];
    float* AsBase = smem;                     // [2][128][ASTR]
    float* BsBase = smem + 2 * ABUF_A;        // [2][256][ASTR]

    const int tid = threadIdx.x;
    const int wid = tid >> 5, lane = tid & 31;
    const int gid = lane >> 2, tig = lane & 3;
    const int warp_m = (wid & 1) * 64;
    const int warp_n = (wid >> 1) * 64;
    const int row0 = blockIdx.y * 128;
    const int col0 = blockIdx.x * 256;

    float acc[4][8][4];
#pragma unroll
    for (int mt = 0; mt < 4; mt++)
#pragma unroll
        for (int nt = 0; nt < 8; nt++)
#pragma unroll
            for (int j = 0; j < 4; j++) acc[mt][nt][j] = 0.f;

    const int nc = K / BK;
    float4 ra[4];

    // ---- prologue: chunk 0 (slice 0) ----
#pragma unroll
    for (int f = 0; f < 8; f++) {
        int i = f * 256 + tid, r = i >> 3, c4 = i & 7;
        uint32_t dst = (uint32_t)__cvta_generic_to_shared(BsBase + r * ASTR + c4 * 4);
        cp_async16(dst, Bt + (size_t)(col0 + r) * K + c4 * 4);
    }
    CP_COMMIT();
    {
        const float* Ap = sa.p[0];
        const int ldA = sa.ld[0];
#pragma unroll
        for (int f = 0; f < 4; f++) {
            int i = f * 256 + tid, r = i >> 3, c4 = i & 7;
            int gr = row0 + r; if (gr >= M) gr = M - 1;
            ra[f] = *(const float4*)(Ap + (size_t)gr * ldA + c4 * 4);
        }
    }
#pragma unroll
    for (int f = 0; f < 4; f++) {
        int i = f * 256 + tid, r = i >> 3, c4 = i & 7;
        float4 v = ra[f];
        v.x = to_tf32(v.x); v.y = to_tf32(v.y); v.z = to_tf32(v.z); v.w = to_tf32(v.w);
        *(float4*)(AsBase + r * ASTR + c4 * 4) = v;
    }
    CP_WAIT0();
    __syncthreads();

    for (int c = 0; c < nc; c++) {
        const int nxt = c + 1;
        if (nxt < nc) {
            const int k0 = nxt * BK;
            float* Bs = BsBase + (nxt & 1) * ABUF_B;
#pragma unroll
            for (int f = 0; f < 8; f++) {
                int i = f * 256 + tid, r = i >> 3, c4 = i & 7;
                uint32_t dst = (uint32_t)__cvta_generic_to_shared(Bs + r * ASTR + c4 * 4);
                cp_async16(dst, Bt + (size_t)(col0 + r) * K + k0 + c4 * 4);
            }
            CP_COMMIT();
            const int sl = k0 >> 8;
            const int off = k0 & 255;
            const float* Ap = sa.p[sl];
            const int ldA = sa.ld[sl];
#pragma unroll
            for (int f = 0; f < 4; f++) {
                int i = f * 256 + tid, r = i >> 3, c4 = i & 7;
                int gr = row0 + r; if (gr >= M) gr = M - 1;
                ra[f] = *(const float4*)(Ap + (size_t)gr * ldA + off + c4 * 4);
            }
        }

        const uint32_t* Asu = (const uint32_t*)(AsBase + (c & 1) * ABUF_A);
        const uint32_t* Bsu = (const uint32_t*)(BsBase + (c & 1) * ABUF_B);
#pragma unroll
        for (int ks = 0; ks < 4; ks++) {
            const int k0c = ks * 8;
            uint32_t afr[4][4], bfr[8][2];
#pragma unroll
            for (int mt = 0; mt < 4; mt++) {
                int r = warp_m + mt * 16 + gid;
                afr[mt][0] = Asu[r * ASTR + k0c + tig];
                afr[mt][1] = Asu[(r + 8) * ASTR + k0c + tig];
                afr[mt][2] = Asu[r * ASTR + k0c + tig + 4];
                afr[mt][3] = Asu[(r + 8) * ASTR + k0c + tig + 4];
            }
#pragma unroll
            for (int nt = 0; nt < 8; nt++) {
                int cc = warp_n + nt * 8 + gid;
                bfr[nt][0] = Bsu[cc * ASTR + k0c + tig];
                bfr[nt][1] = Bsu[cc * ASTR + k0c + tig + 4];
            }
#pragma unroll
            for (int mt = 0; mt < 4; mt++)
#pragma unroll
                for (int nt = 0; nt < 8; nt++)
                    mma_tf32(acc[mt][nt], afr[mt], bfr[nt]);
        }

        if (nxt < nc) {
            float* As = AsBase + (nxt & 1) * ABUF_A;
#pragma unroll
            for (int f = 0; f < 4; f++) {
                int i = f * 256 + tid, r = i >> 3, c4 = i & 7;
                float4 v = ra[f];
                v.x = to_tf32(v.x); v.y = to_tf32(v.y); v.z = to_tf32(v.z); v.w = to_tf32(v.w);
                *(float4*)(As + r * ASTR + c4 * 4) = v;
            }
            CP_WAIT0();
        }
        __syncthreads();
    }

    if (mode == 0) {
        // plain gelu epilogue (FFN1)
#pragma unroll
        for (int mt = 0; mt < 4; mt++) {
#pragma unroll
            for (int nt = 0; nt < 8; nt++) {
                int cc = col0 + warp_n + nt * 8 + 2 * tig;
                float bx = bias[cc], by = bias[cc + 1];
#pragma unroll
                for (int h = 0; h < 2; h++) {
                    int r = row0 + warp_m + mt * 16 + gid + h * 8;
                    if (r >= M) continue;
                    float ox = gelu_f(acc[mt][nt][h * 2 + 0] + bx);
                    float oy = gelu_f(acc[mt][nt][h * 2 + 1] + by);
                    *(float2*)(C + (size_t)r * N + cc) = make_float2(ox, oy);
                }
            }
        }
        return;
    }

    // ---- fused LayerNorm epilogue (N == 256, grid.x == 1) ----
    float2* rowstat = (float2*)smem;   // [128][4]
    float sumv[4][2], sqv[4][2];
#pragma unroll
    for (int mt = 0; mt < 4; mt++)
#pragma unroll
        for (int h = 0; h < 2; h++) { sumv[mt][h] = 0.f; sqv[mt][h] = 0.f; }

#pragma unroll
    for (int mt = 0; mt < 4; mt++) {
#pragma unroll
        for (int h = 0; h < 2; h++) {
            int r = row0 + warp_m + mt * 16 + gid + h * 8;
            int rc = r < M ? r : M - 1;
#pragma unroll
            for (int nt = 0; nt < 8; nt++) {
                int cc = warp_n + nt * 8 + 2 * tig;
                float2 b2 = *(const float2*)(bias + cc);
                float2 rd = *(const float2*)(resid + (size_t)rc * H + cc);
                float vx = acc[mt][nt][h * 2 + 0] + b2.x;
                float vy = acc[mt][nt][h * 2 + 1] + b2.y;
                if (mode == 1) { vx = gelu_f(vx); vy = gelu_f(vy); }
                vx += rd.x; vy += rd.y;
                acc[mt][nt][h * 2 + 0] = vx;
                acc[mt][nt][h * 2 + 1] = vy;
                sumv[mt][h] += vx + vy;
                sqv[mt][h] += vx * vx + vy * vy;
            }
        }
    }
    // reduce over the 4 tig lanes (same rows, different cols)
#pragma unroll
    for (int mt = 0; mt < 4; mt++)
#pragma unroll
        for (int h = 0; h < 2; h++) {
            sumv[mt][h] += __shfl_xor_sync(0xFFFFFFFFu, sumv[mt][h], 1);
            sumv[mt][h] += __shfl_xor_sync(0xFFFFFFFFu, sumv[mt][h], 2);
            sqv[mt][h]  += __shfl_xor_sync(0xFFFFFFFFu, sqv[mt][h], 1);
            sqv[mt][h]  += __shfl_xor_sync(0xFFFFFFFFu, sqv[mt][h], 2);
        }
    if (tig == 0) {
        int wn = warp_n >> 6;
#pragma unroll
        for (int mt = 0; mt < 4; mt++)
#pragma unroll
            for (int h = 0; h < 2; h++) {
                int rl = warp_m + mt * 16 + gid + h * 8;
                rowstat[rl * 4 + wn] = make_float2(sumv[mt][h], sqv[mt][h]);
            }
    }
    __syncthreads();

    float mean_[4][2], rstd_[4][2];
#pragma unroll
    for (int mt = 0; mt < 4; mt++)
#pragma unroll
        for (int h = 0; h < 2; h++) {
            int rl = warp_m + mt * 16 + gid + h * 8;
            float s = 0.f, q = 0.f;
#pragma unroll
            for (int w = 0; w < 4; w++) {
                float2 t = rowstat[rl * 4 + w];
                s += t.x; q += t.y;
            }
            float mean = s * (1.0f / H);
            float var = q * (1.0f / H) - mean * mean;
            mean_[mt][h] = mean;
            rstd_[mt][h] = rsqrtf(var + 1e-5f);
        }

#pragma unroll
    for (int mt = 0; mt < 4; mt++) {
#pragma unroll
        for (int nt = 0; nt < 8; nt++) {
            int cc = warp_n + nt * 8 + 2 * tig;
            float2 gv = *(const float2*)(gamma + cc);
            float2 bv = *(const float2*)(beta + cc);
#pragma unroll
            for (int h = 0; h < 2; h++) {
                int r = row0 + warp_m + mt * 16 + gid + h * 8;
                if (r >= M) continue;
                float m = mean_[mt][h], rs = rstd_[mt][h];
                float ox = (acc[mt][nt][h * 2 + 0] - m) * rs * gv.x + bv.x;
                float oy = (acc[mt][nt][h * 2 + 1] - m) * rs * gv.y + bv.y;
                *(float2*)(C + (size_t)r * H + cc) = make_float2(ox, oy);
            }
        }
    }
}

// ---------------- weight prep (transpose to [N,K] K-major, tf32-rounded) ----------------
__global__ void build_wtcat_kernel(const float* __restrict__ ws, const float* __restrict__ wf,
                                   const float* __restrict__ wk, float* __restrict__ out)
{
    long t = (long)blockIdx.x * blockDim.x + threadIdx.x;
    if (t >= (long)4 * H * 1536) return;
    int lc = (int)(t / (H * 1536));
    int rem = (int)(t % (H * 1536));
    int n = rem / 1536, k = rem % 1536;
    float v;
    if (k < 256) v = ws[(size_t)lc * 65536 + k * 256 + n];
    else if (k < 512) v = wf[(size_t)lc * 65536 + (k - 256) * 256 + n];
    else {
        int hop = (k - 512) >> 8, kk = (k - 512) & 255;
        v = wk[((size_t)(lc * 4 + hop) * 256 + kk) * 256 + n];
    }
    out[t] = to_tf32(v);
}

__global__ void build_wt1_kernel(const float* __restrict__ w1, float* __restrict__ out)
{
    long t = (long)blockIdx.x * blockDim.x + threadIdx.x;
    if (t >= (long)4 * FH * H) return;
    int lc = (int)(t / (FH * H));
    int rem = (int)(t % (FH * H));
    int n = rem / H, k = rem % H;
    out[t] = to_tf32(w1[(size_t)lc * (H * FH) + (size_t)k * FH + n]);
}

__global__ void build_wt2_kernel(const float* __restrict__ w2, float* __restrict__ out)
{
    long t = (long)blockIdx.x * blockDim.x + threadIdx.x;
    if (t >= (long)4 * H * FH) return;
    int lc = (int)(t / (H * FH));
    int rem = (int)(t % (H * FH));
    int n = rem / FH, k = rem % FH;
    out[t] = to_tf32(w2[(size_t)lc * (FH * H) + (size_t)k * H + n]);
}

__global__ void build_bcat_kernel(const float* __restrict__ bs, const float* __restrict__ bf,
                                  const float* __restrict__ bk, float* __restrict__ out)
{
    int t = blockIdx.x * blockDim.x + threadIdx.x;
    if (t >= 4 * H) return;
    int lc = t / H, n = t % H;
    float v = bs[lc * H + n] + bf[lc * H + n];
    for (int i = 0; i < KHOPS; i++) v += bk[(lc * KHOPS + i) * H + n];
    out[t] = v;
}

// ---------------- scatter / gather ----------------
__global__ void scatter_add_kernel(float* __restrict__ out, const float* __restrict__ in,
                                   const int* __restrict__ sidx, int m)
{
    long t = (long)blockIdx.x * blockDim.x + threadIdx.x;
    if (t >= (long)m * 64) return;
    int e = (int)(t >> 6);
    int c = (int)(t & 63) << 2;
    float4 v = *(const float4*)(in + (size_t)e * H + c);
    red_add_v4(out + (size_t)sidx[e] * H + c, v);
}

__global__ void scatter_gather_kernel(float* __restrict__ out, const float* __restrict__ in,
                                      const int* __restrict__ gidx, const int* __restrict__ sidx,
                                      int m)
{
    long t = (long)blockIdx.x * blockDim.x + threadIdx.x;
    if (t >= (long)m * 64) return;
    int e = (int)(t >> 6);
    int c = (int)(t & 63) << 2;
    float4 v = *(const float4*)(in + (size_t)gidx[e] * H + c);
    red_add_v4(out + (size_t)sidx[e] * H + c, v);
}

// fused_nodes: read lg row once, reduce to both endpoints
__global__ void scatter_both_kernel(float* __restrict__ out, const float* __restrict__ in,
                                    const int* __restrict__ src, const int* __restrict__ dst,
                                    int m)
{
    long t = (long)blockIdx.x * blockDim.x + threadIdx.x;
    if (t >= (long)m * 64) return;
    int e = (int)(t >> 6);
    int c = (int)(t & 63) << 2;
    float4 v = *(const float4*)(in + (size_t)e * H + c);
    red_add_v4(out + (size_t)src[e] * H + c, v);
    red_add_v4(out + (size_t)dst[e] * H + c, v);
}

__global__ void gather_sum_kernel(float* __restrict__ out, const float* __restrict__ x,
                                  const int* __restrict__ src, const int* __restrict__ dst,
                                  int m)
{
    long t = (long)blockIdx.x * blockDim.x + threadIdx.x;
    if (t >= (long)m * 64) return;
    int e = (int)(t >> 6);
    int c = (int)(t & 63) << 2;
    float4 a = *(const float4*)(x + (size_t)src[e] * H + c);
    float4 b = *(const float4*)(x + (size_t)dst[e] * H + c);
    *(float4*)(out + (size_t)e * H + c) = make_float4(a.x + b.x, a.y + b.y, a.z + b.z, a.w + b.w);
}

__global__ void gather_embed_kernel(float* __restrict__ out, const float* __restrict__ rel,
                                    const int* __restrict__ feat, int m)
{
    long t = (long)blockIdx.x * blockDim.x + threadIdx.x;
    if (t >= (long)m * 64) return;
    int e = (int)(t >> 6);
    int c = (int)(t & 63) << 2;
    *(float4*)(out + (size_t)e * H + c) = *(const float4*)(rel + (size_t)feat[e] * H + c);
}

// ---------------- host side ----------------
static inline int blocks_for(long threads) { return (int)((threads + 255) / 256); }

struct Scratch {
    float *x0, *x1, *lg0, *lg1, *fn, *fe, *z, *ln1, *ffh;
    float *wtcat, *wt1, *wt2, *bcat;
};

static void run_core(const Scratch& S,
                     const float* xin, const float* fused, float* xout,
                     int n, const int* src, const int* dst, int m,
                     int lc,
                     const float* b_ff1, const float* b_ff2,
                     const float* g1, const float* c1,
                     const float* g2, const float* c2)
{
    const int gy = (n + 127) / 128;
    float* z1 = S.z;
    float* z2 = S.z + (size_t)NEDGES * H;
    float* z3 = S.z + (size_t)2 * NEDGES * H;
    float* z4 = S.z + (size_t)3 * NEDGES * H;

    // zero hop buffers (only the n rows used)
    cudaMemsetAsync(z1, 0, (size_t)n * H * sizeof(float));
    cudaMemsetAsync(z2, 0, (size_t)n * H * sizeof(float));
    cudaMemsetAsync(z3, 0, (size_t)n * H * sizeof(float));
    cudaMemsetAsync(z4, 0, (size_t)n * H * sizeof(float));

    // k-hop chain
    scatter_gather_kernel<<<blocks_for((long)m * 64), 256>>>(z1, xin, src, dst, m);
    scatter_gather_kernel<<<blocks_for((long)m * 64), 256>>>(z2, z1, src, dst, m);
    scatter_gather_kernel<<<blocks_for((long)m * 64), 256>>>(z3, z2, src, dst, m);
    scatter_gather_kernel<<<blocks_for((long)m * 64), 256>>>(z4, z3, src, dst, m);

    // ln1 = LN( xin + gelu( concat_A @ Wcat + bcat ) )
    {
        SliceArgs sa;
        sa.p[0] = xin;   sa.ld[0] = H;
        sa.p[1] = fused; sa.ld[1] = H;
        sa.p[2] = z1;    sa.ld[2] = H;
        sa.p[3] = z2;    sa.ld[3] = H;
        sa.p[4] = z3;    sa.ld[4] = H;
        sa.p[5] = z4;    sa.ld[5] = H;
        mma_gemm2<<<dim3(1, gy), 256, GEMM_SMEM>>>(
            sa, S.wtcat + (size_t)lc * H * 1536, S.bcat + (size_t)lc * H,
            xin, g1, c1, S.ln1, n, H, 1536, 1);
    }
    // ffh = gelu(ln1 @ w1 + b1)
    {
        SliceArgs sa;
        sa.p[0] = S.ln1; sa.ld[0] = H;
        for (int i = 1; i < 6; i++) { sa.p[i] = S.ln1; sa.ld[i] = H; }
        mma_gemm2<<<dim3(FH / 256, gy), 256, GEMM_SMEM>>>(
            sa, S.wt1 + (size_t)lc * FH * H, b_ff1,
            nullptr, nullptr, nullptr, S.ffh, n, FH, H, 0);
    }
    // xout = LN( ln1 + ffh @ w2 + b2 )
    {
        SliceArgs sa;
        for (int i = 0; i < 4; i++) { sa.p[i] = S.ffh + i * 256; sa.ld[i] = FH; }
        sa.p[4] = S.ffh; sa.ld[4] = FH;
        sa.p[5] = S.ffh; sa.ld[5] = FH;
        mma_gemm2<<<dim3(1, gy), 256, GEMM_SMEM>>>(
            sa, S.wt2 + (size_t)lc * H * FH, b_ff2,
            S.ln1, g2, c2, xout, n, H, FH, 2);
    }
}

extern "C" void kernel_launch(void* const* d_in, const int* in_sizes, int n_in,
                              void* d_out, int out_size)
{
    const float* x_in      = (const float*)d_in[0];
    const int*   edge_feat = (const int*)d_in[1];
    const int*   eig       = (const int*)d_in[2];
    const int*   eil       = (const int*)d_in[3];
    const float* rel       = (const float*)d_in[4];
    const float* w_self    = (const float*)d_in[5];
    const float* b_self    = (const float*)d_in[6];
    const float* w_khop    = (const float*)d_in[7];
    const float* b_khop    = (const float*)d_in[8];
    const float* w_fuse    = (const float*)d_in[9];
    const float* b_fuse    = (const float*)d_in[10];
    const float* w_ff1     = (const float*)d_in[11];
    const float* b_ff1     = (const float*)d_in[12];
    const float* w_ff2     = (const float*)d_in[13];
    const float* b_ff2     = (const float*)d_in[14];
    const float* ln1_g     = (const float*)d_in[15];
    const float* ln1_b     = (const float*)d_in[16];
    const float* ln2_g     = (const float*)d_in[17];
    const float* ln2_b     = (const float*)d_in[18];

    const int* src_g = eig;
    const int* dst_g = eig + NEDGES;
    const int* src_l = eil;
    const int* dst_l = eil + NLGE;

    cudaFuncSetAttribute(mma_gemm2, cudaFuncAttributeMaxDynamicSharedMemorySize, GEMM_SMEM);

    Scratch S;
    void* p;
    cudaGetSymbolAddress(&p, g_x0);    S.x0    = (float*)p;
    cudaGetSymbolAddress(&p, g_x1);    S.x1    = (float*)p;
    cudaGetSymbolAddress(&p, g_lg0);   S.lg0   = (float*)p;
    cudaGetSymbolAddress(&p, g_lg1);   S.lg1   = (float*)p;
    cudaGetSymbolAddress(&p, g_fn);    S.fn    = (float*)p;
    cudaGetSymbolAddress(&p, g_fe);    S.fe    = (float*)p;
    cudaGetSymbolAddress(&p, g_z);     S.z     = (float*)p;
    cudaGetSymbolAddress(&p, g_ln1);   S.ln1   = (float*)p;
    cudaGetSymbolAddress(&p, g_ffh);   S.ffh   = (float*)p;
    cudaGetSymbolAddress(&p, g_wtcat); S.wtcat = (float*)p;
    cudaGetSymbolAddress(&p, g_wt1);   S.wt1   = (float*)p;
    cudaGetSymbolAddress(&p, g_wt2);   S.wt2   = (float*)p;
    cudaGetSymbolAddress(&p, g_bcat);  S.bcat  = (float*)p;

    // weight prep (tf32-rounded)
    build_wtcat_kernel<<<blocks_for((long)4 * H * 1536), 256>>>(w_self, w_fuse, w_khop, S.wtcat);
    build_wt1_kernel<<<blocks_for((long)4 * FH * H), 256>>>(w_ff1, S.wt1);
    build_wt2_kernel<<<blocks_for((long)4 * H * FH), 256>>>(w_ff2, S.wt2);
    build_bcat_kernel<<<blocks_for(4 * H), 256>>>(b_self, b_fuse, b_khop, S.bcat);

    float* xb[2]  = {S.x0, S.x1};
    float* lgb[2] = {S.lg0, S.lg1};

    cudaMemcpyAsync(S.x0, x_in, (size_t)NNODES * H * sizeof(float), cudaMemcpyDeviceToDevice);
    gather_embed_kernel<<<blocks_for((long)NEDGES * 64), 256>>>(S.lg0, rel, edge_feat, NEDGES);

    int cur = 0;
    for (int l = 0; l < LNUM; l++) {
        const float* x  = xb[cur];
        const float* lg = lgb[cur];
        float* xn  = xb[1 - cur];
        float* lgn = lgb[1 - cur];

        cudaMemsetAsync(S.fn, 0, (size_t)NNODES * H * sizeof(float));
        scatter_both_kernel<<<blocks_for((long)NEDGES * 64), 256>>>(S.fn, lg, src_g, dst_g, NEDGES);
        gather_sum_kernel<<<blocks_for((long)NEDGES * 64), 256>>>(S.fe, x, src_g, dst_g, NEDGES);

        {
            int lc = l * 2 + 0;
            run_core(S, x, S.fn, xn, NNODES, src_g, dst_g, NEDGES, lc,
                     b_ff1 + (size_t)lc * FH, b_ff2 + (size_t)lc * H,
                     ln1_g + (size_t)lc * H, ln1_b + (size_t)lc * H,
                     ln2_g + (size_t)lc * H, ln2_b + (size_t)lc * H);
        }
        {
            int lc = l * 2 + 1;
            run_core(S, lg, S.fe, lgn, NEDGES, src_l, dst_l, NLGE, lc,
                     b_ff1 + (size_t)lc * FH, b_ff2 + (size_t)lc * H,
                     ln1_g + (size_t)lc * H, ln1_b + (size_t)lc * H,
                     ln2_g + (size_t)lc * H, ln2_b + (size_t)lc * H);
        }
        cur = 1 - cur;
    }

    cudaMemcpyAsync(d_out, xb[cur], (size_t)NNODES * H * sizeof(float),
                    cudaMemcpyDeviceToDevice);
    cudaMemcpyAsync((float*)d_out + (size_t)NNODES * H, lgb[cur],
                    (size_t)NEDGES * H * sizeof(float), cudaMemcpyDeviceToDevice);
}

// round 8
// speedup vs baseline: 3.1659x; 1.1729x over previous
#include <cuda_runtime.h>
#include <math.h>
#include <stdint.h>

#define H 256
#define FH 1024
#define LNUM 2
#define KHOPS 4
#define NNODES 20000
#define NEDGES 160000
#define NLGE 640000

// ---------------- scratch (device globals; no allocations) ----------------
__device__ __align__(256) float g_x0[(size_t)NNODES * H];
__device__ __align__(256) float g_x1[(size_t)NNODES * H];
__device__ __align__(256) float g_lg0[(size_t)NEDGES * H];
__device__ __align__(256) float g_lg1[(size_t)NEDGES * H];
__device__ __align__(256) float g_fn[(size_t)NNODES * H];
__device__ __align__(256) float g_fe[(size_t)NEDGES * H];
__device__ __align__(256) float g_z[(size_t)4 * NEDGES * H];   // z1..z4 hop buffers
__device__ __align__(256) float g_ln1[(size_t)NEDGES * H];
__device__ __align__(256) float g_ffh[(size_t)NEDGES * FH];
// pre-transposed (and tf32-rounded) weights, [lc][N][K] K-major
__device__ __align__(256) float g_wtcat[(size_t)4 * H * (6 * H)];
__device__ __align__(256) float g_wt1[(size_t)4 * FH * H];
__device__ __align__(256) float g_wt2[(size_t)4 * H * FH];
__device__ __align__(256) float g_bcat[(size_t)4 * H];
// CSR structures
__device__ int g_rowptr_g[NNODES + 1];
__device__ int g_val_g[NEDGES];
__device__ int g_rowptr_b[NNODES + 1];
__device__ int g_val_b[2 * NEDGES];
__device__ int g_rowptr_l[NEDGES + 1];
__device__ int g_val_l[NLGE];
__device__ int g_cnt[NEDGES + 1];

// ---------------- device helpers ----------------
__device__ __forceinline__ float to_tf32(float x) {
    float y;
    asm("cvt.rna.tf32.f32 %0, %1;" : "=f"(y) : "f"(x));
    return y;
}
__device__ __forceinline__ float gelu_f(float v) {
    return 0.5f * v * (1.0f + erff(v * 0.70710678118654752f));
}
__device__ __forceinline__ void cp_async16(uint32_t saddr, const void* gptr) {
    asm volatile("cp.async.cg.shared.global [%0], [%1], 16;" :: "r"(saddr), "l"(gptr));
}
#define CP_COMMIT() asm volatile("cp.async.commit_group;")
#define CP_WAIT0()  asm volatile("cp.async.wait_group 0;")

// ---------------- CSR build ----------------
__global__ void hist_kernel(int* __restrict__ cnt, const int* __restrict__ keys, int m)
{
    int t = blockIdx.x * blockDim.x + threadIdx.x;
    if (t < m) atomicAdd(&cnt[keys[t]], 1);
}
__global__ void hist2_kernel(int* __restrict__ cnt, const int* __restrict__ k1,
                             const int* __restrict__ k2, int m)
{
    int t = blockIdx.x * blockDim.x + threadIdx.x;
    if (t < m) { atomicAdd(&cnt[k1[t]], 1); atomicAdd(&cnt[k2[t]], 1); }
}

// single-block exclusive scan; out has n+1 entries
__global__ __launch_bounds__(1024)
void scan_kernel(const int* __restrict__ in, int* __restrict__ out, int n)
{
    __shared__ int carry;
    __shared__ int warpsums[32];
    const int tid = threadIdx.x;
    const int lane = tid & 31, w = tid >> 5;
    if (tid == 0) carry = 0;
    __syncthreads();
    for (int base = 0; base < n; base += 1024) {
        int v = (base + tid < n) ? in[base + tid] : 0;
        int s = v;
#pragma unroll
        for (int o = 1; o < 32; o <<= 1) {
            int t = __shfl_up_sync(0xFFFFFFFFu, s, o);
            if (lane >= o) s += t;
        }
        if (lane == 31) warpsums[w] = s;
        __syncthreads();
        if (w == 0) {
            int ws = warpsums[lane];
#pragma unroll
            for (int o = 1; o < 32; o <<= 1) {
                int t = __shfl_up_sync(0xFFFFFFFFu, ws, o);
                if (lane >= o) ws += t;
            }
            warpsums[lane] = ws;
        }
        __syncthreads();
        int excl = s - v + (w > 0 ? warpsums[w - 1] : 0) + carry;
        if (base + tid < n) out[base + tid] = excl;
        __syncthreads();
        if (tid == 1023) carry = excl + v;
        __syncthreads();
    }
    if (threadIdx.x == 0) out[n] = carry;
}

__global__ void fill_csr_kernel(int* __restrict__ cursor, int* __restrict__ val,
                                const int* __restrict__ keys, const int* __restrict__ payload,
                                int m)
{
    int t = blockIdx.x * blockDim.x + threadIdx.x;
    if (t >= m) return;
    int pos = atomicAdd(&cursor[keys[t]], 1);
    val[pos] = payload[t];
}
__global__ void fill_csr2_kernel(int* __restrict__ cursor, int* __restrict__ val,
                                 const int* __restrict__ k1, const int* __restrict__ k2, int m)
{
    int t = blockIdx.x * blockDim.x + threadIdx.x;
    if (t >= m) return;
    int p1 = atomicAdd(&cursor[k1[t]], 1);
    val[p1] = t;
    int p2 = atomicAdd(&cursor[k2[t]], 1);
    val[p2] = t;
}

// ---------------- CSR SpMM (copy_src + sum): out[row] = sum_{j} in[val[j]] ----------------
__global__ __launch_bounds__(256)
void spmm_csr_kernel(float* __restrict__ out, const float* __restrict__ in,
                     const int* __restrict__ rowptr, const int* __restrict__ val, int n)
{
    int row = blockIdx.x * 8 + (threadIdx.x >> 5);
    if (row >= n) return;
    int lane = threadIdx.x & 31;
    int beg = rowptr[row], end = rowptr[row + 1];
    float4 a0 = make_float4(0.f, 0.f, 0.f, 0.f), a1 = a0;
    for (int j = beg; j < end; j++) {
        const float* p = in + (size_t)val[j] * H + lane * 8;
        float4 v0 = *(const float4*)p;
        float4 v1 = *(const float4*)(p + 4);
        a0.x += v0.x; a0.y += v0.y; a0.z += v0.z; a0.w += v0.w;
        a1.x += v1.x; a1.y += v1.y; a1.z += v1.z; a1.w += v1.w;
    }
    float* o = out + (size_t)row * H + lane * 8;
    *(float4*)o = a0;
    *(float4*)(o + 4) = a1;
}

// ---------------- tf32 mma.sync GEMM with segmented A + fused epilogues ----------------
#define BK 32
#define ASTR 36
#define ABUF_A (128 * ASTR)
#define ABUF_B (256 * ASTR)
#define GEMM_SMEM ((2 * ABUF_A + 2 * ABUF_B) * 4)

struct SliceArgs {
    const float* p[6];
    int ld[6];
};

__device__ __forceinline__ void mma_tf32(float* c, const uint32_t* a, const uint32_t* b) {
    asm volatile(
        "mma.sync.aligned.m16n8k8.row.col.f32.tf32.tf32.f32 "
        "{%0,%1,%2,%3}, {%4,%5,%6,%7}, {%8,%9}, {%0,%1,%2,%3};"
        : "+f"(c[0]), "+f"(c[1]), "+f"(c[2]), "+f"(c[3])
        : "r"(a[0]), "r"(a[1]), "r"(a[2]), "r"(a[3]), "r"(b[0]), "r"(b[1]));
}

__global__ __launch_bounds__(256)
void mma_gemm2(SliceArgs sa,
               const float* __restrict__ Bt,
               const float* __restrict__ bias,
               const float* __restrict__ resid,
               const float* __restrict__ gamma,
               const float* __restrict__ beta,
               float* __restrict__ C,
               int M, int N, int K, int mode)
{
    extern __shared__ float smem[];
    float* AsBase = smem;
    float* BsBase = smem + 2 * ABUF_A;

    const int tid = threadIdx.x;
    const int wid = tid >> 5, lane = tid & 31;
    const int gid = lane >> 2, tig = lane & 3;
    const int warp_m = (wid & 1) * 64;
    const int warp_n = (wid >> 1) * 64;
    const int row0 = blockIdx.y * 128;
    const int col0 = blockIdx.x * 256;

    float acc[4][8][4];
#pragma unroll
    for (int mt = 0; mt < 4; mt++)
#pragma unroll
        for (int nt = 0; nt < 8; nt++)
#pragma unroll
            for (int j = 0; j < 4; j++) acc[mt][nt][j] = 0.f;

    const int nc = K / BK;
    float4 ra[4];

#pragma unroll
    for (int f = 0; f < 8; f++) {
        int i = f * 256 + tid, r = i >> 3, c4 = i & 7;
        uint32_t dst = (uint32_t)__cvta_generic_to_shared(BsBase + r * ASTR + c4 * 4);
        cp_async16(dst, Bt + (size_t)(col0 + r) * K + c4 * 4);
    }
    CP_COMMIT();
    {
        const float* Ap = sa.p[0];
        const int ldA = sa.ld[0];
#pragma unroll
        for (int f = 0; f < 4; f++) {
            int i = f * 256 + tid, r = i >> 3, c4 = i & 7;
            int gr = row0 + r; if (gr >= M) gr = M - 1;
            ra[f] = *(const float4*)(Ap + (size_t)gr * ldA + c4 * 4);
        }
    }
#pragma unroll
    for (int f = 0; f < 4; f++) {
        int i = f * 256 + tid, r = i >> 3, c4 = i & 7;
        float4 v = ra[f];
        v.x = to_tf32(v.x); v.y = to_tf32(v.y); v.z = to_tf32(v.z); v.w = to_tf32(v.w);
        *(float4*)(AsBase + r * ASTR + c4 * 4) = v;
    }
    CP_WAIT0();
    __syncthreads();

    for (int c = 0; c < nc; c++) {
        const int nxt = c + 1;
        if (nxt < nc) {
            const int k0 = nxt * BK;
            float* Bs = BsBase + (nxt & 1) * ABUF_B;
#pragma unroll
            for (int f = 0; f < 8; f++) {
                int i = f * 256 + tid, r = i >> 3, c4 = i & 7;
                uint32_t dst = (uint32_t)__cvta_generic_to_shared(Bs + r * ASTR + c4 * 4);
                cp_async16(dst, Bt + (size_t)(col0 + r) * K + k0 + c4 * 4);
            }
            CP_COMMIT();
            const int sl = k0 >> 8;
            const int off = k0 & 255;
            const float* Ap = sa.p[sl];
            const int ldA = sa.ld[sl];
#pragma unroll
            for (int f = 0; f < 4; f++) {
                int i = f * 256 + tid, r = i >> 3, c4 = i & 7;
                int gr = row0 + r; if (gr >= M) gr = M - 1;
                ra[f] = *(const float4*)(Ap + (size_t)gr * ldA + off + c4 * 4);
            }
        }

        const uint32_t* Asu = (const uint32_t*)(AsBase + (c & 1) * ABUF_A);
        const uint32_t* Bsu = (const uint32_t*)(BsBase + (c & 1) * ABUF_B);
#pragma unroll
        for (int ks = 0; ks < 4; ks++) {
            const int k0c = ks * 8;
            uint32_t afr[4][4], bfr[8][2];
#pragma unroll
            for (int mt = 0; mt < 4; mt++) {
                int r = warp_m + mt * 16 + gid;
                afr[mt][0] = Asu[r * ASTR + k0c + tig];
                afr[mt][1] = Asu[(r + 8) * ASTR + k0c + tig];
                afr[mt][2] = Asu[r * ASTR + k0c + tig + 4];
                afr[mt][3] = Asu[(r + 8) * ASTR + k0c + tig + 4];
            }
#pragma unroll
            for (int nt = 0; nt < 8; nt++) {
                int cc = warp_n + nt * 8 + gid;
                bfr[nt][0] = Bsu[cc * ASTR + k0c + tig];
                bfr[nt][1] = Bsu[cc * ASTR + k0c + tig + 4];
            }
#pragma unroll
            for (int mt = 0; mt < 4; mt++)
#pragma unroll
                for (int nt = 0; nt < 8; nt++)
                    mma_tf32(acc[mt][nt], afr[mt], bfr[nt]);
        }

        if (nxt < nc) {
            float* As = AsBase + (nxt & 1) * ABUF_A;
#pragma unroll
            for (int f = 0; f < 4; f++) {
                int i = f * 256 + tid, r = i >> 3, c4 = i & 7;
                float4 v = ra[f];
                v.x = to_tf32(v.x); v.y = to_tf32(v.y); v.z = to_tf32(v.z); v.w = to_tf32(v.w);
                *(float4*)(As + r * ASTR + c4 * 4) = v;
            }
            CP_WAIT0();
        }
        __syncthreads();
    }

    if (mode == 0) {
#pragma unroll
        for (int mt = 0; mt < 4; mt++) {
#pragma unroll
            for (int nt = 0; nt < 8; nt++) {
                int cc = col0 + warp_n + nt * 8 + 2 * tig;
                float bx = bias[cc], by = bias[cc + 1];
#pragma unroll
                for (int h = 0; h < 2; h++) {
                    int r = row0 + warp_m + mt * 16 + gid + h * 8;
                    if (r >= M) continue;
                    float ox = gelu_f(acc[mt][nt][h * 2 + 0] + bx);
                    float oy = gelu_f(acc[mt][nt][h * 2 + 1] + by);
                    *(float2*)(C + (size_t)r * N + cc) = make_float2(ox, oy);
                }
            }
        }
        return;
    }

    // ---- fused LayerNorm epilogue (N == 256, grid.x == 1) ----
    float2* rowstat = (float2*)smem;
    float sumv[4][2], sqv[4][2];
#pragma unroll
    for (int mt = 0; mt < 4; mt++)
#pragma unroll
        for (int h = 0; h < 2; h++) { sumv[mt][h] = 0.f; sqv[mt][h] = 0.f; }

#pragma unroll
    for (int mt = 0; mt < 4; mt++) {
#pragma unroll
        for (int h = 0; h < 2; h++) {
            int r = row0 + warp_m + mt * 16 + gid + h * 8;
            int rc = r < M ? r : M - 1;
#pragma unroll
            for (int nt = 0; nt < 8; nt++) {
                int cc = warp_n + nt * 8 + 2 * tig;
                float2 b2 = *(const float2*)(bias + cc);
                float2 rd = *(const float2*)(resid + (size_t)rc * H + cc);
                float vx = acc[mt][nt][h * 2 + 0] + b2.x;
                float vy = acc[mt][nt][h * 2 + 1] + b2.y;
                if (mode == 1) { vx = gelu_f(vx); vy = gelu_f(vy); }
                vx += rd.x; vy += rd.y;
                acc[mt][nt][h * 2 + 0] = vx;
                acc[mt][nt][h * 2 + 1] = vy;
                sumv[mt][h] += vx + vy;
                sqv[mt][h] += vx * vx + vy * vy;
            }
        }
    }
#pragma unroll
    for (int mt = 0; mt < 4; mt++)
#pragma unroll
        for (int h = 0; h < 2; h++) {
            sumv[mt][h] += __shfl_xor_sync(0xFFFFFFFFu, sumv[mt][h], 1);
            sumv[mt][h] += __shfl_xor_sync(0xFFFFFFFFu, sumv[mt][h], 2);
            sqv[mt][h]  += __shfl_xor_sync(0xFFFFFFFFu, sqv[mt][h], 1);
            sqv[mt][h]  += __shfl_xor_sync(0xFFFFFFFFu, sqv[mt][h], 2);
        }
    if (tig == 0) {
        int wn = warp_n >> 6;
#pragma unroll
        for (int mt = 0; mt < 4; mt++)
#pragma unroll
            for (int h = 0; h < 2; h++) {
                int rl = warp_m + mt * 16 + gid + h * 8;
                rowstat[rl * 4 + wn] = make_float2(sumv[mt][h], sqv[mt][h]);
            }
    }
    __syncthreads();

    float mean_[4][2], rstd_[4][2];
#pragma unroll
    for (int mt = 0; mt < 4; mt++)
#pragma unroll
        for (int h = 0; h < 2; h++) {
            int rl = warp_m + mt * 16 + gid + h * 8;
            float s = 0.f, q = 0.f;
#pragma unroll
            for (int w = 0; w < 4; w++) {
                float2 t = rowstat[rl * 4 + w];
                s += t.x; q += t.y;
            }
            float mean = s * (1.0f / H);
            float var = q * (1.0f / H) - mean * mean;
            mean_[mt][h] = mean;
            rstd_[mt][h] = rsqrtf(var + 1e-5f);
        }

#pragma unroll
    for (int mt = 0; mt < 4; mt++) {
#pragma unroll
        for (int nt = 0; nt < 8; nt++) {
            int cc = warp_n + nt * 8 + 2 * tig;
            float2 gv = *(const float2*)(gamma + cc);
            float2 bv = *(const float2*)(beta + cc);
#pragma unroll
            for (int h = 0; h < 2; h++) {
                int r = row0 + warp_m + mt * 16 + gid + h * 8;
                if (r >= M) continue;
                float m = mean_[mt][h], rs = rstd_[mt][h];
                float ox = (acc[mt][nt][h * 2 + 0] - m) * rs * gv.x + bv.x;
                float oy = (acc[mt][nt][h * 2 + 1] - m) * rs * gv.y + bv.y;
                *(float2*)(C + (size_t)r * H + cc) = make_float2(ox, oy);
            }
        }
    }
}

// ---------------- weight prep ----------------
__global__ void build_wtcat_kernel(const float* __restrict__ ws, const float* __restrict__ wf,
                                   const float* __restrict__ wk, float* __restrict__ out)
{
    long t = (long)blockIdx.x * blockDim.x + threadIdx.x;
    if (t >= (long)4 * H * 1536) return;
    int lc = (int)(t / (H * 1536));
    int rem = (int)(t % (H * 1536));
    int n = rem / 1536, k = rem % 1536;
    float v;
    if (k < 256) v = ws[(size_t)lc * 65536 + k * 256 + n];
    else if (k < 512) v = wf[(size_t)lc * 65536 + (k - 256) * 256 + n];
    else {
        int hop = (k - 512) >> 8, kk = (k - 512) & 255;
        v = wk[((size_t)(lc * 4 + hop) * 256 + kk) * 256 + n];
    }
    out[t] = to_tf32(v);
}

__global__ void build_wt1_kernel(const float* __restrict__ w1, float* __restrict__ out)
{
    long t = (long)blockIdx.x * blockDim.x + threadIdx.x;
    if (t >= (long)4 * FH * H) return;
    int lc = (int)(t / (FH * H));
    int rem = (int)(t % (FH * H));
    int n = rem / H, k = rem % H;
    out[t] = to_tf32(w1[(size_t)lc * (H * FH) + (size_t)k * FH + n]);
}

__global__ void build_wt2_kernel(const float* __restrict__ w2, float* __restrict__ out)
{
    long t = (long)blockIdx.x * blockDim.x + threadIdx.x;
    if (t >= (long)4 * H * FH) return;
    int lc = (int)(t / (H * FH));
    int rem = (int)(t % (H * FH));
    int n = rem / FH, k = rem % FH;
    out[t] = to_tf32(w2[(size_t)lc * (FH * H) + (size_t)k * H + n]);
}

__global__ void build_bcat_kernel(const float* __restrict__ bs, const float* __restrict__ bf,
                                  const float* __restrict__ bk, float* __restrict__ out)
{
    int t = blockIdx.x * blockDim.x + threadIdx.x;
    if (t >= 4 * H) return;
    int lc = t / H, n = t % H;
    float v = bs[lc * H + n] + bf[lc * H + n];
    for (int i = 0; i < KHOPS; i++) v += bk[(lc * KHOPS + i) * H + n];
    out[t] = v;
}

// ---------------- gathers ----------------
__global__ void gather_sum_kernel(float* __restrict__ out, const float* __restrict__ x,
                                  const int* __restrict__ src, const int* __restrict__ dst,
                                  int m)
{
    long t = (long)blockIdx.x * blockDim.x + threadIdx.x;
    if (t >= (long)m * 64) return;
    int e = (int)(t >> 6);
    int c = (int)(t & 63) << 2;
    float4 a = *(const float4*)(x + (size_t)src[e] * H + c);
    float4 b = *(const float4*)(x + (size_t)dst[e] * H + c);
    *(float4*)(out + (size_t)e * H + c) = make_float4(a.x + b.x, a.y + b.y, a.z + b.z, a.w + b.w);
}

__global__ void gather_embed_kernel(float* __restrict__ out, const float* __restrict__ rel,
                                    const int* __restrict__ feat, int m)
{
    long t = (long)blockIdx.x * blockDim.x + threadIdx.x;
    if (t >= (long)m * 64) return;
    int e = (int)(t >> 6);
    int c = (int)(t & 63) << 2;
    *(float4*)(out + (size_t)e * H + c) = *(const float4*)(rel + (size_t)feat[e] * H + c);
}

// ---------------- host side ----------------
static inline int blocks_for(long threads) { return (int)((threads + 255) / 256); }

struct Scratch {
    float *x0, *x1, *lg0, *lg1, *fn, *fe, *z, *ln1, *ffh;
    float *wtcat, *wt1, *wt2, *bcat;
    int *rp_g, *v_g, *rp_b, *v_b, *rp_l, *v_l, *cnt;
};

static void build_csr(int* cnt, int* rowptr, int* val,
                      const int* keys, const int* payload, int n, int m)
{
    cudaMemsetAsync(cnt, 0, (size_t)n * sizeof(int));
    hist_kernel<<<blocks_for(m), 256>>>(cnt, keys, m);
    scan_kernel<<<1, 1024>>>(cnt, rowptr, n);
    cudaMemcpyAsync(cnt, rowptr, (size_t)n * sizeof(int), cudaMemcpyDeviceToDevice);
    fill_csr_kernel<<<blocks_for(m), 256>>>(cnt, val, keys, payload, m);
}

static void run_core(const Scratch& S,
                     const float* xin, const float* fused, float* xout,
                     int n, const int* rowptr, const int* val,
                     int lc,
                     const float* b_ff1, const float* b_ff2,
                     const float* g1, const float* c1,
                     const float* g2, const float* c2)
{
    const int gy = (n + 127) / 128;
    float* z1 = S.z;
    float* z2 = S.z + (size_t)NEDGES * H;
    float* z3 = S.z + (size_t)2 * NEDGES * H;
    float* z4 = S.z + (size_t)3 * NEDGES * H;

    const int sg = (n + 7) / 8;
    spmm_csr_kernel<<<sg, 256>>>(z1, xin, rowptr, val, n);
    spmm_csr_kernel<<<sg, 256>>>(z2, z1, rowptr, val, n);
    spmm_csr_kernel<<<sg, 256>>>(z3, z2, rowptr, val, n);
    spmm_csr_kernel<<<sg, 256>>>(z4, z3, rowptr, val, n);

    // ln1 = LN( xin + gelu( concat_A @ Wcat + bcat ) )
    {
        SliceArgs sa;
        sa.p[0] = xin;   sa.ld[0] = H;
        sa.p[1] = fused; sa.ld[1] = H;
        sa.p[2] = z1;    sa.ld[2] = H;
        sa.p[3] = z2;    sa.ld[3] = H;
        sa.p[4] = z3;    sa.ld[4] = H;
        sa.p[5] = z4;    sa.ld[5] = H;
        mma_gemm2<<<dim3(1, gy), 256, GEMM_SMEM>>>(
            sa, S.wtcat + (size_t)lc * H * 1536, S.bcat + (size_t)lc * H,
            xin, g1, c1, S.ln1, n, H, 1536, 1);
    }
    // ffh = gelu(ln1 @ w1 + b1)
    {
        SliceArgs sa;
        for (int i = 0; i < 6; i++) { sa.p[i] = S.ln1; sa.ld[i] = H; }
        mma_gemm2<<<dim3(FH / 256, gy), 256, GEMM_SMEM>>>(
            sa, S.wt1 + (size_t)lc * FH * H, b_ff1,
            nullptr, nullptr, nullptr, S.ffh, n, FH, H, 0);
    }
    // xout = LN( ln1 + ffh @ w2 + b2 )
    {
        SliceArgs sa;
        for (int i = 0; i < 4; i++) { sa.p[i] = S.ffh + i * 256; sa.ld[i] = FH; }
        sa.p[4] = S.ffh; sa.ld[4] = FH;
        sa.p[5] = S.ffh; sa.ld[5] = FH;
        mma_gemm2<<<dim3(1, gy), 256, GEMM_SMEM>>>(
            sa, S.wt2 + (size_t)lc * H * FH, b_ff2,
            S.ln1, g2, c2, xout, n, H, FH, 2);
    }
}

extern "C" void kernel_launch(void* const* d_in, const int* in_sizes, int n_in,
                              void* d_out, int out_size)
{
    const float* x_in      = (const float*)d_in[0];
    const int*   edge_feat = (const int*)d_in[1];
    const int*   eig       = (const int*)d_in[2];
    const int*   eil       = (const int*)d_in[3];
    const float* rel       = (const float*)d_in[4];
    const float* w_self    = (const float*)d_in[5];
    const float* b_self    = (const float*)d_in[6];
    const float* w_khop    = (const float*)d_in[7];
    const float* b_khop    = (const float*)d_in[8];
    const float* w_fuse    = (const float*)d_in[9];
    const float* b_fuse    = (const float*)d_in[10];
    const float* w_ff1     = (const float*)d_in[11];
    const float* b_ff1     = (const float*)d_in[12];
    const float* w_ff2     = (const float*)d_in[13];
    const float* b_ff2     = (const float*)d_in[14];
    const float* ln1_g     = (const float*)d_in[15];
    const float* ln1_b     = (const float*)d_in[16];
    const float* ln2_g     = (const float*)d_in[17];
    const float* ln2_b     = (const float*)d_in[18];

    const int* src_g = eig;
    const int* dst_g = eig + NEDGES;
    const int* src_l = eil;
    const int* dst_l = eil + NLGE;

    cudaFuncSetAttribute(mma_gemm2, cudaFuncAttributeMaxDynamicSharedMemorySize, GEMM_SMEM);

    Scratch S;
    void* p;
    cudaGetSymbolAddress(&p, g_x0);       S.x0    = (float*)p;
    cudaGetSymbolAddress(&p, g_x1);       S.x1    = (float*)p;
    cudaGetSymbolAddress(&p, g_lg0);      S.lg0   = (float*)p;
    cudaGetSymbolAddress(&p, g_lg1);      S.lg1   = (float*)p;
    cudaGetSymbolAddress(&p, g_fn);       S.fn    = (float*)p;
    cudaGetSymbolAddress(&p, g_fe);       S.fe    = (float*)p;
    cudaGetSymbolAddress(&p, g_z);        S.z     = (float*)p;
    cudaGetSymbolAddress(&p, g_ln1);      S.ln1   = (float*)p;
    cudaGetSymbolAddress(&p, g_ffh);      S.ffh   = (float*)p;
    cudaGetSymbolAddress(&p, g_wtcat);    S.wtcat = (float*)p;
    cudaGetSymbolAddress(&p, g_wt1);      S.wt1   = (float*)p;
    cudaGetSymbolAddress(&p, g_wt2);      S.wt2   = (float*)p;
    cudaGetSymbolAddress(&p, g_bcat);     S.bcat  = (float*)p;
    cudaGetSymbolAddress(&p, g_rowptr_g); S.rp_g  = (int*)p;
    cudaGetSymbolAddress(&p, g_val_g);    S.v_g   = (int*)p;
    cudaGetSymbolAddress(&p, g_rowptr_b); S.rp_b  = (int*)p;
    cudaGetSymbolAddress(&p, g_val_b);    S.v_b   = (int*)p;
    cudaGetSymbolAddress(&p, g_rowptr_l); S.rp_l  = (int*)p;
    cudaGetSymbolAddress(&p, g_val_l);    S.v_l   = (int*)p;
    cudaGetSymbolAddress(&p, g_cnt);      S.cnt   = (int*)p;

    // ---- CSR builds (once per replay; graphs are fixed inputs) ----
    build_csr(S.cnt, S.rp_g, S.v_g, dst_g, src_g, NNODES, NEDGES);
    build_csr(S.cnt, S.rp_l, S.v_l, dst_l, src_l, NEDGES, NLGE);
    // b: node <- incident edges (both endpoints)
    cudaMemsetAsync(S.cnt, 0, (size_t)NNODES * sizeof(int));
    hist2_kernel<<<blocks_for(NEDGES), 256>>>(S.cnt, src_g, dst_g, NEDGES);
    scan_kernel<<<1, 1024>>>(S.cnt, S.rp_b, NNODES);
    cudaMemcpyAsync(S.cnt, S.rp_b, (size_t)NNODES * sizeof(int), cudaMemcpyDeviceToDevice);
    fill_csr2_kernel<<<blocks_for(NEDGES), 256>>>(S.cnt, S.v_b, src_g, dst_g, NEDGES);

    // ---- weight prep (tf32-rounded) ----
    build_wtcat_kernel<<<blocks_for((long)4 * H * 1536), 256>>>(w_self, w_fuse, w_khop, S.wtcat);
    build_wt1_kernel<<<blocks_for((long)4 * FH * H), 256>>>(w_ff1, S.wt1);
    build_wt2_kernel<<<blocks_for((long)4 * H * FH), 256>>>(w_ff2, S.wt2);
    build_bcat_kernel<<<blocks_for(4 * H), 256>>>(b_self, b_fuse, b_khop, S.bcat);

    float* xb[2]  = {S.x0, S.x1};
    float* lgb[2] = {S.lg0, S.lg1};

    cudaMemcpyAsync(S.x0, x_in, (size_t)NNODES * H * sizeof(float), cudaMemcpyDeviceToDevice);
    gather_embed_kernel<<<blocks_for((long)NEDGES * 64), 256>>>(S.lg0, rel, edge_feat, NEDGES);

    int cur = 0;
    for (int l = 0; l < LNUM; l++) {
        const float* x  = xb[cur];
        const float* lg = lgb[cur];
        float* xn  = xb[1 - cur];
        float* lgn = lgb[1 - cur];

        // fused_nodes via CSR_b gather-sum; fused_edges via plain gather
        spmm_csr_kernel<<<(NNODES + 7) / 8, 256>>>(S.fn, lg, S.rp_b, S.v_b, NNODES);
        gather_sum_kernel<<<blocks_for((long)NEDGES * 64), 256>>>(S.fe, x, src_g, dst_g, NEDGES);

        {
            int lc = l * 2 + 0;
            run_core(S, x, S.fn, xn, NNODES, S.rp_g, S.v_g, lc,
                     b_ff1 + (size_t)lc * FH, b_ff2 + (size_t)lc * H,
                     ln1_g + (size_t)lc * H, ln1_b + (size_t)lc * H,
                     ln2_g + (size_t)lc * H, ln2_b + (size_t)lc * H);
        }
        {
            int lc = l * 2 + 1;
            run_core(S, lg, S.fe, lgn, NEDGES, S.rp_l, S.v_l, lc,
                     b_ff1 + (size_t)lc * FH, b_ff2 + (size_t)lc * H,
                     ln1_g + (size_t)lc * H, ln1_b + (size_t)lc * H,
                     ln2_g + (size_t)lc * H, ln2_b + (size_t)lc * H);
        }
        cur = 1 - cur;
    }

    cudaMemcpyAsync(d_out, xb[cur], (size_t)NNODES * H * sizeof(float),
                    cudaMemcpyDeviceToDevice);
    cudaMemcpyAsync((float*)d_out + (size_t)NNODES * H, lgb[cur],
                    (size_t)NEDGES * H * sizeof(float), cudaMemcpyDeviceToDevice);
}

// round 10
// speedup vs baseline: 3.5672x; 1.1268x over previous
#include <cuda_runtime.h>
#include <math.h>
#include <stdint.h>

#define H 256
#define FH 1024
#define LNUM 2
#define KHOPS 4
#define NNODES 20000
#define NEDGES 160000
#define NLGE 640000

// ---------------- scratch (device globals; no allocations) ----------------
__device__ __align__(256) float g_x0[(size_t)NNODES * H];
__device__ __align__(256) float g_x1[(size_t)NNODES * H];
__device__ __align__(256) float g_lg0[(size_t)NEDGES * H];
__device__ __align__(256) float g_lg1[(size_t)NEDGES * H];
__device__ __align__(256) float g_fn[(size_t)NNODES * H];
__device__ __align__(256) float g_fe[(size_t)NEDGES * H];
__device__ __align__(256) float g_z[(size_t)4 * NEDGES * H];     // edge-core hop buffers
__device__ __align__(256) float g_ln1[(size_t)NEDGES * H];
__device__ __align__(256) float g_ffh[(size_t)NEDGES * FH];
__device__ __align__(256) float g_zn[(size_t)4 * NNODES * H];    // node-core hop buffers
__device__ __align__(256) float g_ln1n[(size_t)NNODES * H];
__device__ __align__(256) float g_ffhn[(size_t)NNODES * FH];
// pre-transposed (and tf32-rounded) weights, [lc][N][K] K-major
__device__ __align__(256) float g_wtcat[(size_t)4 * H * (6 * H)];
__device__ __align__(256) float g_wt1[(size_t)4 * FH * H];
__device__ __align__(256) float g_wt2[(size_t)4 * H * FH];
__device__ __align__(256) float g_bcat[(size_t)4 * H];
// CSR structures
__device__ int g_rowptr_g[NNODES + 1];
__device__ int g_val_g[NEDGES];
__device__ int g_rowptr_b[NNODES + 1];
__device__ int g_val_b[2 * NEDGES];
__device__ int g_rowptr_l[NEDGES + 1];
__device__ int g_val_l[NLGE];
__device__ int g_cnt[NEDGES + 1];
__device__ int g_cnt2[NNODES + 1];
__device__ int g_bsum[1024];
__device__ int g_bsum2[1024];

// ---------------- device helpers ----------------
__device__ __forceinline__ float to_tf32(float x) {
    float y;
    asm("cvt.rna.tf32.f32 %0, %1;" : "=f"(y) : "f"(x));
    return y;
}
__device__ __forceinline__ float gelu_f(float v) {
    return 0.5f * v * (1.0f + erff(v * 0.70710678118654752f));
}
__device__ __forceinline__ void cp_async16(uint32_t saddr, const void* gptr) {
    asm volatile("cp.async.cg.shared.global [%0], [%1], 16;" :: "r"(saddr), "l"(gptr));
}
#define CP_COMMIT() asm volatile("cp.async.commit_group;")
#define CP_WAIT0()  asm volatile("cp.async.wait_group 0;")

// ---------------- CSR build ----------------
__global__ void hist_kernel(int* __restrict__ cnt, const int* __restrict__ keys, int m)
{
    int t = blockIdx.x * blockDim.x + threadIdx.x;
    if (t < m) atomicAdd(&cnt[keys[t]], 1);
}
__global__ void hist2_kernel(int* __restrict__ cnt, const int* __restrict__ k1,
                             const int* __restrict__ k2, int m)
{
    int t = blockIdx.x * blockDim.x + threadIdx.x;
    if (t < m) { atomicAdd(&cnt[k1[t]], 1); atomicAdd(&cnt[k2[t]], 1); }
}

// ---- multi-block exclusive scan (3 phases) ----
__global__ __launch_bounds__(1024)
void scan_part_kernel(const int* __restrict__ in, int* __restrict__ out,
                      int* __restrict__ bsum, int n)
{
    __shared__ int warpsums[32];
    const int tid = threadIdx.x, lane = tid & 31, w = tid >> 5;
    const int i = blockIdx.x * 1024 + tid;
    int v = (i < n) ? in[i] : 0;
    int s = v;
#pragma unroll
    for (int o = 1; o < 32; o <<= 1) {
        int t = __shfl_up_sync(0xFFFFFFFFu, s, o);
        if (lane >= o) s += t;
    }
    if (lane == 31) warpsums[w] = s;
    __syncthreads();
    if (w == 0) {
        int ws = warpsums[lane];
#pragma unroll
        for (int o = 1; o < 32; o <<= 1) {
            int t = __shfl_up_sync(0xFFFFFFFFu, ws, o);
            if (lane >= o) ws += t;
        }
        warpsums[lane] = ws;
    }
    __syncthreads();
    int excl = s - v + (w > 0 ? warpsums[w - 1] : 0);
    if (i < n) out[i] = excl;
    if (tid == 1023) bsum[blockIdx.x] = excl + v;
}

__global__ __launch_bounds__(1024)
void scan_bsum_kernel(int* __restrict__ bsum, int nb)
{
    __shared__ int warpsums[32];
    const int tid = threadIdx.x, lane = tid & 31, w = tid >> 5;
    int v = (tid < nb) ? bsum[tid] : 0;
    int s = v;
#pragma unroll
    for (int o = 1; o < 32; o <<= 1) {
        int t = __shfl_up_sync(0xFFFFFFFFu, s, o);
        if (lane >= o) s += t;
    }
    if (lane == 31) warpsums[w] = s;
    __syncthreads();
    if (w == 0) {
        int ws = warpsums[lane];
#pragma unroll
        for (int o = 1; o < 32; o <<= 1) {
            int t = __shfl_up_sync(0xFFFFFFFFu, ws, o);
            if (lane >= o) ws += t;
        }
        warpsums[lane] = ws;
    }
    __syncthreads();
    int excl = s - v + (w > 0 ? warpsums[w - 1] : 0);
    if (tid < nb) bsum[tid] = excl;
}

__global__ __launch_bounds__(1024)
void scan_add_kernel(const int* __restrict__ in, int* __restrict__ out,
                     const int* __restrict__ bsum, int n)
{
    const int i = blockIdx.x * 1024 + threadIdx.x;
    if (i < n) {
        int o = out[i] + bsum[blockIdx.x];
        out[i] = o;
        if (i == n - 1) out[n] = o + in[i];
    }
}

__global__ void fill_csr_kernel(int* __restrict__ cursor, int* __restrict__ val,
                                const int* __restrict__ keys, const int* __restrict__ payload,
                                int m)
{
    int t = blockIdx.x * blockDim.x + threadIdx.x;
    if (t >= m) return;
    int pos = atomicAdd(&cursor[keys[t]], 1);
    val[pos] = payload[t];
}
__global__ void fill_csr2_kernel(int* __restrict__ cursor, int* __restrict__ val,
                                 const int* __restrict__ k1, const int* __restrict__ k2, int m)
{
    int t = blockIdx.x * blockDim.x + threadIdx.x;
    if (t >= m) return;
    int p1 = atomicAdd(&cursor[k1[t]], 1);
    val[p1] = t;
    int p2 = atomicAdd(&cursor[k2[t]], 1);
    val[p2] = t;
}

// ---------------- CSR SpMM: out[row] = sum_j in[val[j]] ----------------
__global__ __launch_bounds__(256)
void spmm_csr_kernel(float* __restrict__ out, const float* __restrict__ in,
                     const int* __restrict__ rowptr, const int* __restrict__ val, int n)
{
    int row = blockIdx.x * 8 + (threadIdx.x >> 5);
    if (row >= n) return;
    int lane = threadIdx.x & 31;
    int beg = rowptr[row], end = rowptr[row + 1];
    float4 a0 = make_float4(0.f, 0.f, 0.f, 0.f), a1 = a0;
    for (int j = beg; j < end; j++) {
        const float* p = in + (size_t)val[j] * H + lane * 8;
        float4 v0 = *(const float4*)p;
        float4 v1 = *(const float4*)(p + 4);
        a0.x += v0.x; a0.y += v0.y; a0.z += v0.z; a0.w += v0.w;
        a1.x += v1.x; a1.y += v1.y; a1.z += v1.z; a1.w += v1.w;
    }
    float* o = out + (size_t)row * H + lane * 8;
    *(float4*)o = a0;
    *(float4*)(o + 4) = a1;
}

// ---------------- tf32 mma.sync GEMM with segmented A + fused epilogues ----------------
#define BK 32
#define ASTR 36
#define ABUF_A (128 * ASTR)
#define ABUF_B (256 * ASTR)
#define GEMM_SMEM ((2 * ABUF_A + 2 * ABUF_B) * 4)

struct SliceArgs {
    const float* p[6];
    int ld[6];
};

__device__ __forceinline__ void mma_tf32(float* c, const uint32_t* a, const uint32_t* b) {
    asm volatile(
        "mma.sync.aligned.m16n8k8.row.col.f32.tf32.tf32.f32 "
        "{%0,%1,%2,%3}, {%4,%5,%6,%7}, {%8,%9}, {%0,%1,%2,%3};"
        : "+f"(c[0]), "+f"(c[1]), "+f"(c[2]), "+f"(c[3])
        : "r"(a[0]), "r"(a[1]), "r"(a[2]), "r"(a[3]), "r"(b[0]), "r"(b[1]));
}

__global__ __launch_bounds__(256)
void mma_gemm2(SliceArgs sa,
               const float* __restrict__ Bt,
               const float* __restrict__ bias,
               const float* __restrict__ resid,
               const float* __restrict__ gamma,
               const float* __restrict__ beta,
               float* __restrict__ C,
               int M, int N, int K, int mode)
{
    extern __shared__ float smem[];
    float* AsBase = smem;
    float* BsBase = smem + 2 * ABUF_A;

    const int tid = threadIdx.x;
    const int wid = tid >> 5, lane = tid & 31;
    const int gid = lane >> 2, tig = lane & 3;
    const int warp_m = (wid & 1) * 64;
    const int warp_n = (wid >> 1) * 64;
    const int row0 = blockIdx.y * 128;
    const int col0 = blockIdx.x * 256;

    float acc[4][8][4];
#pragma unroll
    for (int mt = 0; mt < 4; mt++)
#pragma unroll
        for (int nt = 0; nt < 8; nt++)
#pragma unroll
            for (int j = 0; j < 4; j++) acc[mt][nt][j] = 0.f;

    const int nc = K / BK;
    float4 ra[4];

#pragma unroll
    for (int f = 0; f < 8; f++) {
        int i = f * 256 + tid, r = i >> 3, c4 = i & 7;
        uint32_t dst = (uint32_t)__cvta_generic_to_shared(BsBase + r * ASTR + c4 * 4);
        cp_async16(dst, Bt + (size_t)(col0 + r) * K + c4 * 4);
    }
    CP_COMMIT();
    {
        const float* Ap = sa.p[0];
        const int ldA = sa.ld[0];
#pragma unroll
        for (int f = 0; f < 4; f++) {
            int i = f * 256 + tid, r = i >> 3, c4 = i & 7;
            int gr = row0 + r; if (gr >= M) gr = M - 1;
            ra[f] = *(const float4*)(Ap + (size_t)gr * ldA + c4 * 4);
        }
    }
#pragma unroll
    for (int f = 0; f < 4; f++) {
        int i = f * 256 + tid, r = i >> 3, c4 = i & 7;
        float4 v = ra[f];
        v.x = to_tf32(v.x); v.y = to_tf32(v.y); v.z = to_tf32(v.z); v.w = to_tf32(v.w);
        *(float4*)(AsBase + r * ASTR + c4 * 4) = v;
    }
    CP_WAIT0();
    __syncthreads();

    for (int c = 0; c < nc; c++) {
        const int nxt = c + 1;
        if (nxt < nc) {
            const int k0 = nxt * BK;
            float* Bs = BsBase + (nxt & 1) * ABUF_B;
#pragma unroll
            for (int f = 0; f < 8; f++) {
                int i = f * 256 + tid, r = i >> 3, c4 = i & 7;
                uint32_t dst = (uint32_t)__cvta_generic_to_shared(Bs + r * ASTR + c4 * 4);
                cp_async16(dst, Bt + (size_t)(col0 + r) * K + k0 + c4 * 4);
            }
            CP_COMMIT();
            const int sl = k0 >> 8;
            const int off = k0 & 255;
            const float* Ap = sa.p[sl];
            const int ldA = sa.ld[sl];
#pragma unroll
            for (int f = 0; f < 4; f++) {
                int i = f * 256 + tid, r = i >> 3, c4 = i & 7;
                int gr = row0 + r; if (gr >= M) gr = M - 1;
                ra[f] = *(const float4*)(Ap + (size_t)gr * ldA + off + c4 * 4);
            }
        }

        const uint32_t* Asu = (const uint32_t*)(AsBase + (c & 1) * ABUF_A);
        const uint32_t* Bsu = (const uint32_t*)(BsBase + (c & 1) * ABUF_B);
#pragma unroll
        for (int ks = 0; ks < 4; ks++) {
            const int k0c = ks * 8;
            uint32_t afr[4][4], bfr[8][2];
#pragma unroll
            for (int mt = 0; mt < 4; mt++) {
                int r = warp_m + mt * 16 + gid;
                afr[mt][0] = Asu[r * ASTR + k0c + tig];
                afr[mt][1] = Asu[(r + 8) * ASTR + k0c + tig];
                afr[mt][2] = Asu[r * ASTR + k0c + tig + 4];
                afr[mt][3] = Asu[(r + 8) * ASTR + k0c + tig + 4];
            }
#pragma unroll
            for (int nt = 0; nt < 8; nt++) {
                int cc = warp_n + nt * 8 + gid;
                bfr[nt][0] = Bsu[cc * ASTR + k0c + tig];
                bfr[nt][1] = Bsu[cc * ASTR + k0c + tig + 4];
            }
#pragma unroll
            for (int mt = 0; mt < 4; mt++)
#pragma unroll
                for (int nt = 0; nt < 8; nt++)
                    mma_tf32(acc[mt][nt], afr[mt], bfr[nt]);
        }

        if (nxt < nc) {
            float* As = AsBase + (nxt & 1) * ABUF_A;
#pragma unroll
            for (int f = 0; f < 4; f++) {
                int i = f * 256 + tid, r = i >> 3, c4 = i & 7;
                float4 v = ra[f];
                v.x = to_tf32(v.x); v.y = to_tf32(v.y); v.z = to_tf32(v.z); v.w = to_tf32(v.w);
                *(float4*)(As + r * ASTR + c4 * 4) = v;
            }
            CP_WAIT0();
        }
        __syncthreads();
    }

    if (mode == 0) {
#pragma unroll
        for (int mt = 0; mt < 4; mt++) {
#pragma unroll
            for (int nt = 0; nt < 8; nt++) {
                int cc = col0 + warp_n + nt * 8 + 2 * tig;
                float bx = bias[cc], by = bias[cc + 1];
#pragma unroll
                for (int h = 0; h < 2; h++) {
                    int r = row0 + warp_m + mt * 16 + gid + h * 8;
                    if (r >= M) continue;
                    float ox = gelu_f(acc[mt][nt][h * 2 + 0] + bx);
                    float oy = gelu_f(acc[mt][nt][h * 2 + 1] + by);
                    *(float2*)(C + (size_t)r * N + cc) = make_float2(ox, oy);
                }
            }
        }
        return;
    }

    // ---- fused LayerNorm epilogue (N == 256, grid.x == 1) ----
    float2* rowstat = (float2*)smem;
    float sumv[4][2], sqv[4][2];
#pragma unroll
    for (int mt = 0; mt < 4; mt++)
#pragma unroll
        for (int h = 0; h < 2; h++) { sumv[mt][h] = 0.f; sqv[mt][h] = 0.f; }

#pragma unroll
    for (int mt = 0; mt < 4; mt++) {
#pragma unroll
        for (int h = 0; h < 2; h++) {
            int r = row0 + warp_m + mt * 16 + gid + h * 8;
            int rc = r < M ? r : M - 1;
#pragma unroll
            for (int nt = 0; nt < 8; nt++) {
                int cc = warp_n + nt * 8 + 2 * tig;
                float2 b2 = *(const float2*)(bias + cc);
                float2 rd = *(const float2*)(resid + (size_t)rc * H + cc);
                float vx = acc[mt][nt][h * 2 + 0] + b2.x;
                float vy = acc[mt][nt][h * 2 + 1] + b2.y;
                if (mode == 1) { vx = gelu_f(vx); vy = gelu_f(vy); }
                vx += rd.x; vy += rd.y;
                acc[mt][nt][h * 2 + 0] = vx;
                acc[mt][nt][h * 2 + 1] = vy;
                sumv[mt][h] += vx + vy;
                sqv[mt][h] += vx * vx + vy * vy;
            }
        }
    }
#pragma unroll
    for (int mt = 0; mt < 4; mt++)
#pragma unroll
        for (int h = 0; h < 2; h++) {
            sumv[mt][h] += __shfl_xor_sync(0xFFFFFFFFu, sumv[mt][h], 1);
            sumv[mt][h] += __shfl_xor_sync(0xFFFFFFFFu, sumv[mt][h], 2);
            sqv[mt][h]  += __shfl_xor_sync(0xFFFFFFFFu, sqv[mt][h], 1);
            sqv[mt][h]  += __shfl_xor_sync(0xFFFFFFFFu, sqv[mt][h], 2);
        }
    if (tig == 0) {
        int wn = warp_n >> 6;
#pragma unroll
        for (int mt = 0; mt < 4; mt++)
#pragma unroll
            for (int h = 0; h < 2; h++) {
                int rl = warp_m + mt * 16 + gid + h * 8;
                rowstat[rl * 4 + wn] = make_float2(sumv[mt][h], sqv[mt][h]);
            }
    }
    __syncthreads();

    float mean_[4][2], rstd_[4][2];
#pragma unroll
    for (int mt = 0; mt < 4; mt++)
#pragma unroll
        for (int h = 0; h < 2; h++) {
            int rl = warp_m + mt * 16 + gid + h * 8;
            float s = 0.f, q = 0.f;
#pragma unroll
            for (int w = 0; w < 4; w++) {
                float2 t = rowstat[rl * 4 + w];
                s += t.x; q += t.y;
            }
            float mean = s * (1.0f / H);
            float var = q * (1.0f / H) - mean * mean;
            mean_[mt][h] = mean;
            rstd_[mt][h] = rsqrtf(var + 1e-5f);
        }

#pragma unroll
    for (int mt = 0; mt < 4; mt++) {
#pragma unroll
        for (int nt = 0; nt < 8; nt++) {
            int cc = warp_n + nt * 8 + 2 * tig;
            float2 gv = *(const float2*)(gamma + cc);
            float2 bv = *(const float2*)(beta + cc);
#pragma unroll
            for (int h = 0; h < 2; h++) {
                int r = row0 + warp_m + mt * 16 + gid + h * 8;
                if (r >= M) continue;
                float m = mean_[mt][h], rs = rstd_[mt][h];
                float ox = (acc[mt][nt][h * 2 + 0] - m) * rs * gv.x + bv.x;
                float oy = (acc[mt][nt][h * 2 + 1] - m) * rs * gv.y + bv.y;
                *(float2*)(C + (size_t)r * H + cc) = make_float2(ox, oy);
            }
        }
    }
}

// ---------------- weight prep ----------------
__global__ void build_wtcat_kernel(const float* __restrict__ ws, const float* __restrict__ wf,
                                   const float* __restrict__ wk, float* __restrict__ out)
{
    long t = (long)blockIdx.x * blockDim.x + threadIdx.x;
    if (t >= (long)4 * H * 1536) return;
    int lc = (int)(t / (H * 1536));
    int rem = (int)(t % (H * 1536));
    int n = rem / 1536, k = rem % 1536;
    float v;
    if (k < 256) v = ws[(size_t)lc * 65536 + k * 256 + n];
    else if (k < 512) v = wf[(size_t)lc * 65536 + (k - 256) * 256 + n];
    else {
        int hop = (k - 512) >> 8, kk = (k - 512) & 255;
        v = wk[((size_t)(lc * 4 + hop) * 256 + kk) * 256 + n];
    }
    out[t] = to_tf32(v);
}

__global__ void build_wt1_kernel(const float* __restrict__ w1, float* __restrict__ out)
{
    long t = (long)blockIdx.x * blockDim.x + threadIdx.x;
    if (t >= (long)4 * FH * H) return;
    int lc = (int)(t / (FH * H));
    int rem = (int)(t % (FH * H));
    int n = rem / H, k = rem % H;
    out[t] = to_tf32(w1[(size_t)lc * (H * FH) + (size_t)k * FH + n]);
}

__global__ void build_wt2_kernel(const float* __restrict__ w2, float* __restrict__ out)
{
    long t = (long)blockIdx.x * blockDim.x + threadIdx.x;
    if (t >= (long)4 * H * FH) return;
    int lc = (int)(t / (H * FH));
    int rem = (int)(t % (H * FH));
    int n = rem / FH, k = rem % FH;
    out[t] = to_tf32(w2[(size_t)lc * (FH * H) + (size_t)k * H + n]);
}

__global__ void build_bcat_kernel(const float* __restrict__ bs, const float* __restrict__ bf,
                                  const float* __restrict__ bk, float* __restrict__ out)
{
    int t = blockIdx.x * blockDim.x + threadIdx.x;
    if (t >= 4 * H) return;
    int lc = t / H, n = t % H;
    float v = bs[lc * H + n] + bf[lc * H + n];
    for (int i = 0; i < KHOPS; i++) v += bk[(lc * KHOPS + i) * H + n];
    out[t] = v;
}

// ---------------- gathers ----------------
__global__ void gather_sum_kernel(float* __restrict__ out, const float* __restrict__ x,
                                  const int* __restrict__ src, const int* __restrict__ dst,
                                  int m)
{
    long t = (long)blockIdx.x * blockDim.x + threadIdx.x;
    if (t >= (long)m * 64) return;
    int e = (int)(t >> 6);
    int c = (int)(t & 63) << 2;
    float4 a = *(const float4*)(x + (size_t)src[e] * H + c);
    float4 b = *(const float4*)(x + (size_t)dst[e] * H + c);
    *(float4*)(out + (size_t)e * H + c) = make_float4(a.x + b.x, a.y + b.y, a.z + b.z, a.w + b.w);
}

__global__ void gather_embed_kernel(float* __restrict__ out, const float* __restrict__ rel,
                                    const int* __restrict__ feat, int m)
{
    long t = (long)blockIdx.x * blockDim.x + threadIdx.x;
    if (t >= (long)m * 64) return;
    int e = (int)(t >> 6);
    int c = (int)(t & 63) << 2;
    *(float4*)(out + (size_t)e * H + c) = *(const float4*)(rel + (size_t)feat[e] * H + c);
}

// ---------------- host side ----------------
static inline int blocks_for(long threads) { return (int)((threads + 255) / 256); }

struct Scratch {
    float *x0, *x1, *lg0, *lg1, *fn, *fe;
    float *z, *ln1, *ffh;          // edge-core scratch
    float *zn, *ln1n, *ffhn;       // node-core scratch
    float *wtcat, *wt1, *wt2, *bcat;
    int *rp_g, *v_g, *rp_b, *v_b, *rp_l, *v_l, *cnt, *cnt2, *bsum, *bsum2;
};

// Streams/events created once per process (first call = correctness run, so the
// driver's stream-pool allocation is inside the harness's pre-capture baseline
// and NOTHING is allocated during capture/replay). Same captured work each call.
struct StreamCtx {
    cudaStream_t s1, s2;
    cudaEvent_t evF, evA, evB, evT[2], evN[2];
    StreamCtx() {
        cudaStreamCreateWithFlags(&s1, cudaStreamNonBlocking);
        cudaStreamCreateWithFlags(&s2, cudaStreamNonBlocking);
        cudaEventCreateWithFlags(&evF, cudaEventDisableTiming);
        cudaEventCreateWithFlags(&evA, cudaEventDisableTiming);
        cudaEventCreateWithFlags(&evB, cudaEventDisableTiming);
        for (int i = 0; i < 2; i++) {
            cudaEventCreateWithFlags(&evT[i], cudaEventDisableTiming);
            cudaEventCreateWithFlags(&evN[i], cudaEventDisableTiming);
        }
    }
};
static StreamCtx& ctx() { static StreamCtx c; return c; }

static void scan_excl(const int* in, int* out, int* bsum, int n, cudaStream_t st)
{
    int nb = (n + 1023) / 1024;
    scan_part_kernel<<<nb, 1024, 0, st>>>(in, out, bsum, n);
    scan_bsum_kernel<<<1, 1024, 0, st>>>(bsum, nb);
    scan_add_kernel<<<nb, 1024, 0, st>>>(in, out, bsum, n);
}

static void build_csr(int* cnt, int* bsum, int* rowptr, int* val,
                      const int* keys, const int* payload, int n, int m, cudaStream_t st)
{
    cudaMemsetAsync(cnt, 0, (size_t)n * sizeof(int), st);
    hist_kernel<<<blocks_for(m), 256, 0, st>>>(cnt, keys, m);
    scan_excl(cnt, rowptr, bsum, n, st);
    cudaMemcpyAsync(cnt, rowptr, (size_t)n * sizeof(int), cudaMemcpyDeviceToDevice, st);
    fill_csr_kernel<<<blocks_for(m), 256, 0, st>>>(cnt, val, keys, payload, m);
}

static void run_core(const Scratch& S,
                     const float* xin, const float* fused, float* xout,
                     int n, const int* rowptr, const int* val,
                     float* zbuf, size_t zstride, float* ln1buf, float* ffhbuf,
                     int lc,
                     const float* b_ff1, const float* b_ff2,
                     const float* g1, const float* c1,
                     const float* g2, const float* c2,
                     cudaStream_t st)
{
    const int gy = (n + 127) / 128;
    float* z1 = zbuf;
    float* z2 = zbuf + zstride;
    float* z3 = zbuf + 2 * zstride;
    float* z4 = zbuf + 3 * zstride;

    const int sg = (n + 7) / 8;
    spmm_csr_kernel<<<sg, 256, 0, st>>>(z1, xin, rowptr, val, n);
    spmm_csr_kernel<<<sg, 256, 0, st>>>(z2, z1, rowptr, val, n);
    spmm_csr_kernel<<<sg, 256, 0, st>>>(z3, z2, rowptr, val, n);
    spmm_csr_kernel<<<sg, 256, 0, st>>>(z4, z3, rowptr, val, n);

    // ln1 = LN( xin + gelu( concat_A @ Wcat + bcat ) )
    {
        SliceArgs sa;
        sa.p[0] = xin;   sa.ld[0] = H;
        sa.p[1] = fused; sa.ld[1] = H;
        sa.p[2] = z1;    sa.ld[2] = H;
        sa.p[3] = z2;    sa.ld[3] = H;
        sa.p[4] = z3;    sa.ld[4] = H;
        sa.p[5] = z4;    sa.ld[5] = H;
        mma_gemm2<<<dim3(1, gy), 256, GEMM_SMEM, st>>>(
            sa, S.wtcat + (size_t)lc * H * 1536, S.bcat + (size_t)lc * H,
            xin, g1, c1, ln1buf, n, H, 1536, 1);
    }
    // ffh = gelu(ln1 @ w1 + b1)
    {
        SliceArgs sa;
        for (int i = 0; i < 6; i++) { sa.p[i] = ln1buf; sa.ld[i] = H; }
        mma_gemm2<<<dim3(FH / 256, gy), 256, GEMM_SMEM, st>>>(
            sa, S.wt1 + (size_t)lc * FH * H, b_ff1,
            nullptr, nullptr, nullptr, ffhbuf, n, FH, H, 0);
    }
    // xout = LN( ln1 + ffh @ w2 + b2 )
    {
        SliceArgs sa;
        for (int i = 0; i < 4; i++) { sa.p[i] = ffhbuf + i * 256; sa.ld[i] = FH; }
        sa.p[4] = ffhbuf; sa.ld[4] = FH;
        sa.p[5] = ffhbuf; sa.ld[5] = FH;
        mma_gemm2<<<dim3(1, gy), 256, GEMM_SMEM, st>>>(
            sa, S.wt2 + (size_t)lc * H * FH, b_ff2,
            ln1buf, g2, c2, xout, n, H, FH, 2);
    }
}

extern "C" void kernel_launch(void* const* d_in, const int* in_sizes, int n_in,
                              void* d_out, int out_size)
{
    const float* x_in      = (const float*)d_in[0];
    const int*   edge_feat = (const int*)d_in[1];
    const int*   eig       = (const int*)d_in[2];
    const int*   eil       = (const int*)d_in[3];
    const float* rel       = (const float*)d_in[4];
    const float* w_self    = (const float*)d_in[5];
    const float* b_self    = (const float*)d_in[6];
    const float* w_khop    = (const float*)d_in[7];
    const float* b_khop    = (const float*)d_in[8];
    const float* w_fuse    = (const float*)d_in[9];
    const float* b_fuse    = (const float*)d_in[10];
    const float* w_ff1     = (const float*)d_in[11];
    const float* b_ff1     = (const float*)d_in[12];
    const float* w_ff2     = (const float*)d_in[13];
    const float* b_ff2     = (const float*)d_in[14];
    const float* ln1_g     = (const float*)d_in[15];
    const float* ln1_b     = (const float*)d_in[16];
    const float* ln2_g     = (const float*)d_in[17];
    const float* ln2_b     = (const float*)d_in[18];

    const int* src_g = eig;
    const int* dst_g = eig + NEDGES;
    const int* src_l = eil;
    const int* dst_l = eil + NLGE;

    cudaFuncSetAttribute(mma_gemm2, cudaFuncAttributeMaxDynamicSharedMemorySize, GEMM_SMEM);

    Scratch S;
    void* p;
    cudaGetSymbolAddress(&p, g_x0);       S.x0    = (float*)p;
    cudaGetSymbolAddress(&p, g_x1);       S.x1    = (float*)p;
    cudaGetSymbolAddress(&p, g_lg0);      S.lg0   = (float*)p;
    cudaGetSymbolAddress(&p, g_lg1);      S.lg1   = (float*)p;
    cudaGetSymbolAddress(&p, g_fn);       S.fn    = (float*)p;
    cudaGetSymbolAddress(&p, g_fe);       S.fe    = (float*)p;
    cudaGetSymbolAddress(&p, g_z);        S.z     = (float*)p;
    cudaGetSymbolAddress(&p, g_ln1);      S.ln1   = (float*)p;
    cudaGetSymbolAddress(&p, g_ffh);      S.ffh   = (float*)p;
    cudaGetSymbolAddress(&p, g_zn);       S.zn    = (float*)p;
    cudaGetSymbolAddress(&p, g_ln1n);     S.ln1n  = (float*)p;
    cudaGetSymbolAddress(&p, g_ffhn);     S.ffhn  = (float*)p;
    cudaGetSymbolAddress(&p, g_wtcat);    S.wtcat = (float*)p;
    cudaGetSymbolAddress(&p, g_wt1);      S.wt1   = (float*)p;
    cudaGetSymbolAddress(&p, g_wt2);      S.wt2   = (float*)p;
    cudaGetSymbolAddress(&p, g_bcat);     S.bcat  = (float*)p;
    cudaGetSymbolAddress(&p, g_rowptr_g); S.rp_g  = (int*)p;
    cudaGetSymbolAddress(&p, g_val_g);    S.v_g   = (int*)p;
    cudaGetSymbolAddress(&p, g_rowptr_b); S.rp_b  = (int*)p;
    cudaGetSymbolAddress(&p, g_val_b);    S.v_b   = (int*)p;
    cudaGetSymbolAddress(&p, g_rowptr_l); S.rp_l  = (int*)p;
    cudaGetSymbolAddress(&p, g_val_l);    S.v_l   = (int*)p;
    cudaGetSymbolAddress(&p, g_cnt);      S.cnt   = (int*)p;
    cudaGetSymbolAddress(&p, g_cnt2);     S.cnt2  = (int*)p;
    cudaGetSymbolAddress(&p, g_bsum);     S.bsum  = (int*)p;
    cudaGetSymbolAddress(&p, g_bsum2);    S.bsum2 = (int*)p;

    StreamCtx& C = ctx();
    cudaStream_t s1 = C.s1, s2 = C.s2;

    // ---- fork for prep ----
    cudaEventRecord(C.evF, 0);
    cudaStreamWaitEvent(s1, C.evF, 0);
    cudaStreamWaitEvent(s2, C.evF, 0);

    // s1: CSR g then CSR b (share cnt2/bsum2)
    build_csr(S.cnt2, S.bsum2, S.rp_g, S.v_g, dst_g, src_g, NNODES, NEDGES, s1);
    cudaMemsetAsync(S.cnt2, 0, (size_t)NNODES * sizeof(int), s1);
    hist2_kernel<<<blocks_for(NEDGES), 256, 0, s1>>>(S.cnt2, src_g, dst_g, NEDGES);
    scan_excl(S.cnt2, S.rp_b, S.bsum2, NNODES, s1);
    cudaMemcpyAsync(S.cnt2, S.rp_b, (size_t)NNODES * sizeof(int), cudaMemcpyDeviceToDevice, s1);
    fill_csr2_kernel<<<blocks_for(NEDGES), 256, 0, s1>>>(S.cnt2, S.v_b, src_g, dst_g, NEDGES);

    // s2: CSR l
    build_csr(S.cnt, S.bsum, S.rp_l, S.v_l, dst_l, src_l, NEDGES, NLGE, s2);

    // legacy: weight prep + initial activations
    build_wtcat_kernel<<<blocks_for((long)4 * H * 1536), 256>>>(w_self, w_fuse, w_khop, S.wtcat);
    build_wt1_kernel<<<blocks_for((long)4 * FH * H), 256>>>(w_ff1, S.wt1);
    build_wt2_kernel<<<blocks_for((long)4 * H * FH), 256>>>(w_ff2, S.wt2);
    build_bcat_kernel<<<blocks_for(4 * H), 256>>>(b_self, b_fuse, b_khop, S.bcat);
    cudaMemcpyAsync(S.x0, x_in, (size_t)NNODES * H * sizeof(float), cudaMemcpyDeviceToDevice);
    gather_embed_kernel<<<blocks_for((long)NEDGES * 64), 256>>>(S.lg0, rel, edge_feat, NEDGES);

    // join prep
    cudaEventRecord(C.evA, s1);
    cudaEventRecord(C.evB, s2);
    cudaStreamWaitEvent(0, C.evA, 0);
    cudaStreamWaitEvent(0, C.evB, 0);

    float* xb[2]  = {S.x0, S.x1};
    float* lgb[2] = {S.lg0, S.lg1};

    int cur = 0;
    for (int l = 0; l < LNUM; l++) {
        const float* x  = xb[cur];
        const float* lg = lgb[cur];
        float* xn  = xb[1 - cur];
        float* lgn = lgb[1 - cur];

        // fork: s1 runs the node core, legacy runs the edge core
        cudaEventRecord(C.evT[l], 0);
        cudaStreamWaitEvent(s1, C.evT[l], 0);

        // s1: fused_nodes + node core
        spmm_csr_kernel<<<(NNODES + 7) / 8, 256, 0, s1>>>(S.fn, lg, S.rp_b, S.v_b, NNODES);
        {
            int lc = l * 2 + 0;
            run_core(S, x, S.fn, xn, NNODES, S.rp_g, S.v_g,
                     S.zn, (size_t)NNODES * H, S.ln1n, S.ffhn, lc,
                     b_ff1 + (size_t)lc * FH, b_ff2 + (size_t)lc * H,
                     ln1_g + (size_t)lc * H, ln1_b + (size_t)lc * H,
                     ln2_g + (size_t)lc * H, ln2_b + (size_t)lc * H, s1);
        }

        // legacy: fused_edges + edge core
        gather_sum_kernel<<<blocks_for((long)NEDGES * 64), 256>>>(S.fe, x, src_g, dst_g, NEDGES);
        {
            int lc = l * 2 + 1;
            run_core(S, lg, S.fe, lgn, NEDGES, S.rp_l, S.v_l,
                     S.z, (size_t)NEDGES * H, S.ln1, S.ffh, lc,
                     b_ff1 + (size_t)lc * FH, b_ff2 + (size_t)lc * H,
                     ln1_g + (size_t)lc * H, ln1_b + (size_t)lc * H,
                     ln2_g + (size_t)lc * H, ln2_b + (size_t)lc * H, (cudaStream_t)0);
        }

        // join
        cudaEventRecord(C.evN[l], s1);
        cudaStreamWaitEvent(0, C.evN[l], 0);

        cur = 1 - cur;
    }

    cudaMemcpyAsync(d_out, xb[cur], (size_t)NNODES * H * sizeof(float),
                    cudaMemcpyDeviceToDevice);
    cudaMemcpyAsync((float*)d_out + (size_t)NNODES * H, lgb[cur],
                    (size_t)NEDGES * H * sizeof(float), cudaMemcpyDeviceToDevice);
}

// round 13
// speedup vs baseline: 4.8287x; 1.3536x over previous
#include <cuda_runtime.h>
#include <cuda_fp16.h>
#include <math.h>
#include <stdint.h>

#define H 256
#define FH 1024
#define LNUM 2
#define KHOPS 4
#define NNODES 20000
#define NEDGES 160000
#define NLGE 640000

// ---------------- scratch (device globals; no allocations) ----------------
__device__ __align__(256) float g_x0[(size_t)NNODES * H];
__device__ __align__(256) float g_x1[(size_t)NNODES * H];
__device__ __align__(256) float g_lg0[(size_t)NEDGES * H];
__device__ __align__(256) float g_lg1[(size_t)NEDGES * H];
__device__ __align__(256) float g_fn[(size_t)NNODES * H];
__device__ __align__(256) float g_fe[(size_t)NEDGES * H];
__device__ __align__(256) float g_z[(size_t)4 * NEDGES * H];     // edge-core hop buffers
__device__ __align__(256) float g_ln1[(size_t)NEDGES * H];
__device__ __align__(256) __half g_ffh[(size_t)NEDGES * FH];     // fp16 intermediate
__device__ __align__(256) float g_zn[(size_t)4 * NNODES * H];    // node-core hop buffers
__device__ __align__(256) float g_ln1n[(size_t)NNODES * H];
__device__ __align__(256) __half g_ffhn[(size_t)NNODES * FH];
// pre-transposed fp16 weights, [lc][N][K] K-major
__device__ __align__(256) __half g_wtcat[(size_t)4 * H * (6 * H)];
__device__ __align__(256) __half g_wt1[(size_t)4 * FH * H];
__device__ __align__(256) __half g_wt2[(size_t)4 * H * FH];
__device__ __align__(256) float g_bcat[(size_t)4 * H];
// CSR structures
__device__ int g_rowptr_g[NNODES + 1];
__device__ int g_val_g[NEDGES];
__device__ int g_rowptr_b[NNODES + 1];
__device__ int g_val_b[2 * NEDGES];
__device__ int g_rowptr_l[NEDGES + 1];
__device__ int g_val_l[NLGE];
__device__ int g_cnt[NEDGES + 1];
__device__ int g_cnt2[NNODES + 1];
__device__ int g_bsum[1024];
__device__ int g_bsum2[1024];

// ---------------- device helpers ----------------
__device__ __forceinline__ float gelu_f(float v) {
    return 0.5f * v * (1.0f + erff(v * 0.70710678118654752f));
}
__device__ __forceinline__ uint2 f4_to_h4(float4 v) {
    __half2 lo = __floats2half2_rn(v.x, v.y);
    __half2 hi = __floats2half2_rn(v.z, v.w);
    uint2 r;
    r.x = *(uint32_t*)&lo;
    r.y = *(uint32_t*)&hi;
    return r;
}
__device__ __forceinline__ void cp_async16(uint32_t saddr, const void* gptr) {
    asm volatile("cp.async.cg.shared.global [%0], [%1], 16;" :: "r"(saddr), "l"(gptr));
}
#define CP_COMMIT() asm volatile("cp.async.commit_group;")
#define CP_WAIT0()  asm volatile("cp.async.wait_group 0;")

// ---------------- CSR build ----------------
__global__ void hist_kernel(int* __restrict__ cnt, const int* __restrict__ keys, int m)
{
    int t = blockIdx.x * blockDim.x + threadIdx.x;
    if (t < m) atomicAdd(&cnt[keys[t]], 1);
}
__global__ void hist2_kernel(int* __restrict__ cnt, const int* __restrict__ k1,
                             const int* __restrict__ k2, int m)
{
    int t = blockIdx.x * blockDim.x + threadIdx.x;
    if (t < m) { atomicAdd(&cnt[k1[t]], 1); atomicAdd(&cnt[k2[t]], 1); }
}

// ---- multi-block exclusive scan (3 phases) ----
__global__ __launch_bounds__(1024)
void scan_part_kernel(const int* __restrict__ in, int* __restrict__ out,
                      int* __restrict__ bsum, int n)
{
    __shared__ int warpsums[32];
    const int tid = threadIdx.x, lane = tid & 31, w = tid >> 5;
    const int i = blockIdx.x * 1024 + tid;
    int v = (i < n) ? in[i] : 0;
    int s = v;
#pragma unroll
    for (int o = 1; o < 32; o <<= 1) {
        int t = __shfl_up_sync(0xFFFFFFFFu, s, o);
        if (lane >= o) s += t;
    }
    if (lane == 31) warpsums[w] = s;
    __syncthreads();
    if (w == 0) {
        int ws = warpsums[lane];
#pragma unroll
        for (int o = 1; o < 32; o <<= 1) {
            int t = __shfl_up_sync(0xFFFFFFFFu, ws, o);
            if (lane >= o) ws += t;
        }
        warpsums[lane] = ws;
    }
    __syncthreads();
    int excl = s - v + (w > 0 ? warpsums[w - 1] : 0);
    if (i < n) out[i] = excl;
    if (tid == 1023) bsum[blockIdx.x] = excl + v;
}

__global__ __launch_bounds__(1024)
void scan_bsum_kernel(int* __restrict__ bsum, int nb)
{
    __shared__ int warpsums[32];
    const int tid = threadIdx.x, lane = tid & 31, w = tid >> 5;
    int v = (tid < nb) ? bsum[tid] : 0;
    int s = v;
#pragma unroll
    for (int o = 1; o < 32; o <<= 1) {
        int t = __shfl_up_sync(0xFFFFFFFFu, s, o);
        if (lane >= o) s += t;
    }
    if (lane == 31) warpsums[w] = s;
    __syncthreads();
    if (w == 0) {
        int ws = warpsums[lane];
#pragma unroll
        for (int o = 1; o < 32; o <<= 1) {
            int t = __shfl_up_sync(0xFFFFFFFFu, ws, o);
            if (lane >= o) ws += t;
        }
        warpsums[lane] = ws;
    }
    __syncthreads();
    int excl = s - v + (w > 0 ? warpsums[w - 1] : 0);
    if (tid < nb) bsum[tid] = excl;
}

__global__ __launch_bounds__(1024)
void scan_add_kernel(const int* __restrict__ in, int* __restrict__ out,
                     const int* __restrict__ bsum, int n)
{
    const int i = blockIdx.x * 1024 + threadIdx.x;
    if (i < n) {
        int o = out[i] + bsum[blockIdx.x];
        out[i] = o;
        if (i == n - 1) out[n] = o + in[i];
    }
}

__global__ void fill_csr_kernel(int* __restrict__ cursor, int* __restrict__ val,
                                const int* __restrict__ keys, const int* __restrict__ payload,
                                int m)
{
    int t = blockIdx.x * blockDim.x + threadIdx.x;
    if (t >= m) return;
    int pos = atomicAdd(&cursor[keys[t]], 1);
    val[pos] = payload[t];
}
__global__ void fill_csr2_kernel(int* __restrict__ cursor, int* __restrict__ val,
                                 const int* __restrict__ k1, const int* __restrict__ k2, int m)
{
    int t = blockIdx.x * blockDim.x + threadIdx.x;
    if (t >= m) return;
    int p1 = atomicAdd(&cursor[k1[t]], 1);
    val[p1] = t;
    int p2 = atomicAdd(&cursor[k2[t]], 1);
    val[p2] = t;
}

// ---------------- CSR SpMM: out[row] = sum_j in[val[j]] ----------------
__global__ __launch_bounds__(256)
void spmm_csr_kernel(float* __restrict__ out, const float* __restrict__ in,
                     const int* __restrict__ rowptr, const int* __restrict__ val, int n)
{
    int row = blockIdx.x * 8 + (threadIdx.x >> 5);
    if (row >= n) return;
    int lane = threadIdx.x & 31;
    int beg = rowptr[row], end = rowptr[row + 1];
    float4 a0 = make_float4(0.f, 0.f, 0.f, 0.f), a1 = a0;
    for (int j = beg; j < end; j++) {
        const float* p = in + (size_t)val[j] * H + lane * 8;
        float4 v0 = *(const float4*)p;
        float4 v1 = *(const float4*)(p + 4);
        a0.x += v0.x; a0.y += v0.y; a0.z += v0.z; a0.w += v0.w;
        a1.x += v1.x; a1.y += v1.y; a1.z += v1.z; a1.w += v1.w;
    }
    float* o = out + (size_t)row * H + lane * 8;
    *(float4*)o = a0;
    *(float4*)(o + 4) = a1;
}

// ---------------- fp16 mma.sync GEMM with segmented A + fused epilogues ----------------
// C = A @ Bt^T + bias. Block tile 128x256, BK=32 (2 k16 steps), 8 warps 64x64.
// A: fp32 slices (converted on smem store) or fp16 (a_half=1, cp.async direct).
// Bt: fp16 [N][K] K-major.
// mode 0: gelu(out) -> C as fp16    (FFN1)
// mode 1: LN(resid + gelu(out)) -> C fp32  (N==256, grid.x==1)
// mode 2: LN(resid + out) -> C fp32        (N==256, grid.x==1)
#define ASTR32 20                      // uint32 per smem row (40 halves: 32 data + 8 pad)
#define ABUF_A32 (128 * ASTR32)
#define ABUF_B32 (256 * ASTR32)
#define GEMM_SMEM ((2 * ABUF_A32 + 2 * ABUF_B32) * 4)

struct SliceArgs {
    const void* p[6];
    int ld[6];
};

__device__ __forceinline__ void mma_f16(float* c, const uint32_t* a, const uint32_t* b) {
    asm volatile(
        "mma.sync.aligned.m16n8k16.row.col.f32.f16.f16.f32 "
        "{%0,%1,%2,%3}, {%4,%5,%6,%7}, {%8,%9}, {%0,%1,%2,%3};"
        : "+f"(c[0]), "+f"(c[1]), "+f"(c[2]), "+f"(c[3])
        : "r"(a[0]), "r"(a[1]), "r"(a[2]), "r"(a[3]), "r"(b[0]), "r"(b[1]));
}

__global__ __launch_bounds__(256)
void mma_gemm3(SliceArgs sa, int a_half,
               const __half* __restrict__ Bt,
               const float* __restrict__ bias,
               const float* __restrict__ resid,
               const float* __restrict__ gamma,
               const float* __restrict__ beta,
               float* __restrict__ C,
               int M, int N, int K, int mode)
{
    extern __shared__ uint32_t smem[];
    uint32_t* AsBase = smem;                      // [2][128][ASTR32]
    uint32_t* BsBase = smem + 2 * ABUF_A32;       // [2][256][ASTR32]

    const int tid = threadIdx.x;
    const int wid = tid >> 5, lane = tid & 31;
    const int gid = lane >> 2, tig = lane & 3;
    const int warp_m = (wid & 1) * 64;
    const int warp_n = (wid >> 1) * 64;
    const int row0 = blockIdx.y * 128;
    const int col0 = blockIdx.x * 256;

    float acc[4][8][4];
#pragma unroll
    for (int mt = 0; mt < 4; mt++)
#pragma unroll
        for (int nt = 0; nt < 8; nt++)
#pragma unroll
            for (int j = 0; j < 4; j++) acc[mt][nt][j] = 0.f;

    const int nc = K >> 5;
    float4 ra[4];

    // ---- prologue chunk 0 ----
#pragma unroll
    for (int f = 0; f < 4; f++) {
        int i = f * 256 + tid, r = i >> 2, c16 = i & 3;
        uint32_t dst = (uint32_t)__cvta_generic_to_shared(BsBase + r * ASTR32 + c16 * 4);
        cp_async16(dst, Bt + (size_t)(col0 + r) * K + c16 * 8);
    }
    if (a_half) {
        const __half* Ah = (const __half*)sa.p[0];
        const int ldA = sa.ld[0];
#pragma unroll
        for (int f = 0; f < 2; f++) {
            int i = f * 256 + tid, r = i >> 2, c16 = i & 3;
            int gr = row0 + r; if (gr >= M) gr = M - 1;
            uint32_t dst = (uint32_t)__cvta_generic_to_shared(AsBase + r * ASTR32 + c16 * 4);
            cp_async16(dst, Ah + (size_t)gr * ldA + c16 * 8);
        }
        CP_COMMIT();
    } else {
        CP_COMMIT();
        const float* Ap = (const float*)sa.p[0];
        const int ldA = sa.ld[0];
#pragma unroll
        for (int f = 0; f < 4; f++) {
            int i = f * 256 + tid, r = i >> 3, c4 = i & 7;
            int gr = row0 + r; if (gr >= M) gr = M - 1;
            ra[f] = *(const float4*)(Ap + (size_t)gr * ldA + c4 * 4);
        }
#pragma unroll
        for (int f = 0; f < 4; f++) {
            int i = f * 256 + tid, r = i >> 3, c4 = i & 7;
            *(uint2*)(AsBase + r * ASTR32 + c4 * 2) = f4_to_h4(ra[f]);
        }
    }
    CP_WAIT0();
    __syncthreads();

    for (int c = 0; c < nc; c++) {
        const int nxt = c + 1;
        if (nxt < nc) {
            const int k0 = nxt << 5;
            uint32_t* Bs = BsBase + (nxt & 1) * ABUF_B32;
#pragma unroll
            for (int f = 0; f < 4; f++) {
                int i = f * 256 + tid, r = i >> 2, c16 = i & 3;
                uint32_t dst = (uint32_t)__cvta_generic_to_shared(Bs + r * ASTR32 + c16 * 4);
                cp_async16(dst, Bt + (size_t)(col0 + r) * K + k0 + c16 * 8);
            }
            const int sl = k0 >> 8;
            const int off = k0 & 255;
            if (a_half) {
                const __half* Ah = (const __half*)sa.p[sl];
                const int ldA = sa.ld[sl];
                uint32_t* As = AsBase + (nxt & 1) * ABUF_A32;
#pragma unroll
                for (int f = 0; f < 2; f++) {
                    int i = f * 256 + tid, r = i >> 2, c16 = i & 3;
                    int gr = row0 + r; if (gr >= M) gr = M - 1;
                    uint32_t dst = (uint32_t)__cvta_generic_to_shared(As + r * ASTR32 + c16 * 4);
                    cp_async16(dst, Ah + (size_t)gr * ldA + off + c16 * 8);
                }
                CP_COMMIT();
            } else {
                CP_COMMIT();
                const float* Ap = (const float*)sa.p[sl];
                const int ldA = sa.ld[sl];
#pragma unroll
                for (int f = 0; f < 4; f++) {
                    int i = f * 256 + tid, r = i >> 3, c4 = i & 7;
                    int gr = row0 + r; if (gr >= M) gr = M - 1;
                    ra[f] = *(const float4*)(Ap + (size_t)gr * ldA + off + c4 * 4);
                }
            }
        }

        const uint32_t* Asu = AsBase + (c & 1) * ABUF_A32;
        const uint32_t* Bsu = BsBase + (c & 1) * ABUF_B32;
#pragma unroll
        for (int ks = 0; ks < 2; ks++) {
            const int k0c = ks * 8;
            uint32_t afr[4][4], bfr[8][2];
#pragma unroll
            for (int mt = 0; mt < 4; mt++) {
                int r = warp_m + mt * 16 + gid;
                afr[mt][0] = Asu[r * ASTR32 + k0c + tig];
                afr[mt][1] = Asu[(r + 8) * ASTR32 + k0c + tig];
                afr[mt][2] = Asu[r * ASTR32 + k0c + tig + 4];
                afr[mt][3] = Asu[(r + 8) * ASTR32 + k0c + tig + 4];
            }
#pragma unroll
            for (int nt = 0; nt < 8; nt++) {
                int cc = warp_n + nt * 8 + gid;
                bfr[nt][0] = Bsu[cc * ASTR32 + k0c + tig];
                bfr[nt][1] = Bsu[cc * ASTR32 + k0c + tig + 4];
            }
#pragma unroll
            for (int mt = 0; mt < 4; mt++)
#pragma unroll
                for (int nt = 0; nt < 8; nt++)
                    mma_f16(acc[mt][nt], afr[mt], bfr[nt]);
        }

        if (nxt < nc) {
            if (!a_half) {
                uint32_t* As = AsBase + (nxt & 1) * ABUF_A32;
#pragma unroll
                for (int f = 0; f < 4; f++) {
                    int i = f * 256 + tid, r = i >> 3, c4 = i & 7;
                    *(uint2*)(As + r * ASTR32 + c4 * 2) = f4_to_h4(ra[f]);
                }
            }
            CP_WAIT0();
        }
        __syncthreads();
    }

    if (mode == 0) {
        // gelu epilogue, fp16 output (FFN1 -> ffh)
        __half* Ch = (__half*)C;
#pragma unroll
        for (int mt = 0; mt < 4; mt++) {
#pragma unroll
            for (int nt = 0; nt < 8; nt++) {
                int cc = col0 + warp_n + nt * 8 + 2 * tig;
                float bx = bias[cc], by = bias[cc + 1];
#pragma unroll
                for (int h = 0; h < 2; h++) {
                    int r = row0 + warp_m + mt * 16 + gid + h * 8;
                    if (r >= M) continue;
                    float ox = gelu_f(acc[mt][nt][h * 2 + 0] + bx);
                    float oy = gelu_f(acc[mt][nt][h * 2 + 1] + by);
                    *(__half2*)(Ch + (size_t)r * N + cc) = __floats2half2_rn(ox, oy);
                }
            }
        }
        return;
    }

    // ---- fused LayerNorm epilogue (N == 256, grid.x == 1) ----
    float2* rowstat = (float2*)smem;
    float sumv[4][2], sqv[4][2];
#pragma unroll
    for (int mt = 0; mt < 4; mt++)
#pragma unroll
        for (int h = 0; h < 2; h++) { sumv[mt][h] = 0.f; sqv[mt][h] = 0.f; }

#pragma unroll
    for (int mt = 0; mt < 4; mt++) {
#pragma unroll
        for (int h = 0; h < 2; h++) {
            int r = row0 + warp_m + mt * 16 + gid + h * 8;
            int rc = r < M ? r : M - 1;
#pragma unroll
            for (int nt = 0; nt < 8; nt++) {
                int cc = warp_n + nt * 8 + 2 * tig;
                float2 b2 = *(const float2*)(bias + cc);
                float2 rd = *(const float2*)(resid + (size_t)rc * H + cc);
                float vx = acc[mt][nt][h * 2 + 0] + b2.x;
                float vy = acc[mt][nt][h * 2 + 1] + b2.y;
                if (mode == 1) { vx = gelu_f(vx); vy = gelu_f(vy); }
                vx += rd.x; vy += rd.y;
                acc[mt][nt][h * 2 + 0] = vx;
                acc[mt][nt][h * 2 + 1] = vy;
                sumv[mt][h] += vx + vy;
                sqv[mt][h] += vx * vx + vy * vy;
            }
        }
    }
#pragma unroll
    for (int mt = 0; mt < 4; mt++)
#pragma unroll
        for (int h = 0; h < 2; h++) {
            sumv[mt][h] += __shfl_xor_sync(0xFFFFFFFFu, sumv[mt][h], 1);
            sumv[mt][h] += __shfl_xor_sync(0xFFFFFFFFu, sumv[mt][h], 2);
            sqv[mt][h]  += __shfl_xor_sync(0xFFFFFFFFu, sqv[mt][h], 1);
            sqv[mt][h]  += __shfl_xor_sync(0xFFFFFFFFu, sqv[mt][h], 2);
        }
    if (tig == 0) {
        int wn = warp_n >> 6;
#pragma unroll
        for (int mt = 0; mt < 4; mt++)
#pragma unroll
            for (int h = 0; h < 2; h++) {
                int rl = warp_m + mt * 16 + gid + h * 8;
                rowstat[rl * 4 + wn] = make_float2(sumv[mt][h], sqv[mt][h]);
            }
    }
    __syncthreads();

    float mean_[4][2], rstd_[4][2];
#pragma unroll
    for (int mt = 0; mt < 4; mt++)
#pragma unroll
        for (int h = 0; h < 2; h++) {
            int rl = warp_m + mt * 16 + gid + h * 8;
            float s = 0.f, q = 0.f;
#pragma unroll
            for (int w = 0; w < 4; w++) {
                float2 t = rowstat[rl * 4 + w];
                s += t.x; q += t.y;
            }
            float mean = s * (1.0f / H);
            float var = q * (1.0f / H) - mean * mean;
            mean_[mt][h] = mean;
            rstd_[mt][h] = rsqrtf(var + 1e-5f);
        }

#pragma unroll
    for (int mt = 0; mt < 4; mt++) {
#pragma unroll
        for (int nt = 0; nt < 8; nt++) {
            int cc = warp_n + nt * 8 + 2 * tig;
            float2 gv = *(const float2*)(gamma + cc);
            float2 bv = *(const float2*)(beta + cc);
#pragma unroll
            for (int h = 0; h < 2; h++) {
                int r = row0 + warp_m + mt * 16 + gid + h * 8;
                if (r >= M) continue;
                float m = mean_[mt][h], rs = rstd_[mt][h];
                float ox = (acc[mt][nt][h * 2 + 0] - m) * rs * gv.x + bv.x;
                float oy = (acc[mt][nt][h * 2 + 1] - m) * rs * gv.y + bv.y;
                *(float2*)(C + (size_t)r * H + cc) = make_float2(ox, oy);
            }
        }
    }
}

// ---------------- weight prep (transpose to [N,K] K-major, fp16) ----------------
__global__ void build_wtcat_kernel(const float* __restrict__ ws, const float* __restrict__ wf,
                                   const float* __restrict__ wk, __half* __restrict__ out)
{
    long t = (long)blockIdx.x * blockDim.x + threadIdx.x;
    if (t >= (long)4 * H * 1536) return;
    int lc = (int)(t / (H * 1536));
    int rem = (int)(t % (H * 1536));
    int n = rem / 1536, k = rem % 1536;
    float v;
    if (k < 256) v = ws[(size_t)lc * 65536 + k * 256 + n];
    else if (k < 512) v = wf[(size_t)lc * 65536 + (k - 256) * 256 + n];
    else {
        int hop = (k - 512) >> 8, kk = (k - 512) & 255;
        v = wk[((size_t)(lc * 4 + hop) * 256 + kk) * 256 + n];
    }
    out[t] = __float2half_rn(v);
}

__global__ void build_wt1_kernel(const float* __restrict__ w1, __half* __restrict__ out)
{
    long t = (long)blockIdx.x * blockDim.x + threadIdx.x;
    if (t >= (long)4 * FH * H) return;
    int lc = (int)(t / (FH * H));
    int rem = (int)(t % (FH * H));
    int n = rem / H, k = rem % H;
    out[t] = __float2half_rn(w1[(size_t)lc * (H * FH) + (size_t)k * FH + n]);
}

__global__ void build_wt2_kernel(const float* __restrict__ w2, __half* __restrict__ out)
{
    long t = (long)blockIdx.x * blockDim.x + threadIdx.x;
    if (t >= (long)4 * H * FH) return;
    int lc = (int)(t / (H * FH));
    int rem = (int)(t % (H * FH));
    int n = rem / FH, k = rem % FH;
    out[t] = __float2half_rn(w2[(size_t)lc * (FH * H) + (size_t)k * H + n]);
}

__global__ void build_bcat_kernel(const float* __restrict__ bs, const float* __restrict__ bf,
                                  const float* __restrict__ bk, float* __restrict__ out)
{
    int t = blockIdx.x * blockDim.x + threadIdx.x;
    if (t >= 4 * H) return;
    int lc = t / H, n = t % H;
    float v = bs[lc * H + n] + bf[lc * H + n];
    for (int i = 0; i < KHOPS; i++) v += bk[(lc * KHOPS + i) * H + n];
    out[t] = v;
}

// ---------------- gathers ----------------
__global__ void gather_sum_kernel(float* __restrict__ out, const float* __restrict__ x,
                                  const int* __restrict__ src, const int* __restrict__ dst,
                                  int m)
{
    long t = (long)blockIdx.x * blockDim.x + threadIdx.x;
    if (t >= (long)m * 64) return;
    int e = (int)(t >> 6);
    int c = (int)(t & 63) << 2;
    float4 a = *(const float4*)(x + (size_t)src[e] * H + c);
    float4 b = *(const float4*)(x + (size_t)dst[e] * H + c);
    *(float4*)(out + (size_t)e * H + c) = make_float4(a.x + b.x, a.y + b.y, a.z + b.z, a.w + b.w);
}

__global__ void gather_embed_kernel(float* __restrict__ out, const float* __restrict__ rel,
                                    const int* __restrict__ feat, int m)
{
    long t = (long)blockIdx.x * blockDim.x + threadIdx.x;
    if (t >= (long)m * 64) return;
    int e = (int)(t >> 6);
    int c = (int)(t & 63) << 2;
    *(float4*)(out + (size_t)e * H + c) = *(const float4*)(rel + (size_t)feat[e] * H + c);
}

// ---------------- host side ----------------
static inline int blocks_for(long threads) { return (int)((threads + 255) / 256); }

struct Scratch {
    float *x0, *x1, *lg0, *lg1, *fn, *fe;
    float *z, *ln1;
    __half *ffh;
    float *zn, *ln1n;
    __half *ffhn;
    __half *wtcat, *wt1, *wt2;
    float *bcat;
    int *rp_g, *v_g, *rp_b, *v_b, *rp_l, *v_l, *cnt, *cnt2, *bsum, *bsum2;
};

struct StreamCtx {
    cudaStream_t s1, s2;
    cudaEvent_t evF, evA, evB, evT[2], evN[2];
    StreamCtx() {
        cudaStreamCreateWithFlags(&s1, cudaStreamNonBlocking);
        cudaStreamCreateWithFlags(&s2, cudaStreamNonBlocking);
        cudaEventCreateWithFlags(&evF, cudaEventDisableTiming);
        cudaEventCreateWithFlags(&evA, cudaEventDisableTiming);
        cudaEventCreateWithFlags(&evB, cudaEventDisableTiming);
        for (int i = 0; i < 2; i++) {
            cudaEventCreateWithFlags(&evT[i], cudaEventDisableTiming);
            cudaEventCreateWithFlags(&evN[i], cudaEventDisableTiming);
        }
    }
};
static StreamCtx& ctx() { static StreamCtx c; return c; }

static void scan_excl(const int* in, int* out, int* bsum, int n, cudaStream_t st)
{
    int nb = (n + 1023) / 1024;
    scan_part_kernel<<<nb, 1024, 0, st>>>(in, out, bsum, n);
    scan_bsum_kernel<<<1, 1024, 0, st>>>(bsum, nb);
    scan_add_kernel<<<nb, 1024, 0, st>>>(in, out, bsum, n);
}

static void build_csr(int* cnt, int* bsum, int* rowptr, int* val,
                      const int* keys, const int* payload, int n, int m, cudaStream_t st)
{
    cudaMemsetAsync(cnt, 0, (size_t)n * sizeof(int), st);
    hist_kernel<<<blocks_for(m), 256, 0, st>>>(cnt, keys, m);
    scan_excl(cnt, rowptr, bsum, n, st);
    cudaMemcpyAsync(cnt, rowptr, (size_t)n * sizeof(int), cudaMemcpyDeviceToDevice, st);
    fill_csr_kernel<<<blocks_for(m), 256, 0, st>>>(cnt, val, keys, payload, m);
}

static void run_core(const Scratch& S,
                     const float* xin, const float* fused, float* xout,
                     int n, const int* rowptr, const int* val,
                     float* zbuf, size_t zstride, float* ln1buf, __half* ffhbuf,
                     int lc,
                     const float* b_ff1, const float* b_ff2,
                     const float* g1, const float* c1,
                     const float* g2, const float* c2,
                     cudaStream_t st)
{
    const int gy = (n + 127) / 128;
    float* z1 = zbuf;
    float* z2 = zbuf + zstride;
    float* z3 = zbuf + 2 * zstride;
    float* z4 = zbuf + 3 * zstride;

    const int sg = (n + 7) / 8;
    spmm_csr_kernel<<<sg, 256, 0, st>>>(z1, xin, rowptr, val, n);
    spmm_csr_kernel<<<sg, 256, 0, st>>>(z2, z1, rowptr, val, n);
    spmm_csr_kernel<<<sg, 256, 0, st>>>(z3, z2, rowptr, val, n);
    spmm_csr_kernel<<<sg, 256, 0, st>>>(z4, z3, rowptr, val, n);

    // ln1 = LN( xin + gelu( concat_A @ Wcat + bcat ) )
    {
        SliceArgs sa;
        sa.p[0] = xin;   sa.ld[0] = H;
        sa.p[1] = fused; sa.ld[1] = H;
        sa.p[2] = z1;    sa.ld[2] = H;
        sa.p[3] = z2;    sa.ld[3] = H;
        sa.p[4] = z3;    sa.ld[4] = H;
        sa.p[5] = z4;    sa.ld[5] = H;
        mma_gemm3<<<dim3(1, gy), 256, GEMM_SMEM, st>>>(
            sa, 0, S.wtcat + (size_t)lc * H * 1536, S.bcat + (size_t)lc * H,
            xin, g1, c1, ln1buf, n, H, 1536, 1);
    }
    // ffh = gelu(ln1 @ w1 + b1)  [fp16 out]
    {
        SliceArgs sa;
        for (int i = 0; i < 6; i++) { sa.p[i] = ln1buf; sa.ld[i] = H; }
        mma_gemm3<<<dim3(FH / 256, gy), 256, GEMM_SMEM, st>>>(
            sa, 0, S.wt1 + (size_t)lc * FH * H, b_ff1,
            nullptr, nullptr, nullptr, (float*)ffhbuf, n, FH, H, 0);
    }
    // xout = LN( ln1 + ffh @ w2 + b2 )  [fp16 A]
    {
        SliceArgs sa;
        for (int i = 0; i < 4; i++) { sa.p[i] = ffhbuf + (size_t)i * 256; sa.ld[i] = FH; }
        sa.p[4] = ffhbuf; sa.ld[4] = FH;
        sa.p[5] = ffhbuf; sa.ld[5] = FH;
        mma_gemm3<<<dim3(1, gy), 256, GEMM_SMEM, st>>>(
            sa, 1, S.wt2 + (size_t)lc * H * FH, b_ff2,
            ln1buf, g2, c2, xout, n, H, FH, 2);
    }
}

extern "C" void kernel_launch(void* const* d_in, const int* in_sizes, int n_in,
                              void* d_out, int out_size)
{
    const float* x_in      = (const float*)d_in[0];
    const int*   edge_feat = (const int*)d_in[1];
    const int*   eig       = (const int*)d_in[2];
    const int*   eil       = (const int*)d_in[3];
    const float* rel       = (const float*)d_in[4];
    const float* w_self    = (const float*)d_in[5];
    const float* b_self    = (const float*)d_in[6];
    const float* w_khop    = (const float*)d_in[7];
    const float* b_khop    = (const float*)d_in[8];
    const float* w_fuse    = (const float*)d_in[9];
    const float* b_fuse    = (const float*)d_in[10];
    const float* w_ff1     = (const float*)d_in[11];
    const float* b_ff1     = (const float*)d_in[12];
    const float* w_ff2     = (const float*)d_in[13];
    const float* b_ff2     = (const float*)d_in[14];
    const float* ln1_g     = (const float*)d_in[15];
    const float* ln1_b     = (const float*)d_in[16];
    const float* ln2_g     = (const float*)d_in[17];
    const float* ln2_b     = (const float*)d_in[18];

    const int* src_g = eig;
    const int* dst_g = eig + NEDGES;
    const int* src_l = eil;
    const int* dst_l = eil + NLGE;

    cudaFuncSetAttribute(mma_gemm3, cudaFuncAttributeMaxDynamicSharedMemorySize, GEMM_SMEM);

    Scratch S;
    void* p;
    cudaGetSymbolAddress(&p, g_x0);       S.x0    = (float*)p;
    cudaGetSymbolAddress(&p, g_x1);       S.x1    = (float*)p;
    cudaGetSymbolAddress(&p, g_lg0);      S.lg0   = (float*)p;
    cudaGetSymbolAddress(&p, g_lg1);      S.lg1   = (float*)p;
    cudaGetSymbolAddress(&p, g_fn);       S.fn    = (float*)p;
    cudaGetSymbolAddress(&p, g_fe);       S.fe    = (float*)p;
    cudaGetSymbolAddress(&p, g_z);        S.z     = (float*)p;
    cudaGetSymbolAddress(&p, g_ln1);      S.ln1   = (float*)p;
    cudaGetSymbolAddress(&p, g_ffh);      S.ffh   = (__half*)p;
    cudaGetSymbolAddress(&p, g_zn);       S.zn    = (float*)p;
    cudaGetSymbolAddress(&p, g_ln1n);     S.ln1n  = (float*)p;
    cudaGetSymbolAddress(&p, g_ffhn);     S.ffhn  = (__half*)p;
    cudaGetSymbolAddress(&p, g_wtcat);    S.wtcat = (__half*)p;
    cudaGetSymbolAddress(&p, g_wt1);      S.wt1   = (__half*)p;
    cudaGetSymbolAddress(&p, g_wt2);      S.wt2   = (__half*)p;
    cudaGetSymbolAddress(&p, g_bcat);     S.bcat  = (float*)p;
    cudaGetSymbolAddress(&p, g_rowptr_g); S.rp_g  = (int*)p;
    cudaGetSymbolAddress(&p, g_val_g);    S.v_g   = (int*)p;
    cudaGetSymbolAddress(&p, g_rowptr_b); S.rp_b  = (int*)p;
    cudaGetSymbolAddress(&p, g_val_b);    S.v_b   = (int*)p;
    cudaGetSymbolAddress(&p, g_rowptr_l); S.rp_l  = (int*)p;
    cudaGetSymbolAddress(&p, g_val_l);    S.v_l   = (int*)p;
    cudaGetSymbolAddress(&p, g_cnt);      S.cnt   = (int*)p;
    cudaGetSymbolAddress(&p, g_cnt2);     S.cnt2  = (int*)p;
    cudaGetSymbolAddress(&p, g_bsum);     S.bsum  = (int*)p;
    cudaGetSymbolAddress(&p, g_bsum2);    S.bsum2 = (int*)p;

    StreamCtx& C = ctx();
    cudaStream_t s1 = C.s1, s2 = C.s2;

    // ---- fork for prep ----
    cudaEventRecord(C.evF, 0);
    cudaStreamWaitEvent(s1, C.evF, 0);
    cudaStreamWaitEvent(s2, C.evF, 0);

    // s1: CSR g then CSR b
    build_csr(S.cnt2, S.bsum2, S.rp_g, S.v_g, dst_g, src_g, NNODES, NEDGES, s1);
    cudaMemsetAsync(S.cnt2, 0, (size_t)NNODES * sizeof(int), s1);
    hist2_kernel<<<blocks_for(NEDGES), 256, 0, s1>>>(S.cnt2, src_g, dst_g, NEDGES);
    scan_excl(S.cnt2, S.rp_b, S.bsum2, NNODES, s1);
    cudaMemcpyAsync(S.cnt2, S.rp_b, (size_t)NNODES * sizeof(int), cudaMemcpyDeviceToDevice, s1);
    fill_csr2_kernel<<<blocks_for(NEDGES), 256, 0, s1>>>(S.cnt2, S.v_b, src_g, dst_g, NEDGES);

    // s2: CSR l
    build_csr(S.cnt, S.bsum, S.rp_l, S.v_l, dst_l, src_l, NEDGES, NLGE, s2);

    // legacy: weight prep + initial activations
    build_wtcat_kernel<<<blocks_for((long)4 * H * 1536), 256>>>(w_self, w_fuse, w_khop, S.wtcat);
    build_wt1_kernel<<<blocks_for((long)4 * FH * H), 256>>>(w_ff1, S.wt1);
    build_wt2_kernel<<<blocks_for((long)4 * H * FH), 256>>>(w_ff2, S.wt2);
    build_bcat_kernel<<<blocks_for(4 * H), 256>>>(b_self, b_fuse, b_khop, S.bcat);
    cudaMemcpyAsync(S.x0, x_in, (size_t)NNODES * H * sizeof(float), cudaMemcpyDeviceToDevice);
    gather_embed_kernel<<<blocks_for((long)NEDGES * 64), 256>>>(S.lg0, rel, edge_feat, NEDGES);

    // join prep
    cudaEventRecord(C.evA, s1);
    cudaEventRecord(C.evB, s2);
    cudaStreamWaitEvent(0, C.evA, 0);
    cudaStreamWaitEvent(0, C.evB, 0);

    float* xb[2]  = {S.x0, S.x1};
    float* lgb[2] = {S.lg0, S.lg1};

    int cur = 0;
    for (int l = 0; l < LNUM; l++) {
        const float* x  = xb[cur];
        const float* lg = lgb[cur];
        float* xn  = xb[1 - cur];
        float* lgn = lgb[1 - cur];

        cudaEventRecord(C.evT[l], 0);
        cudaStreamWaitEvent(s1, C.evT[l], 0);

        // s1: fused_nodes + node core
        spmm_csr_kernel<<<(NNODES + 7) / 8, 256, 0, s1>>>(S.fn, lg, S.rp_b, S.v_b, NNODES);
        {
            int lc = l * 2 + 0;
            run_core(S, x, S.fn, xn, NNODES, S.rp_g, S.v_g,
                     S.zn, (size_t)NNODES * H, S.ln1n, S.ffhn, lc,
                     b_ff1 + (size_t)lc * FH, b_ff2 + (size_t)lc * H,
                     ln1_g + (size_t)lc * H, ln1_b + (size_t)lc * H,
                     ln2_g + (size_t)lc * H, ln2_b + (size_t)lc * H, s1);
        }

        // legacy: fused_edges + edge core
        gather_sum_kernel<<<blocks_for((long)NEDGES * 64), 256>>>(S.fe, x, src_g, dst_g, NEDGES);
        {
            int lc = l * 2 + 1;
            run_core(S, lg, S.fe, lgn, NEDGES, S.rp_l, S.v_l,
                     S.z, (size_t)NEDGES * H, S.ln1, S.ffh, lc,
                     b_ff1 + (size_t)lc * FH, b_ff2 + (size_t)lc * H,
                     ln1_g + (size_t)lc * H, ln1_b + (size_t)lc * H,
                     ln2_g + (size_t)lc * H, ln2_b + (size_t)lc * H, (cudaStream_t)0);
        }

        cudaEventRecord(C.evN[l], s1);
        cudaStreamWaitEvent(0, C.evN[l], 0);

        cur = 1 - cur;
    }

    cudaMemcpyAsync(d_out, xb[cur], (size_t)NNODES * H * sizeof(float),
                    cudaMemcpyDeviceToDevice);
    cudaMemcpyAsync((float*)d_out + (size_t)NNODES * H, lgb[cur],
                    (size_t)NEDGES * H * sizeof(float), cudaMemcpyDeviceToDevice);
}

// round 14
// speedup vs baseline: 5.3630x; 1.1107x over previous
#include <cuda_runtime.h>
#include <cuda_fp16.h>
#include <math.h>
#include <stdint.h>

#define H 256
#define FH 1024
#define LNUM 2
#define KHOPS 4
#define NNODES 20000
#define NEDGES 160000
#define NLGE 640000

// ---------------- scratch (device globals; no allocations) ----------------
__device__ __align__(256) float g_x0[(size_t)NNODES * H];
__device__ __align__(256) float g_x1[(size_t)NNODES * H];
__device__ __align__(256) float g_lg0[(size_t)NEDGES * H];
__device__ __align__(256) float g_lg1[(size_t)NEDGES * H];
__device__ __align__(256) __half g_xh[(size_t)NNODES * H];      // fp16 mirror of x
__device__ __align__(256) __half g_lgh[(size_t)NEDGES * H];     // fp16 mirror of lg
__device__ __align__(256) __half g_fnh[(size_t)NNODES * H];
__device__ __align__(256) __half g_feh[(size_t)NEDGES * H];
__device__ __align__(256) __half g_zh[(size_t)4 * NEDGES * H];  // edge-core hops (fp16)
__device__ __align__(256) __half g_znh[(size_t)4 * NNODES * H]; // node-core hops (fp16)
__device__ __align__(256) float g_ln1[(size_t)NEDGES * H];
__device__ __align__(256) __half g_ffh[(size_t)NEDGES * FH];
__device__ __align__(256) float g_ln1n[(size_t)NNODES * H];
__device__ __align__(256) __half g_ffhn[(size_t)NNODES * FH];
// pre-transposed fp16 weights, [lc][N][K] K-major
__device__ __align__(256) __half g_wtcat[(size_t)4 * H * (6 * H)];
__device__ __align__(256) __half g_wt1[(size_t)4 * FH * H];
__device__ __align__(256) __half g_wt2[(size_t)4 * H * FH];
__device__ __align__(256) float g_bcat[(size_t)4 * H];
// CSR structures
__device__ int g_rowptr_g[NNODES + 1];
__device__ int g_val_g[NEDGES];
__device__ int g_rowptr_b[NNODES + 1];
__device__ int g_val_b[2 * NEDGES];
__device__ int g_rowptr_l[NEDGES + 1];
__device__ int g_val_l[NLGE];
__device__ int g_cnt[NEDGES + 1];
__device__ int g_cnt2[NNODES + 1];
__device__ int g_bsum[1024];
__device__ int g_bsum2[1024];

// ---------------- device helpers ----------------
__device__ __forceinline__ float gelu_f(float v) {
    return 0.5f * v * (1.0f + erff(v * 0.70710678118654752f));
}
__device__ __forceinline__ uint2 f4_to_h4(float4 v) {
    __half2 lo = __floats2half2_rn(v.x, v.y);
    __half2 hi = __floats2half2_rn(v.z, v.w);
    uint2 r;
    r.x = *(uint32_t*)&lo;
    r.y = *(uint32_t*)&hi;
    return r;
}
__device__ __forceinline__ void cp_async16(uint32_t saddr, const void* gptr) {
    asm volatile("cp.async.cg.shared.global [%0], [%1], 16;" :: "r"(saddr), "l"(gptr));
}
#define CP_COMMIT() asm volatile("cp.async.commit_group;")
#define CP_WAIT0()  asm volatile("cp.async.wait_group 0;")

// ---------------- CSR build ----------------
__global__ void hist_kernel(int* __restrict__ cnt, const int* __restrict__ keys, int m)
{
    int t = blockIdx.x * blockDim.x + threadIdx.x;
    if (t < m) atomicAdd(&cnt[keys[t]], 1);
}
__global__ void hist2_kernel(int* __restrict__ cnt, const int* __restrict__ k1,
                             const int* __restrict__ k2, int m)
{
    int t = blockIdx.x * blockDim.x + threadIdx.x;
    if (t < m) { atomicAdd(&cnt[k1[t]], 1); atomicAdd(&cnt[k2[t]], 1); }
}

__global__ __launch_bounds__(1024)
void scan_part_kernel(const int* __restrict__ in, int* __restrict__ out,
                      int* __restrict__ bsum, int n)
{
    __shared__ int warpsums[32];
    const int tid = threadIdx.x, lane = tid & 31, w = tid >> 5;
    const int i = blockIdx.x * 1024 + tid;
    int v = (i < n) ? in[i] : 0;
    int s = v;
#pragma unroll
    for (int o = 1; o < 32; o <<= 1) {
        int t = __shfl_up_sync(0xFFFFFFFFu, s, o);
        if (lane >= o) s += t;
    }
    if (lane == 31) warpsums[w] = s;
    __syncthreads();
    if (w == 0) {
        int ws = warpsums[lane];
#pragma unroll
        for (int o = 1; o < 32; o <<= 1) {
            int t = __shfl_up_sync(0xFFFFFFFFu, ws, o);
            if (lane >= o) ws += t;
        }
        warpsums[lane] = ws;
    }
    __syncthreads();
    int excl = s - v + (w > 0 ? warpsums[w - 1] : 0);
    if (i < n) out[i] = excl;
    if (tid == 1023) bsum[blockIdx.x] = excl + v;
}

__global__ __launch_bounds__(1024)
void scan_bsum_kernel(int* __restrict__ bsum, int nb)
{
    __shared__ int warpsums[32];
    const int tid = threadIdx.x, lane = tid & 31, w = tid >> 5;
    int v = (tid < nb) ? bsum[tid] : 0;
    int s = v;
#pragma unroll
    for (int o = 1; o < 32; o <<= 1) {
        int t = __shfl_up_sync(0xFFFFFFFFu, s, o);
        if (lane >= o) s += t;
    }
    if (lane == 31) warpsums[w] = s;
    __syncthreads();
    if (w == 0) {
        int ws = warpsums[lane];
#pragma unroll
        for (int o = 1; o < 32; o <<= 1) {
            int t = __shfl_up_sync(0xFFFFFFFFu, ws, o);
            if (lane >= o) ws += t;
        }
        warpsums[lane] = ws;
    }
    __syncthreads();
    int excl = s - v + (w > 0 ? warpsums[w - 1] : 0);
    if (tid < nb) bsum[tid] = excl;
}

__global__ __launch_bounds__(1024)
void scan_add_kernel(const int* __restrict__ in, int* __restrict__ out,
                     const int* __restrict__ bsum, int n)
{
    const int i = blockIdx.x * 1024 + threadIdx.x;
    if (i < n) {
        int o = out[i] + bsum[blockIdx.x];
        out[i] = o;
        if (i == n - 1) out[n] = o + in[i];
    }
}

__global__ void fill_csr_kernel(int* __restrict__ cursor, int* __restrict__ val,
                                const int* __restrict__ keys, const int* __restrict__ payload,
                                int m)
{
    int t = blockIdx.x * blockDim.x + threadIdx.x;
    if (t >= m) return;
    int pos = atomicAdd(&cursor[keys[t]], 1);
    val[pos] = payload[t];
}
__global__ void fill_csr2_kernel(int* __restrict__ cursor, int* __restrict__ val,
                                 const int* __restrict__ k1, const int* __restrict__ k2, int m)
{
    int t = blockIdx.x * blockDim.x + threadIdx.x;
    if (t >= m) return;
    int p1 = atomicAdd(&cursor[k1[t]], 1);
    val[p1] = t;
    int p2 = atomicAdd(&cursor[k2[t]], 1);
    val[p2] = t;
}

// ---------------- fp16 CSR SpMM: out[row] = sum_j in[val[j]] (fp32 accum) ----------------
__global__ __launch_bounds__(256)
void spmm_csr_h_kernel(__half* __restrict__ out, const __half* __restrict__ in,
                       const int* __restrict__ rowptr, const int* __restrict__ val, int n)
{
    int row = blockIdx.x * 8 + (threadIdx.x >> 5);
    if (row >= n) return;
    int lane = threadIdx.x & 31;
    int beg = rowptr[row], end = rowptr[row + 1];
    float a[8] = {0.f, 0.f, 0.f, 0.f, 0.f, 0.f, 0.f, 0.f};
    for (int j = beg; j < end; j++) {
        uint4 v = *(const uint4*)(in + (size_t)val[j] * H + lane * 8);
        const __half2* h = (const __half2*)&v;
#pragma unroll
        for (int q = 0; q < 4; q++) {
            float2 f = __half22float2(h[q]);
            a[2 * q] += f.x;
            a[2 * q + 1] += f.y;
        }
    }
    uint4 o;
    __half2* oh = (__half2*)&o;
#pragma unroll
    for (int q = 0; q < 4; q++)
        oh[q] = __floats2half2_rn(a[2 * q], a[2 * q + 1]);
    *(uint4*)(out + (size_t)row * H + lane * 8) = o;
}

// ---------------- fp32 -> fp16 convert (8 elems/thread) ----------------
__global__ void f2h_kernel(__half* __restrict__ out, const float* __restrict__ in, long n8)
{
    long t = (long)blockIdx.x * blockDim.x + threadIdx.x;
    if (t >= n8) return;
    float4 v0 = *(const float4*)(in + t * 8);
    float4 v1 = *(const float4*)(in + t * 8 + 4);
    uint2 lo = f4_to_h4(v0), hi = f4_to_h4(v1);
    uint4 o;
    o.x = lo.x; o.y = lo.y; o.z = hi.x; o.w = hi.y;
    *(uint4*)(out + t * 8) = o;
}

// ---------------- fp16 gather-sum: out[e] = xh[src]+xh[dst] ----------------
__global__ void gather_sum_h_kernel(__half* __restrict__ out, const __half* __restrict__ xh,
                                    const int* __restrict__ src, const int* __restrict__ dst,
                                    int m)
{
    long t = (long)blockIdx.x * blockDim.x + threadIdx.x;
    if (t >= (long)m * 32) return;
    int e = (int)(t >> 5);
    int c = (int)(t & 31) * 8;
    uint4 a = *(const uint4*)(xh + (size_t)src[e] * H + c);
    uint4 b = *(const uint4*)(xh + (size_t)dst[e] * H + c);
    const __half2* ah = (const __half2*)&a;
    const __half2* bh = (const __half2*)&b;
    uint4 o;
    __half2* oh = (__half2*)&o;
#pragma unroll
    for (int q = 0; q < 4; q++) {
        float2 fa = __half22float2(ah[q]);
        float2 fb = __half22float2(bh[q]);
        oh[q] = __floats2half2_rn(fa.x + fb.x, fa.y + fb.y);
    }
    *(uint4*)(out + (size_t)e * H + c) = o;
}

// ---------------- fp16 mma.sync GEMM with segmented A + fused epilogues ----------------
#define ASTR32 20
#define ABUF_A32 (128 * ASTR32)
#define ABUF_B32 (256 * ASTR32)
#define GEMM_SMEM ((2 * ABUF_A32 + 2 * ABUF_B32) * 4)

struct SliceArgs {
    const void* p[6];
    int ld[6];
};

__device__ __forceinline__ void mma_f16(float* c, const uint32_t* a, const uint32_t* b) {
    asm volatile(
        "mma.sync.aligned.m16n8k16.row.col.f32.f16.f16.f32 "
        "{%0,%1,%2,%3}, {%4,%5,%6,%7}, {%8,%9}, {%0,%1,%2,%3};"
        : "+f"(c[0]), "+f"(c[1]), "+f"(c[2]), "+f"(c[3])
        : "r"(a[0]), "r"(a[1]), "r"(a[2]), "r"(a[3]), "r"(b[0]), "r"(b[1]));
}

__global__ __launch_bounds__(256)
void mma_gemm3(SliceArgs sa, int a_half,
               const __half* __restrict__ Bt,
               const float* __restrict__ bias,
               const float* __restrict__ resid,
               const float* __restrict__ gamma,
               const float* __restrict__ beta,
               float* __restrict__ C,
               int M, int N, int K, int mode)
{
    extern __shared__ uint32_t smem[];
    uint32_t* AsBase = smem;
    uint32_t* BsBase = smem + 2 * ABUF_A32;

    const int tid = threadIdx.x;
    const int wid = tid >> 5, lane = tid & 31;
    const int gid = lane >> 2, tig = lane & 3;
    const int warp_m = (wid & 1) * 64;
    const int warp_n = (wid >> 1) * 64;
    const int row0 = blockIdx.y * 128;
    const int col0 = blockIdx.x * 256;

    float acc[4][8][4];
#pragma unroll
    for (int mt = 0; mt < 4; mt++)
#pragma unroll
        for (int nt = 0; nt < 8; nt++)
#pragma unroll
            for (int j = 0; j < 4; j++) acc[mt][nt][j] = 0.f;

    const int nc = K >> 5;
    float4 ra[4];

#pragma unroll
    for (int f = 0; f < 4; f++) {
        int i = f * 256 + tid, r = i >> 2, c16 = i & 3;
        uint32_t dst = (uint32_t)__cvta_generic_to_shared(BsBase + r * ASTR32 + c16 * 4);
        cp_async16(dst, Bt + (size_t)(col0 + r) * K + c16 * 8);
    }
    if (a_half) {
        const __half* Ah = (const __half*)sa.p[0];
        const int ldA = sa.ld[0];
#pragma unroll
        for (int f = 0; f < 2; f++) {
            int i = f * 256 + tid, r = i >> 2, c16 = i & 3;
            int gr = row0 + r; if (gr >= M) gr = M - 1;
            uint32_t dst = (uint32_t)__cvta_generic_to_shared(AsBase + r * ASTR32 + c16 * 4);
            cp_async16(dst, Ah + (size_t)gr * ldA + c16 * 8);
        }
        CP_COMMIT();
    } else {
        CP_COMMIT();
        const float* Ap = (const float*)sa.p[0];
        const int ldA = sa.ld[0];
#pragma unroll
        for (int f = 0; f < 4; f++) {
            int i = f * 256 + tid, r = i >> 3, c4 = i & 7;
            int gr = row0 + r; if (gr >= M) gr = M - 1;
            ra[f] = *(const float4*)(Ap + (size_t)gr * ldA + c4 * 4);
        }
#pragma unroll
        for (int f = 0; f < 4; f++) {
            int i = f * 256 + tid, r = i >> 3, c4 = i & 7;
            *(uint2*)(AsBase + r * ASTR32 + c4 * 2) = f4_to_h4(ra[f]);
        }
    }
    CP_WAIT0();
    __syncthreads();

    for (int c = 0; c < nc; c++) {
        const int nxt = c + 1;
        if (nxt < nc) {
            const int k0 = nxt << 5;
            uint32_t* Bs = BsBase + (nxt & 1) * ABUF_B32;
#pragma unroll
            for (int f = 0; f < 4; f++) {
                int i = f * 256 + tid, r = i >> 2, c16 = i & 3;
                uint32_t dst = (uint32_t)__cvta_generic_to_shared(Bs + r * ASTR32 + c16 * 4);
                cp_async16(dst, Bt + (size_t)(col0 + r) * K + k0 + c16 * 8);
            }
            const int sl = k0 >> 8;
            const int off = k0 & 255;
            if (a_half) {
                const __half* Ah = (const __half*)sa.p[sl];
                const int ldA = sa.ld[sl];
                uint32_t* As = AsBase + (nxt & 1) * ABUF_A32;
#pragma unroll
                for (int f = 0; f < 2; f++) {
                    int i = f * 256 + tid, r = i >> 2, c16 = i & 3;
                    int gr = row0 + r; if (gr >= M) gr = M - 1;
                    uint32_t dst = (uint32_t)__cvta_generic_to_shared(As + r * ASTR32 + c16 * 4);
                    cp_async16(dst, Ah + (size_t)gr * ldA + off + c16 * 8);
                }
                CP_COMMIT();
            } else {
                CP_COMMIT();
                const float* Ap = (const float*)sa.p[sl];
                const int ldA = sa.ld[sl];
#pragma unroll
                for (int f = 0; f < 4; f++) {
                    int i = f * 256 + tid, r = i >> 3, c4 = i & 7;
                    int gr = row0 + r; if (gr >= M) gr = M - 1;
                    ra[f] = *(const float4*)(Ap + (size_t)gr * ldA + off + c4 * 4);
                }
            }
        }

        const uint32_t* Asu = AsBase + (c & 1) * ABUF_A32;
        const uint32_t* Bsu = BsBase + (c & 1) * ABUF_B32;
#pragma unroll
        for (int ks = 0; ks < 2; ks++) {
            const int k0c = ks * 8;
            uint32_t afr[4][4], bfr[8][2];
#pragma unroll
            for (int mt = 0; mt < 4; mt++) {
                int r = warp_m + mt * 16 + gid;
                afr[mt][0] = Asu[r * ASTR32 + k0c + tig];
                afr[mt][1] = Asu[(r + 8) * ASTR32 + k0c + tig];
                afr[mt][2] = Asu[r * ASTR32 + k0c + tig + 4];
                afr[mt][3] = Asu[(r + 8) * ASTR32 + k0c + tig + 4];
            }
#pragma unroll
            for (int nt = 0; nt < 8; nt++) {
                int cc = warp_n + nt * 8 + gid;
                bfr[nt][0] = Bsu[cc * ASTR32 + k0c + tig];
                bfr[nt][1] = Bsu[cc * ASTR32 + k0c + tig + 4];
            }
#pragma unroll
            for (int mt = 0; mt < 4; mt++)
#pragma unroll
                for (int nt = 0; nt < 8; nt++)
                    mma_f16(acc[mt][nt], afr[mt], bfr[nt]);
        }

        if (nxt < nc) {
            if (!a_half) {
                uint32_t* As = AsBase + (nxt & 1) * ABUF_A32;
#pragma unroll
                for (int f = 0; f < 4; f++) {
                    int i = f * 256 + tid, r = i >> 3, c4 = i & 7;
                    *(uint2*)(As + r * ASTR32 + c4 * 2) = f4_to_h4(ra[f]);
                }
            }
            CP_WAIT0();
        }
        __syncthreads();
    }

    if (mode == 0) {
        __half* Ch = (__half*)C;
#pragma unroll
        for (int mt = 0; mt < 4; mt++) {
#pragma unroll
            for (int nt = 0; nt < 8; nt++) {
                int cc = col0 + warp_n + nt * 8 + 2 * tig;
                float bx = bias[cc], by = bias[cc + 1];
#pragma unroll
                for (int h = 0; h < 2; h++) {
                    int r = row0 + warp_m + mt * 16 + gid + h * 8;
                    if (r >= M) continue;
                    float ox = gelu_f(acc[mt][nt][h * 2 + 0] + bx);
                    float oy = gelu_f(acc[mt][nt][h * 2 + 1] + by);
                    *(__half2*)(Ch + (size_t)r * N + cc) = __floats2half2_rn(ox, oy);
                }
            }
        }
        return;
    }

    // ---- fused LayerNorm epilogue (N == 256, grid.x == 1) ----
    float2* rowstat = (float2*)smem;
    float sumv[4][2], sqv[4][2];
#pragma unroll
    for (int mt = 0; mt < 4; mt++)
#pragma unroll
        for (int h = 0; h < 2; h++) { sumv[mt][h] = 0.f; sqv[mt][h] = 0.f; }

#pragma unroll
    for (int mt = 0; mt < 4; mt++) {
#pragma unroll
        for (int h = 0; h < 2; h++) {
            int r = row0 + warp_m + mt * 16 + gid + h * 8;
            int rc = r < M ? r : M - 1;
#pragma unroll
            for (int nt = 0; nt < 8; nt++) {
                int cc = warp_n + nt * 8 + 2 * tig;
                float2 b2 = *(const float2*)(bias + cc);
                float2 rd = *(const float2*)(resid + (size_t)rc * H + cc);
                float vx = acc[mt][nt][h * 2 + 0] + b2.x;
                float vy = acc[mt][nt][h * 2 + 1] + b2.y;
                if (mode == 1) { vx = gelu_f(vx); vy = gelu_f(vy); }
                vx += rd.x; vy += rd.y;
                acc[mt][nt][h * 2 + 0] = vx;
                acc[mt][nt][h * 2 + 1] = vy;
                sumv[mt][h] += vx + vy;
                sqv[mt][h] += vx * vx + vy * vy;
            }
        }
    }
#pragma unroll
    for (int mt = 0; mt < 4; mt++)
#pragma unroll
        for (int h = 0; h < 2; h++) {
            sumv[mt][h] += __shfl_xor_sync(0xFFFFFFFFu, sumv[mt][h], 1);
            sumv[mt][h] += __shfl_xor_sync(0xFFFFFFFFu, sumv[mt][h], 2);
            sqv[mt][h]  += __shfl_xor_sync(0xFFFFFFFFu, sqv[mt][h], 1);
            sqv[mt][h]  += __shfl_xor_sync(0xFFFFFFFFu, sqv[mt][h], 2);
        }
    if (tig == 0) {
        int wn = warp_n >> 6;
#pragma unroll
        for (int mt = 0; mt < 4; mt++)
#pragma unroll
            for (int h = 0; h < 2; h++) {
                int rl = warp_m + mt * 16 + gid + h * 8;
                rowstat[rl * 4 + wn] = make_float2(sumv[mt][h], sqv[mt][h]);
            }
    }
    __syncthreads();

    float mean_[4][2], rstd_[4][2];
#pragma unroll
    for (int mt = 0; mt < 4; mt++)
#pragma unroll
        for (int h = 0; h < 2; h++) {
            int rl = warp_m + mt * 16 + gid + h * 8;
            float s = 0.f, q = 0.f;
#pragma unroll
            for (int w = 0; w < 4; w++) {
                float2 t = rowstat[rl * 4 + w];
                s += t.x; q += t.y;
            }
            float mean = s * (1.0f / H);
            float var = q * (1.0f / H) - mean * mean;
            mean_[mt][h] = mean;
            rstd_[mt][h] = rsqrtf(var + 1e-5f);
        }

#pragma unroll
    for (int mt = 0; mt < 4; mt++) {
#pragma unroll
        for (int nt = 0; nt < 8; nt++) {
            int cc = warp_n + nt * 8 + 2 * tig;
            float2 gv = *(const float2*)(gamma + cc);
            float2 bv = *(const float2*)(beta + cc);
#pragma unroll
            for (int h = 0; h < 2; h++) {
                int r = row0 + warp_m + mt * 16 + gid + h * 8;
                if (r >= M) continue;
                float m = mean_[mt][h], rs = rstd_[mt][h];
                float ox = (acc[mt][nt][h * 2 + 0] - m) * rs * gv.x + bv.x;
                float oy = (acc[mt][nt][h * 2 + 1] - m) * rs * gv.y + bv.y;
                *(float2*)(C + (size_t)r * H + cc) = make_float2(ox, oy);
            }
        }
    }
}

// ---------------- weight prep (transpose to [N,K] K-major, fp16) ----------------
__global__ void build_wtcat_kernel(const float* __restrict__ ws, const float* __restrict__ wf,
                                   const float* __restrict__ wk, __half* __restrict__ out)
{
    long t = (long)blockIdx.x * blockDim.x + threadIdx.x;
    if (t >= (long)4 * H * 1536) return;
    int lc = (int)(t / (H * 1536));
    int rem = (int)(t % (H * 1536));
    int n = rem / 1536, k = rem % 1536;
    float v;
    if (k < 256) v = ws[(size_t)lc * 65536 + k * 256 + n];
    else if (k < 512) v = wf[(size_t)lc * 65536 + (k - 256) * 256 + n];
    else {
        int hop = (k - 512) >> 8, kk = (k - 512) & 255;
        v = wk[((size_t)(lc * 4 + hop) * 256 + kk) * 256 + n];
    }
    out[t] = __float2half_rn(v);
}

__global__ void build_wt1_kernel(const float* __restrict__ w1, __half* __restrict__ out)
{
    long t = (long)blockIdx.x * blockDim.x + threadIdx.x;
    if (t >= (long)4 * FH * H) return;
    int lc = (int)(t / (FH * H));
    int rem = (int)(t % (FH * H));
    int n = rem / H, k = rem % H;
    out[t] = __float2half_rn(w1[(size_t)lc * (H * FH) + (size_t)k * FH + n]);
}

__global__ void build_wt2_kernel(const float* __restrict__ w2, __half* __restrict__ out)
{
    long t = (long)blockIdx.x * blockDim.x + threadIdx.x;
    if (t >= (long)4 * H * FH) return;
    int lc = (int)(t / (H * FH));
    int rem = (int)(t % (H * FH));
    int n = rem / FH, k = rem % FH;
    out[t] = __float2half_rn(w2[(size_t)lc * (FH * H) + (size_t)k * H + n]);
}

__global__ void build_bcat_kernel(const float* __restrict__ bs, const float* __restrict__ bf,
                                  const float* __restrict__ bk, float* __restrict__ out)
{
    int t = blockIdx.x * blockDim.x + threadIdx.x;
    if (t >= 4 * H) return;
    int lc = t / H, n = t % H;
    float v = bs[lc * H + n] + bf[lc * H + n];
    for (int i = 0; i < KHOPS; i++) v += bk[(lc * KHOPS + i) * H + n];
    out[t] = v;
}

// ---------------- embed gather ----------------
__global__ void gather_embed_kernel(float* __restrict__ out, const float* __restrict__ rel,
                                    const int* __restrict__ feat, int m)
{
    long t = (long)blockIdx.x * blockDim.x + threadIdx.x;
    if (t >= (long)m * 64) return;
    int e = (int)(t >> 6);
    int c = (int)(t & 63) << 2;
    *(float4*)(out + (size_t)e * H + c) = *(const float4*)(rel + (size_t)feat[e] * H + c);
}

// ---------------- host side ----------------
static inline int blocks_for(long threads) { return (int)((threads + 255) / 256); }

struct Scratch {
    float *x0, *x1, *lg0, *lg1;
    __half *xh, *lgh, *fnh, *feh, *zh, *znh;
    float *ln1, *ln1n;
    __half *ffh, *ffhn;
    __half *wtcat, *wt1, *wt2;
    float *bcat;
    int *rp_g, *v_g, *rp_b, *v_b, *rp_l, *v_l, *cnt, *cnt2, *bsum, *bsum2;
};

struct StreamCtx {
    cudaStream_t s1, s2;
    cudaEvent_t evF, evA, evB, evT[2], evN[2];
    StreamCtx() {
        cudaStreamCreateWithFlags(&s1, cudaStreamNonBlocking);
        cudaStreamCreateWithFlags(&s2, cudaStreamNonBlocking);
        cudaEventCreateWithFlags(&evF, cudaEventDisableTiming);
        cudaEventCreateWithFlags(&evA, cudaEventDisableTiming);
        cudaEventCreateWithFlags(&evB, cudaEventDisableTiming);
        for (int i = 0; i < 2; i++) {
            cudaEventCreateWithFlags(&evT[i], cudaEventDisableTiming);
            cudaEventCreateWithFlags(&evN[i], cudaEventDisableTiming);
        }
    }
};
static StreamCtx& ctx() { static StreamCtx c; return c; }

static void scan_excl(const int* in, int* out, int* bsum, int n, cudaStream_t st)
{
    int nb = (n + 1023) / 1024;
    scan_part_kernel<<<nb, 1024, 0, st>>>(in, out, bsum, n);
    scan_bsum_kernel<<<1, 1024, 0, st>>>(bsum, nb);
    scan_add_kernel<<<nb, 1024, 0, st>>>(in, out, bsum, n);
}

static void build_csr(int* cnt, int* bsum, int* rowptr, int* val,
                      const int* keys, const int* payload, int n, int m, cudaStream_t st)
{
    cudaMemsetAsync(cnt, 0, (size_t)n * sizeof(int), st);
    hist_kernel<<<blocks_for(m), 256, 0, st>>>(cnt, keys, m);
    scan_excl(cnt, rowptr, bsum, n, st);
    cudaMemcpyAsync(cnt, rowptr, (size_t)n * sizeof(int), cudaMemcpyDeviceToDevice, st);
    fill_csr_kernel<<<blocks_for(m), 256, 0, st>>>(cnt, val, keys, payload, m);
}

static void run_core(const Scratch& S,
                     const __half* xin_h, const float* resid_x, const __half* fused_h,
                     float* xout, int n, const int* rowptr, const int* val,
                     __half* zbuf, size_t zstride, float* ln1buf, __half* ffhbuf,
                     int lc,
                     const float* b_ff1, const float* b_ff2,
                     const float* g1, const float* c1,
                     const float* g2, const float* c2,
                     cudaStream_t st)
{
    const int gy = (n + 127) / 128;
    __half* z1 = zbuf;
    __half* z2 = zbuf + zstride;
    __half* z3 = zbuf + 2 * zstride;
    __half* z4 = zbuf + 3 * zstride;

    const int sg = (n + 7) / 8;
    spmm_csr_h_kernel<<<sg, 256, 0, st>>>(z1, xin_h, rowptr, val, n);
    spmm_csr_h_kernel<<<sg, 256, 0, st>>>(z2, z1, rowptr, val, n);
    spmm_csr_h_kernel<<<sg, 256, 0, st>>>(z3, z2, rowptr, val, n);
    spmm_csr_h_kernel<<<sg, 256, 0, st>>>(z4, z3, rowptr, val, n);

    // ln1 = LN( resid + gelu( concat_A @ Wcat + bcat ) ), all-A fp16
    {
        SliceArgs sa;
        sa.p[0] = xin_h;  sa.ld[0] = H;
        sa.p[1] = fused_h; sa.ld[1] = H;
        sa.p[2] = z1;     sa.ld[2] = H;
        sa.p[3] = z2;     sa.ld[3] = H;
        sa.p[4] = z3;     sa.ld[4] = H;
        sa.p[5] = z4;     sa.ld[5] = H;
        mma_gemm3<<<dim3(1, gy), 256, GEMM_SMEM, st>>>(
            sa, 1, S.wtcat + (size_t)lc * H * 1536, S.bcat + (size_t)lc * H,
            resid_x, g1, c1, ln1buf, n, H, 1536, 1);
    }
    // ffh = gelu(ln1 @ w1 + b1)  [fp32 A, fp16 out]
    {
        SliceArgs sa;
        for (int i = 0; i < 6; i++) { sa.p[i] = ln1buf; sa.ld[i] = H; }
        mma_gemm3<<<dim3(FH / 256, gy), 256, GEMM_SMEM, st>>>(
            sa, 0, S.wt1 + (size_t)lc * FH * H, b_ff1,
            nullptr, nullptr, nullptr, (float*)ffhbuf, n, FH, H, 0);
    }
    // xout = LN( ln1 + ffh @ w2 + b2 )  [fp16 A]
    {
        SliceArgs sa;
        for (int i = 0; i < 4; i++) { sa.p[i] = ffhbuf + (size_t)i * 256; sa.ld[i] = FH; }
        sa.p[4] = ffhbuf; sa.ld[4] = FH;
        sa.p[5] = ffhbuf; sa.ld[5] = FH;
        mma_gemm3<<<dim3(1, gy), 256, GEMM_SMEM, st>>>(
            sa, 1, S.wt2 + (size_t)lc * H * FH, b_ff2,
            ln1buf, g2, c2, xout, n, H, FH, 2);
    }
}

extern "C" void kernel_launch(void* const* d_in, const int* in_sizes, int n_in,
                              void* d_out, int out_size)
{
    const float* x_in      = (const float*)d_in[0];
    const int*   edge_feat = (const int*)d_in[1];
    const int*   eig       = (const int*)d_in[2];
    const int*   eil       = (const int*)d_in[3];
    const float* rel       = (const float*)d_in[4];
    const float* w_self    = (const float*)d_in[5];
    const float* b_self    = (const float*)d_in[6];
    const float* w_khop    = (const float*)d_in[7];
    const float* b_khop    = (const float*)d_in[8];
    const float* w_fuse    = (const float*)d_in[9];
    const float* b_fuse    = (const float*)d_in[10];
    const float* w_ff1     = (const float*)d_in[11];
    const float* b_ff1     = (const float*)d_in[12];
    const float* w_ff2     = (const float*)d_in[13];
    const float* b_ff2     = (const float*)d_in[14];
    const float* ln1_g     = (const float*)d_in[15];
    const float* ln1_b     = (const float*)d_in[16];
    const float* ln2_g     = (const float*)d_in[17];
    const float* ln2_b     = (const float*)d_in[18];

    const int* src_g = eig;
    const int* dst_g = eig + NEDGES;
    const int* src_l = eil;
    const int* dst_l = eil + NLGE;

    cudaFuncSetAttribute(mma_gemm3, cudaFuncAttributeMaxDynamicSharedMemorySize, GEMM_SMEM);

    Scratch S;
    void* p;
    cudaGetSymbolAddress(&p, g_x0);       S.x0    = (float*)p;
    cudaGetSymbolAddress(&p, g_x1);       S.x1    = (float*)p;
    cudaGetSymbolAddress(&p, g_lg0);      S.lg0   = (float*)p;
    cudaGetSymbolAddress(&p, g_lg1);      S.lg1   = (float*)p;
    cudaGetSymbolAddress(&p, g_xh);       S.xh    = (__half*)p;
    cudaGetSymbolAddress(&p, g_lgh);      S.lgh   = (__half*)p;
    cudaGetSymbolAddress(&p, g_fnh);      S.fnh   = (__half*)p;
    cudaGetSymbolAddress(&p, g_feh);      S.feh   = (__half*)p;
    cudaGetSymbolAddress(&p, g_zh);       S.zh    = (__half*)p;
    cudaGetSymbolAddress(&p, g_znh);      S.znh   = (__half*)p;
    cudaGetSymbolAddress(&p, g_ln1);      S.ln1   = (float*)p;
    cudaGetSymbolAddress(&p, g_ln1n);     S.ln1n  = (float*)p;
    cudaGetSymbolAddress(&p, g_ffh);      S.ffh   = (__half*)p;
    cudaGetSymbolAddress(&p, g_ffhn);     S.ffhn  = (__half*)p;
    cudaGetSymbolAddress(&p, g_wtcat);    S.wtcat = (__half*)p;
    cudaGetSymbolAddress(&p, g_wt1);      S.wt1   = (__half*)p;
    cudaGetSymbolAddress(&p, g_wt2);      S.wt2   = (__half*)p;
    cudaGetSymbolAddress(&p, g_bcat);     S.bcat  = (float*)p;
    cudaGetSymbolAddress(&p, g_rowptr_g); S.rp_g  = (int*)p;
    cudaGetSymbolAddress(&p, g_val_g);    S.v_g   = (int*)p;
    cudaGetSymbolAddress(&p, g_rowptr_b); S.rp_b  = (int*)p;
    cudaGetSymbolAddress(&p, g_val_b);    S.v_b   = (int*)p;
    cudaGetSymbolAddress(&p, g_rowptr_l); S.rp_l  = (int*)p;
    cudaGetSymbolAddress(&p, g_val_l);    S.v_l   = (int*)p;
    cudaGetSymbolAddress(&p, g_cnt);      S.cnt   = (int*)p;
    cudaGetSymbolAddress(&p, g_cnt2);     S.cnt2  = (int*)p;
    cudaGetSymbolAddress(&p, g_bsum);     S.bsum  = (int*)p;
    cudaGetSymbolAddress(&p, g_bsum2);    S.bsum2 = (int*)p;

    StreamCtx& C = ctx();
    cudaStream_t s1 = C.s1, s2 = C.s2;

    // ---- fork for prep ----
    cudaEventRecord(C.evF, 0);
    cudaStreamWaitEvent(s1, C.evF, 0);
    cudaStreamWaitEvent(s2, C.evF, 0);

    // s1: CSR g then CSR b
    build_csr(S.cnt2, S.bsum2, S.rp_g, S.v_g, dst_g, src_g, NNODES, NEDGES, s1);
    cudaMemsetAsync(S.cnt2, 0, (size_t)NNODES * sizeof(int), s1);
    hist2_kernel<<<blocks_for(NEDGES), 256, 0, s1>>>(S.cnt2, src_g, dst_g, NEDGES);
    scan_excl(S.cnt2, S.rp_b, S.bsum2, NNODES, s1);
    cudaMemcpyAsync(S.cnt2, S.rp_b, (size_t)NNODES * sizeof(int), cudaMemcpyDeviceToDevice, s1);
    fill_csr2_kernel<<<blocks_for(NEDGES), 256, 0, s1>>>(S.cnt2, S.v_b, src_g, dst_g, NEDGES);

    // s2: CSR l
    build_csr(S.cnt, S.bsum, S.rp_l, S.v_l, dst_l, src_l, NEDGES, NLGE, s2);

    // legacy: weight prep + initial activations
    build_wtcat_kernel<<<blocks_for((long)4 * H * 1536), 256>>>(w_self, w_fuse, w_khop, S.wtcat);
    build_wt1_kernel<<<blocks_for((long)4 * FH * H), 256>>>(w_ff1, S.wt1);
    build_wt2_kernel<<<blocks_for((long)4 * H * FH), 256>>>(w_ff2, S.wt2);
    build_bcat_kernel<<<blocks_for(4 * H), 256>>>(b_self, b_fuse, b_khop, S.bcat);
    cudaMemcpyAsync(S.x0, x_in, (size_t)NNODES * H * sizeof(float), cudaMemcpyDeviceToDevice);
    gather_embed_kernel<<<blocks_for((long)NEDGES * 64), 256>>>(S.lg0, rel, edge_feat, NEDGES);

    // join prep
    cudaEventRecord(C.evA, s1);
    cudaEventRecord(C.evB, s2);
    cudaStreamWaitEvent(0, C.evA, 0);
    cudaStreamWaitEvent(0, C.evB, 0);

    float* xb[2]  = {S.x0, S.x1};
    float* lgb[2] = {S.lg0, S.lg1};

    int cur = 0;
    for (int l = 0; l < LNUM; l++) {
        const float* x  = xb[cur];
        const float* lg = lgb[cur];
        float* xn  = xb[1 - cur];
        float* lgn = lgb[1 - cur];

        // fp16 mirrors of current state (both streams need both)
        f2h_kernel<<<blocks_for((long)NNODES * H / 8), 256>>>(S.xh, x, (long)NNODES * H / 8);
        f2h_kernel<<<blocks_for((long)NEDGES * H / 8), 256>>>(S.lgh, lg, (long)NEDGES * H / 8);

        cudaEventRecord(C.evT[l], 0);
        cudaStreamWaitEvent(s1, C.evT[l], 0);

        // s1: fused_nodes + node core
        spmm_csr_h_kernel<<<(NNODES + 7) / 8, 256, 0, s1>>>(S.fnh, S.lgh, S.rp_b, S.v_b, NNODES);
        {
            int lc = l * 2 + 0;
            run_core(S, S.xh, x, S.fnh, xn, NNODES, S.rp_g, S.v_g,
                     S.znh, (size_t)NNODES * H, S.ln1n, S.ffhn, lc,
                     b_ff1 + (size_t)lc * FH, b_ff2 + (size_t)lc * H,
                     ln1_g + (size_t)lc * H, ln1_b + (size_t)lc * H,
                     ln2_g + (size_t)lc * H, ln2_b + (size_t)lc * H, s1);
        }

        // legacy: fused_edges + edge core
        gather_sum_h_kernel<<<blocks_for((long)NEDGES * 32), 256>>>(S.feh, S.xh, src_g, dst_g, NEDGES);
        {
            int lc = l * 2 + 1;
            run_core(S, S.lgh, lg, S.feh, lgn, NEDGES, S.rp_l, S.v_l,
                     S.zh, (size_t)NEDGES * H, S.ln1, S.ffh, lc,
                     b_ff1 + (size_t)lc * FH, b_ff2 + (size_t)lc * H,
                     ln1_g + (size_t)lc * H, ln1_b + (size_t)lc * H,
                     ln2_g + (size_t)lc * H, ln2_b + (size_t)lc * H, (cudaStream_t)0);
        }

        cudaEventRecord(C.evN[l], s1);
        cudaStreamWaitEvent(0, C.evN[l], 0);

        cur = 1 - cur;
    }

    cudaMemcpyAsync(d_out, xb[cur], (size_t)NNODES * H * sizeof(float),
                    cudaMemcpyDeviceToDevice);
    cudaMemcpyAsync((float*)d_out + (size_t)NNODES * H, lgb[cur],
                    (size_t)NEDGES * H * sizeof(float), cudaMemcpyDeviceToDevice);
}